// round 9
// baseline (speedup 1.0000x reference)
#include <cuda_runtime.h>
#include <cuda_bf16.h>
#include <cstdint>

// ----------------------------------------------------------------------------
// Problem constants
// ----------------------------------------------------------------------------
#define BATCH   2
#define LQ      4096
#define LKV     1024
#define DIM     1024
#define KV_DIM  768
#define NHEADS  16
#define HDIM    64

// ----------------------------------------------------------------------------
// Scratch (device globals; allocation-free per harness rules)
// ----------------------------------------------------------------------------
__device__ float g_qtmp[(BATCH*LQ)*DIM];   // Q proj out (fp32)
__device__ float g_ktmp[(BATCH*LKV)*DIM];  // K proj out (fp32)
__device__ float g_v   [(BATCH*LKV)*DIM];  // V proj out (fp32)

__device__ __nv_bfloat16 g_qhi[(BATCH*LQ)*DIM],  g_qlo[(BATCH*LQ)*DIM];
__device__ __nv_bfloat16 g_khi[(BATCH*LKV)*DIM], g_klo[(BATCH*LKV)*DIM];
__device__ __nv_bfloat16 g_vthi[(BATCH*LKV)*DIM], g_vtlo[(BATCH*LKV)*DIM]; // V^T [b,h,d,c]

__device__ __nv_bfloat16 g_xhi[(BATCH*LQ)*DIM],  g_xlo[(BATCH*LQ)*DIM];   // x split; later attn-out split
__device__ __nv_bfloat16 g_yhi[(BATCH*LKV)*KV_DIM], g_ylo[(BATCH*LKV)*KV_DIM];
__device__ __nv_bfloat16 g_wqt_hi[DIM*DIM],    g_wqt_lo[DIM*DIM];
__device__ __nv_bfloat16 g_wkt_hi[DIM*KV_DIM], g_wkt_lo[DIM*KV_DIM];
__device__ __nv_bfloat16 g_wvt_hi[DIM*KV_DIM], g_wvt_lo[DIM*KV_DIM];
__device__ __nv_bfloat16 g_wot_hi[DIM*DIM],    g_wot_lo[DIM*DIM];

// ----------------------------------------------------------------------------
// mma.sync / cp.async helpers (baseline PTX, OK for compute_103 virtual target)
// ----------------------------------------------------------------------------
#define MMA16816(d, a, b) \
    asm volatile("mma.sync.aligned.m16n8k16.row.col.f32.bf16.bf16.f32 " \
        "{%0,%1,%2,%3}, {%4,%5,%6,%7}, {%8,%9}, {%0,%1,%2,%3};" \
        : "+f"((d)[0]), "+f"((d)[1]), "+f"((d)[2]), "+f"((d)[3]) \
        : "r"((a)[0]), "r"((a)[1]), "r"((a)[2]), "r"((a)[3]), \
          "r"((b)[0]), "r"((b)[1]))

#define CP16(sp, gp) do { \
    uint32_t _s = (uint32_t)__cvta_generic_to_shared(sp); \
    asm volatile("cp.async.cg.shared.global [%0], [%1], 16;" :: "r"(_s), "l"(gp)); \
} while (0)
#define CP_COMMIT()  asm volatile("cp.async.commit_group;" ::: "memory")
#define CP_WAIT1()   asm volatile("cp.async.wait_group 1;" ::: "memory")

__device__ __forceinline__ uint32_t packbf2(float x, float y) {
    __nv_bfloat162 t = __float22bfloat162_rn(make_float2(x, y));
    return *reinterpret_cast<uint32_t*>(&t);
}

// ----------------------------------------------------------------------------
// bf16x3 GEMM, 2-stage cp.async pipeline (unchanged from R8):
//   C[M,N] = A[M,K] @ Bt[N,K]^T + bias
// ----------------------------------------------------------------------------
#define SSTR 40
#define GEMM_STAGE_ELEMS (4 * 128 * SSTR)
#define GEMM_SMEM_BYTES  (2 * GEMM_STAGE_ELEMS * 2)       // 81920 B

__global__ __launch_bounds__(256, 2) void gemm_bf16x3_mma_kernel(
    const __nv_bfloat16* __restrict__ Ahi, const __nv_bfloat16* __restrict__ Alo,
    const __nv_bfloat16* __restrict__ Bhi, const __nv_bfloat16* __restrict__ Blo,
    const float* __restrict__ bias, float* __restrict__ C,
    int M, int N, int K)
{
    extern __shared__ __nv_bfloat16 dsm[];

    const int tid  = threadIdx.x;
    const int wid  = tid >> 5;
    const int lane = tid & 31;
    const int warpM = wid >> 2;
    const int warpN = wid & 3;
    const int bm = blockIdx.y * 128;
    const int bn = blockIdx.x * 128;
    const int tq = lane >> 2;
    const int tr = lane & 3;

    const int r0g = tid >> 2;
    const int r1g = r0g + 64;
    const int c0g = (tid & 3) * 8;

    float acc[4][4][4];
#pragma unroll
    for (int i = 0; i < 4; i++)
#pragma unroll
        for (int j = 0; j < 4; j++)
#pragma unroll
            for (int r = 0; r < 4; r++) acc[i][j][r] = 0.f;

    const int nchunks = K >> 5;

    auto issue = [&](int c, int s) {
        __nv_bfloat16* sAh = dsm + s * GEMM_STAGE_ELEMS;
        __nv_bfloat16* sAl = sAh + 128 * SSTR;
        __nv_bfloat16* sBh = sAl + 128 * SSTR;
        __nv_bfloat16* sBl = sBh + 128 * SSTR;
        const int k0 = c << 5;
        const long a0 = (long)(bm + r0g) * K + k0 + c0g;
        const long a1 = (long)(bm + r1g) * K + k0 + c0g;
        const long b0 = (long)(bn + r0g) * K + k0 + c0g;
        const long b1 = (long)(bn + r1g) * K + k0 + c0g;
        CP16(&sAh[r0g * SSTR + c0g], &Ahi[a0]);
        CP16(&sAh[r1g * SSTR + c0g], &Ahi[a1]);
        CP16(&sAl[r0g * SSTR + c0g], &Alo[a0]);
        CP16(&sAl[r1g * SSTR + c0g], &Alo[a1]);
        CP16(&sBh[r0g * SSTR + c0g], &Bhi[b0]);
        CP16(&sBh[r1g * SSTR + c0g], &Bhi[b1]);
        CP16(&sBl[r0g * SSTR + c0g], &Blo[b0]);
        CP16(&sBl[r1g * SSTR + c0g], &Blo[b1]);
    };

    issue(0, 0);
    CP_COMMIT();

    for (int c = 0; c < nchunks; c++) {
        if (c + 1 < nchunks) issue(c + 1, (c + 1) & 1);
        CP_COMMIT();
        CP_WAIT1();
        __syncthreads();

        const __nv_bfloat16* sAh = dsm + (c & 1) * GEMM_STAGE_ELEMS;
        const __nv_bfloat16* sAl = sAh + 128 * SSTR;
        const __nv_bfloat16* sBh = sAl + 128 * SSTR;
        const __nv_bfloat16* sBl = sBh + 128 * SSTR;

#pragma unroll
        for (int ks = 0; ks < 2; ks++) {
            const int kb = ks * 16 + tr * 2;
            uint32_t ah[4][4], al[4][4];
#pragma unroll
            for (int mf = 0; mf < 4; mf++) {
                const int rA = warpM * 64 + mf * 16 + tq;
                ah[mf][0] = *(const uint32_t*)&sAh[(rA    ) * SSTR + kb    ];
                ah[mf][1] = *(const uint32_t*)&sAh[(rA + 8) * SSTR + kb    ];
                ah[mf][2] = *(const uint32_t*)&sAh[(rA    ) * SSTR + kb + 8];
                ah[mf][3] = *(const uint32_t*)&sAh[(rA + 8) * SSTR + kb + 8];
                al[mf][0] = *(const uint32_t*)&sAl[(rA    ) * SSTR + kb    ];
                al[mf][1] = *(const uint32_t*)&sAl[(rA + 8) * SSTR + kb    ];
                al[mf][2] = *(const uint32_t*)&sAl[(rA    ) * SSTR + kb + 8];
                al[mf][3] = *(const uint32_t*)&sAl[(rA + 8) * SSTR + kb + 8];
            }
#pragma unroll
            for (int nf = 0; nf < 4; nf++) {
                const int rB = warpN * 32 + nf * 8 + tq;
                uint32_t bh[2], bl[2];
                bh[0] = *(const uint32_t*)&sBh[rB * SSTR + kb    ];
                bh[1] = *(const uint32_t*)&sBh[rB * SSTR + kb + 8];
                bl[0] = *(const uint32_t*)&sBl[rB * SSTR + kb    ];
                bl[1] = *(const uint32_t*)&sBl[rB * SSTR + kb + 8];
#pragma unroll
                for (int mf = 0; mf < 4; mf++) {
                    MMA16816(acc[mf][nf], ah[mf], bh);
                    MMA16816(acc[mf][nf], ah[mf], bl);
                    MMA16816(acc[mf][nf], al[mf], bh);
                }
            }
        }
        __syncthreads();
    }

#pragma unroll
    for (int mf = 0; mf < 4; mf++) {
        const int row = bm + warpM * 64 + mf * 16 + tq;
#pragma unroll
        for (int nf = 0; nf < 4; nf++) {
            const int col = bn + warpN * 32 + nf * 8 + tr * 2;
            const float b0 = bias[col], b1 = bias[col + 1];
            float2 v0 = make_float2(acc[mf][nf][0] + b0, acc[mf][nf][1] + b1);
            float2 v1 = make_float2(acc[mf][nf][2] + b0, acc[mf][nf][3] + b1);
            *(float2*)&C[(long)row * N + col]       = v0;
            *(float2*)&C[(long)(row + 8) * N + col] = v1;
        }
    }
}

// ----------------------------------------------------------------------------
// Split fp32 -> bf16 hi + lo (elementwise)
// ----------------------------------------------------------------------------
__global__ __launch_bounds__(256) void split_bf16_kernel(
    const float* __restrict__ src, __nv_bfloat16* __restrict__ hi,
    __nv_bfloat16* __restrict__ lo, int n4)
{
    int i = blockIdx.x * blockDim.x + threadIdx.x;
    if (i >= n4) return;
    float4 v = *(const float4*)&src[(long)i * 4];
    __nv_bfloat16 h0 = __float2bfloat16(v.x), h1 = __float2bfloat16(v.y);
    __nv_bfloat16 h2 = __float2bfloat16(v.z), h3 = __float2bfloat16(v.w);
    uint32_t ph0 = packbf2(v.x, v.y), ph1 = packbf2(v.z, v.w);
    uint32_t pl0 = packbf2(v.x - __bfloat162float(h0), v.y - __bfloat162float(h1));
    uint32_t pl1 = packbf2(v.z - __bfloat162float(h2), v.w - __bfloat162float(h3));
    *(uint2*)&hi[(long)i * 4] = make_uint2(ph0, ph1);
    *(uint2*)&lo[(long)i * 4] = make_uint2(pl0, pl1);
}

// ----------------------------------------------------------------------------
// Split + transpose, batched pair: z=0 -> (W0,...), z=1 -> (W1,...)
// W [K,N] fp32 -> Wt hi/lo [N,K] bf16
// ----------------------------------------------------------------------------
__global__ __launch_bounds__(256) void split_transpose2_kernel(
    const float* __restrict__ W0, __nv_bfloat16* __restrict__ T0hi, __nv_bfloat16* __restrict__ T0lo,
    const float* __restrict__ W1, __nv_bfloat16* __restrict__ T1hi, __nv_bfloat16* __restrict__ T1lo,
    int K, int N)
{
    const float* W = blockIdx.z ? W1 : W0;
    __nv_bfloat16* Thi = blockIdx.z ? T1hi : T0hi;
    __nv_bfloat16* Tlo = blockIdx.z ? T1lo : T0lo;

    __shared__ float tile[32][33];
    const int bx = blockIdx.x * 32;
    const int by = blockIdx.y * 32;
    const int tx = threadIdx.x & 31;
    const int ty = threadIdx.x >> 5;
#pragma unroll
    for (int i = 0; i < 4; i++) {
        int kk = by + ty + i * 8;
        tile[ty + i * 8][tx] = W[(long)kk * N + bx + tx];
    }
    __syncthreads();
#pragma unroll
    for (int i = 0; i < 4; i++) {
        int nn = bx + ty + i * 8;
        float v = tile[tx][ty + i * 8];
        __nv_bfloat16 h = __float2bfloat16(v);
        __nv_bfloat16 l = __float2bfloat16(v - __bfloat162float(h));
        Thi[(long)nn * K + by + tx] = h;
        Tlo[(long)nn * K + by + tx] = l;
    }
}

// ----------------------------------------------------------------------------
// V transpose-split: V [B*Lkv, DIM] fp32 -> Vt hi/lo [b,h,d][Lkv] bf16
// ----------------------------------------------------------------------------
__global__ __launch_bounds__(256) void vtrans_split_kernel(
    const float* __restrict__ V, __nv_bfloat16* __restrict__ Thi,
    __nv_bfloat16* __restrict__ Tlo)
{
    __shared__ float tile[32][33];
    const int bx = blockIdx.x * 32;   // col base (h*64+d)
    const int by = blockIdx.y * 32;   // row base (b*1024+c)
    const int tx = threadIdx.x & 31;
    const int ty = threadIdx.x >> 5;
#pragma unroll
    for (int i = 0; i < 4; i++) {
        int rr = by + ty + i * 8;
        tile[ty + i * 8][tx] = V[(long)rr * DIM + bx + tx];
    }
    __syncthreads();
#pragma unroll
    for (int i = 0; i < 4; i++) {
        int colg = bx + ty + i * 8;
        int rowg = by + tx;
        int b = rowg >> 10, c = rowg & 1023;
        int h = colg >> 6,  d = colg & 63;
        float v = tile[tx][ty + i * 8];
        __nv_bfloat16 hh = __float2bfloat16(v);
        __nv_bfloat16 ll = __float2bfloat16(v - __bfloat162float(hh));
        long o = ((long)((b * NHEADS + h) * HDIM + d)) * LKV + c;
        Thi[o] = hh;
        Tlo[o] = ll;
    }
}

// ----------------------------------------------------------------------------
// Fused RMSNorm + RoPE -> bf16 hi/lo outputs
// ----------------------------------------------------------------------------
__global__ __launch_bounds__(256) void normrope_bf16_kernel(
    const float* __restrict__ in, __nv_bfloat16* __restrict__ outhi,
    __nv_bfloat16* __restrict__ outlo,
    const float* __restrict__ g, const float* __restrict__ cosb,
    const float* __restrict__ sinb)
{
    const int row = blockIdx.x;
    const float* h = in + (long)row * DIM;
    const int tid = threadIdx.x;
    const int e = tid << 2;

    float4 t = *(const float4*)&h[e];
    float ss = t.x * t.x + t.y * t.y + t.z * t.z + t.w * t.w;
#pragma unroll
    for (int o = 16; o > 0; o >>= 1)
        ss += __shfl_xor_sync(0xffffffffu, ss, o);
    __shared__ float red[8];
    if ((tid & 31) == 0) red[tid >> 5] = ss;
    __syncthreads();
    float tot = red[0] + red[1] + red[2] + red[3] + red[4] + red[5] + red[6] + red[7];
    float inv = rsqrtf(tot * (1.0f / (float)DIM) + 1e-6f);

    const int d   = e & (HDIM - 1);
    const int po  = (d < 32) ? 32 : -32;
    const float sgn = (d < 32) ? -1.0f : 1.0f;

    float4 tp  = *(const float4*)&h[e + po];
    float4 g4  = *(const float4*)&g[e];
    float4 gp4 = *(const float4*)&g[e + po];
    float4 c4  = *(const float4*)&cosb[(long)row * HDIM + d];
    float4 s4  = *(const float4*)&sinb[(long)row * HDIM + d];

    float4 o4;
    o4.x = t.x * inv * g4.x * c4.x + sgn * tp.x * inv * gp4.x * s4.x;
    o4.y = t.y * inv * g4.y * c4.y + sgn * tp.y * inv * gp4.y * s4.y;
    o4.z = t.z * inv * g4.z * c4.z + sgn * tp.z * inv * gp4.z * s4.z;
    o4.w = t.w * inv * g4.w * c4.w + sgn * tp.w * inv * gp4.w * s4.w;

    __nv_bfloat16 h0 = __float2bfloat16(o4.x), h1 = __float2bfloat16(o4.y);
    __nv_bfloat16 h2 = __float2bfloat16(o4.z), h3 = __float2bfloat16(o4.w);
    uint32_t ph0 = packbf2(o4.x, o4.y), ph1 = packbf2(o4.z, o4.w);
    uint32_t pl0 = packbf2(o4.x - __bfloat162float(h0), o4.y - __bfloat162float(h1));
    uint32_t pl1 = packbf2(o4.z - __bfloat162float(h2), o4.w - __bfloat162float(h3));
    *(uint2*)&outhi[(long)row * DIM + e] = make_uint2(ph0, ph1);
    *(uint2*)&outlo[(long)row * DIM + e] = make_uint2(pl0, pl1);
}

// ----------------------------------------------------------------------------
// Flash attention, bf16x3 mma.sync, 2-stage cp.async pipeline.
// CTA = 256 threads (8 warps), 128 q-rows per CTA (16 per warp).
// KV chunks of 64 shared by all 8 warps -> half the smem/L2 traffic per FLOP.
// ----------------------------------------------------------------------------
#define SK 72
#define ATT_STAGE_ELEMS (4 * 64 * SK)                 // Kh,Kl,Vh,Vl
#define ATT_SMEM_BYTES  (2 * ATT_STAGE_ELEMS * 2)     // 73728 B

__global__ __launch_bounds__(256, 2) void attn_mma_kernel(
    const __nv_bfloat16* __restrict__ qhi, const __nv_bfloat16* __restrict__ qlo,
    const __nv_bfloat16* __restrict__ khi, const __nv_bfloat16* __restrict__ klo,
    const __nv_bfloat16* __restrict__ vthi, const __nv_bfloat16* __restrict__ vtlo,
    __nv_bfloat16* __restrict__ ohi, __nv_bfloat16* __restrict__ olo)
{
    extern __shared__ __nv_bfloat16 dsm[];

    const int tid  = threadIdx.x;
    const int w    = tid >> 5;
    const int lane = tid & 31;
    const int tq   = lane >> 2;
    const int tr   = lane & 3;
    const int b    = blockIdx.x >> 4;
    const int h    = blockIdx.x & 15;
    const int q0   = blockIdx.y * 128;
    const float SCALE = 0.125f;

    // loader mapping (256 threads): row = tid>>2 (0..63), 16-col quarter
    const int lrow = tid >> 2, lqtr = (tid & 3) * 16;

    auto issue = [&](int c, int s) {
        __nv_bfloat16* sKh = dsm + s * ATT_STAGE_ELEMS;
        __nv_bfloat16* sKl = sKh + 64 * SK;
        __nv_bfloat16* sVh = sKl + 64 * SK;
        __nv_bfloat16* sVl = sVh + 64 * SK;
        const int j0 = c << 6;
        const __nv_bfloat16* kh_g = khi + ((long)(b * LKV + j0 + lrow)) * DIM + h * HDIM + lqtr;
        const __nv_bfloat16* kl_g = klo + ((long)(b * LKV + j0 + lrow)) * DIM + h * HDIM + lqtr;
        const long vo = ((long)((b * NHEADS + h) * HDIM + lrow)) * LKV + j0 + lqtr;
        const __nv_bfloat16* vh_g = vthi + vo;
        const __nv_bfloat16* vl_g = vtlo + vo;
        const int so = lrow * SK + lqtr;
        CP16(&sKh[so],     &kh_g[0]);
        CP16(&sKh[so + 8], &kh_g[8]);
        CP16(&sKl[so],     &kl_g[0]);
        CP16(&sKl[so + 8], &kl_g[8]);
        CP16(&sVh[so],     &vh_g[0]);
        CP16(&sVh[so + 8], &vh_g[8]);
        CP16(&sVl[so],     &vl_g[0]);
        CP16(&sVl[so + 8], &vl_g[8]);
    };

    // Q fragments, loaded once from gmem
    const long grow0 = (long)(b * LQ + q0 + w * 16 + tq);
    const __nv_bfloat16* qh0 = qhi + grow0 * DIM + h * HDIM;
    const __nv_bfloat16* ql0 = qlo + grow0 * DIM + h * HDIM;
    uint32_t aQh[4][4], aQl[4][4];
#pragma unroll
    for (int ks = 0; ks < 4; ks++) {
        const int c0 = ks * 16 + 2 * tr;
        aQh[ks][0] = *(const uint32_t*)&qh0[c0];
        aQh[ks][1] = *(const uint32_t*)&qh0[8 * DIM + c0];
        aQh[ks][2] = *(const uint32_t*)&qh0[c0 + 8];
        aQh[ks][3] = *(const uint32_t*)&qh0[8 * DIM + c0 + 8];
        aQl[ks][0] = *(const uint32_t*)&ql0[c0];
        aQl[ks][1] = *(const uint32_t*)&ql0[8 * DIM + c0];
        aQl[ks][2] = *(const uint32_t*)&ql0[c0 + 8];
        aQl[ks][3] = *(const uint32_t*)&ql0[8 * DIM + c0 + 8];
    }

    float oacc[8][4];
#pragma unroll
    for (int i = 0; i < 8; i++)
#pragma unroll
        for (int j = 0; j < 4; j++) oacc[i][j] = 0.f;
    float m[2] = {-1e30f, -1e30f}, l[2] = {0.f, 0.f};

    issue(0, 0);
    CP_COMMIT();

    const int NCH = LKV / 64;
    for (int c = 0; c < NCH; c++) {
        if (c + 1 < NCH) issue(c + 1, (c + 1) & 1);
        CP_COMMIT();
        CP_WAIT1();
        __syncthreads();

        const __nv_bfloat16* sKh = dsm + (c & 1) * ATT_STAGE_ELEMS;
        const __nv_bfloat16* sKl = sKh + 64 * SK;
        const __nv_bfloat16* sVh = sKl + 64 * SK;
        const __nv_bfloat16* sVl = sVh + 64 * SK;

        // ---- S = Q K^T (bf16x3) ----
        float s[8][4];
#pragma unroll
        for (int i = 0; i < 8; i++)
#pragma unroll
            for (int j = 0; j < 4; j++) s[i][j] = 0.f;

#pragma unroll
        for (int ks = 0; ks < 4; ks++) {
            const int kb = ks * 16 + 2 * tr;
#pragma unroll
            for (int nf = 0; nf < 8; nf++) {
                const int rB = (nf * 8 + tq) * SK + kb;
                uint32_t bh[2], bl[2];
                bh[0] = *(const uint32_t*)&sKh[rB];
                bh[1] = *(const uint32_t*)&sKh[rB + 8];
                bl[0] = *(const uint32_t*)&sKl[rB];
                bl[1] = *(const uint32_t*)&sKl[rB + 8];
                MMA16816(s[nf], aQh[ks], bh);
                MMA16816(s[nf], aQh[ks], bl);
                MMA16816(s[nf], aQl[ks], bh);
            }
        }

        // ---- online softmax (rows tq and tq+8) ----
#pragma unroll
        for (int r = 0; r < 2; r++) {
            float mx = -1e30f;
#pragma unroll
            for (int nf = 0; nf < 8; nf++)
                mx = fmaxf(mx, fmaxf(s[nf][2 * r], s[nf][2 * r + 1]));
            mx = fmaxf(mx, __shfl_xor_sync(0xffffffffu, mx, 1));
            mx = fmaxf(mx, __shfl_xor_sync(0xffffffffu, mx, 2));
            const float mn = fmaxf(m[r], mx);
            const float f  = __expf((m[r] - mn) * SCALE);
            float rs = 0.f;
#pragma unroll
            for (int nf = 0; nf < 8; nf++) {
                s[nf][2 * r]     = __expf((s[nf][2 * r]     - mn) * SCALE);
                s[nf][2 * r + 1] = __expf((s[nf][2 * r + 1] - mn) * SCALE);
                rs += s[nf][2 * r] + s[nf][2 * r + 1];
            }
            rs += __shfl_xor_sync(0xffffffffu, rs, 1);
            rs += __shfl_xor_sync(0xffffffffu, rs, 2);
            m[r] = mn;
            l[r] = l[r] * f + rs;
#pragma unroll
            for (int nf = 0; nf < 8; nf++) {
                oacc[nf][2 * r]     *= f;
                oacc[nf][2 * r + 1] *= f;
            }
        }

        // ---- O += P V (P hi/lo in registers; bf16x3) ----
#pragma unroll
        for (int ks = 0; ks < 4; ks++) {
            float v0 = s[2 * ks][0],     v1 = s[2 * ks][1];
            float v2 = s[2 * ks][2],     v3 = s[2 * ks][3];
            float v4 = s[2 * ks + 1][0], v5 = s[2 * ks + 1][1];
            float v6 = s[2 * ks + 1][2], v7 = s[2 * ks + 1][3];
            __nv_bfloat16 h0 = __float2bfloat16(v0), h1 = __float2bfloat16(v1);
            __nv_bfloat16 h2 = __float2bfloat16(v2), h3 = __float2bfloat16(v3);
            __nv_bfloat16 h4 = __float2bfloat16(v4), h5 = __float2bfloat16(v5);
            __nv_bfloat16 h6 = __float2bfloat16(v6), h7 = __float2bfloat16(v7);
            uint32_t aPh[4], aPl[4];
            aPh[0] = packbf2(v0, v1); aPh[1] = packbf2(v2, v3);
            aPh[2] = packbf2(v4, v5); aPh[3] = packbf2(v6, v7);
            aPl[0] = packbf2(v0 - __bfloat162float(h0), v1 - __bfloat162float(h1));
            aPl[1] = packbf2(v2 - __bfloat162float(h2), v3 - __bfloat162float(h3));
            aPl[2] = packbf2(v4 - __bfloat162float(h4), v5 - __bfloat162float(h5));
            aPl[3] = packbf2(v6 - __bfloat162float(h6), v7 - __bfloat162float(h7));

            const int kb = ks * 16 + 2 * tr;
#pragma unroll
            for (int nf = 0; nf < 8; nf++) {
                const int rB = (nf * 8 + tq) * SK + kb;
                uint32_t bh[2], bl[2];
                bh[0] = *(const uint32_t*)&sVh[rB];
                bh[1] = *(const uint32_t*)&sVh[rB + 8];
                bl[0] = *(const uint32_t*)&sVl[rB];
                bl[1] = *(const uint32_t*)&sVl[rB + 8];
                MMA16816(oacc[nf], aPh, bh);
                MMA16816(oacc[nf], aPh, bl);
                MMA16816(oacc[nf], aPl, bh);
            }
        }
        __syncthreads();
    }

    // ---- epilogue: O /= l, write bf16 hi/lo ----
    const float inv0 = 1.f / l[0], inv1 = 1.f / l[1];
    __nv_bfloat16* oh0 = ohi + grow0 * DIM + h * HDIM;
    __nv_bfloat16* ol0 = olo + grow0 * DIM + h * HDIM;
#pragma unroll
    for (int nf = 0; nf < 8; nf++) {
        const int col = nf * 8 + 2 * tr;
        float x0 = oacc[nf][0] * inv0, y0 = oacc[nf][1] * inv0;
        float x1 = oacc[nf][2] * inv1, y1 = oacc[nf][3] * inv1;
        __nv_bfloat16 hx0 = __float2bfloat16(x0), hy0 = __float2bfloat16(y0);
        __nv_bfloat16 hx1 = __float2bfloat16(x1), hy1 = __float2bfloat16(y1);
        *(uint32_t*)&oh0[col]           = packbf2(x0, y0);
        *(uint32_t*)&oh0[8 * DIM + col] = packbf2(x1, y1);
        *(uint32_t*)&ol0[col]           = packbf2(x0 - __bfloat162float(hx0), y0 - __bfloat162float(hy0));
        *(uint32_t*)&ol0[8 * DIM + col] = packbf2(x1 - __bfloat162float(hx1), y1 - __bfloat162float(hy1));
    }
}

// ----------------------------------------------------------------------------
// Launch
// ----------------------------------------------------------------------------
extern "C" void kernel_launch(void* const* d_in, const int* in_sizes, int n_in,
                              void* d_out, int out_size)
{
    const float* x     = (const float*)d_in[0];
    const float* y     = (const float*)d_in[1];
    const float* x_cos = (const float*)d_in[2];
    const float* x_sin = (const float*)d_in[3];
    const float* y_cos = (const float*)d_in[4];
    const float* y_sin = (const float*)d_in[5];
    const float* Wq    = (const float*)d_in[6];
    const float* bq    = (const float*)d_in[7];
    const float* Wk    = (const float*)d_in[8];
    const float* bk    = (const float*)d_in[9];
    const float* Wv    = (const float*)d_in[10];
    const float* bv    = (const float*)d_in[11];
    const float* Wo    = (const float*)d_in[12];
    const float* bo    = (const float*)d_in[13];
    const float* gq    = (const float*)d_in[14];
    const float* gk    = (const float*)d_in[15];
    float* out = (float*)d_out;

    float *qtmp, *ktmp, *vb;
    cudaGetSymbolAddress((void**)&qtmp, g_qtmp);
    cudaGetSymbolAddress((void**)&ktmp, g_ktmp);
    cudaGetSymbolAddress((void**)&vb,   g_v);

    __nv_bfloat16 *qhi, *qlo, *khi, *klo, *vthi, *vtlo;
    __nv_bfloat16 *xhi, *xlo, *yhi, *ylo;
    __nv_bfloat16 *wqh, *wql, *wkh, *wkl, *wvh, *wvl, *woh, *wol;
    cudaGetSymbolAddress((void**)&qhi, g_qhi);
    cudaGetSymbolAddress((void**)&qlo, g_qlo);
    cudaGetSymbolAddress((void**)&khi, g_khi);
    cudaGetSymbolAddress((void**)&klo, g_klo);
    cudaGetSymbolAddress((void**)&vthi, g_vthi);
    cudaGetSymbolAddress((void**)&vtlo, g_vtlo);
    cudaGetSymbolAddress((void**)&xhi, g_xhi);
    cudaGetSymbolAddress((void**)&xlo, g_xlo);
    cudaGetSymbolAddress((void**)&yhi, g_yhi);
    cudaGetSymbolAddress((void**)&ylo, g_ylo);
    cudaGetSymbolAddress((void**)&wqh, g_wqt_hi);
    cudaGetSymbolAddress((void**)&wql, g_wqt_lo);
    cudaGetSymbolAddress((void**)&wkh, g_wkt_hi);
    cudaGetSymbolAddress((void**)&wkl, g_wkt_lo);
    cudaGetSymbolAddress((void**)&wvh, g_wvt_hi);
    cudaGetSymbolAddress((void**)&wvl, g_wvt_lo);
    cudaGetSymbolAddress((void**)&woh, g_wot_hi);
    cudaGetSymbolAddress((void**)&wol, g_wot_lo);

    cudaFuncSetAttribute(gemm_bf16x3_mma_kernel,
                         cudaFuncAttributeMaxDynamicSharedMemorySize, GEMM_SMEM_BYTES);
    cudaFuncSetAttribute(attn_mma_kernel,
                         cudaFuncAttributeMaxDynamicSharedMemorySize, ATT_SMEM_BYTES);

    const int Mq = BATCH * LQ;    // 8192
    const int Mk = BATCH * LKV;   // 2048

    // Split activations + weights (weight transposes batched in pairs)
    split_bf16_kernel<<<(Mq * DIM / 4 + 255) / 256, 256>>>(x, xhi, xlo, Mq * DIM / 4);
    split_bf16_kernel<<<(Mk * KV_DIM / 4 + 255) / 256, 256>>>(y, yhi, ylo, Mk * KV_DIM / 4);
    split_transpose2_kernel<<<dim3(DIM / 32, DIM / 32, 2), 256>>>(
        Wq, wqh, wql, Wo, woh, wol, DIM, DIM);
    split_transpose2_kernel<<<dim3(DIM / 32, KV_DIM / 32, 2), 256>>>(
        Wk, wkh, wkl, Wv, wvh, wvl, KV_DIM, DIM);

    // Projections (mma.sync bf16x3, cp.async pipelined)
    gemm_bf16x3_mma_kernel<<<dim3(DIM / 128, Mq / 128), 256, GEMM_SMEM_BYTES>>>(
        xhi, xlo, wqh, wql, bq, qtmp, Mq, DIM, DIM);
    gemm_bf16x3_mma_kernel<<<dim3(DIM / 128, Mk / 128), 256, GEMM_SMEM_BYTES>>>(
        yhi, ylo, wkh, wkl, bk, ktmp, Mk, DIM, KV_DIM);
    gemm_bf16x3_mma_kernel<<<dim3(DIM / 128, Mk / 128), 256, GEMM_SMEM_BYTES>>>(
        yhi, ylo, wvh, wvl, bv, vb, Mk, DIM, KV_DIM);

    // RMSNorm + RoPE -> bf16 hi/lo; V -> transposed bf16 hi/lo
    normrope_bf16_kernel<<<Mq, 256>>>(qtmp, qhi, qlo, gq, x_cos, x_sin);
    normrope_bf16_kernel<<<Mk, 256>>>(ktmp, khi, klo, gk, y_cos, y_sin);
    vtrans_split_kernel<<<dim3(DIM / 32, Mk / 32), 256>>>(vb, vthi, vtlo);

    // Flash attention (tensor cores, cp.async pipelined, 128 q-rows/CTA)
    attn_mma_kernel<<<dim3(BATCH * NHEADS, LQ / 128), 256, ATT_SMEM_BYTES>>>(
        qhi, qlo, khi, klo, vthi, vtlo, xhi, xlo);

    // Output projection
    gemm_bf16x3_mma_kernel<<<dim3(DIM / 128, Mq / 128), 256, GEMM_SMEM_BYTES>>>(
        xhi, xlo, woh, wol, bo, out, Mq, DIM, DIM);
}

// round 10
// speedup vs baseline: 1.4169x; 1.4169x over previous
#include <cuda_runtime.h>
#include <cuda_bf16.h>
#include <cstdint>

// ----------------------------------------------------------------------------
// Problem constants
// ----------------------------------------------------------------------------
#define BATCH   2
#define LQ      4096
#define LKV     1024
#define DIM     1024
#define KV_DIM  768
#define NHEADS  16
#define HDIM    64

// ----------------------------------------------------------------------------
// Scratch (device globals; allocation-free per harness rules)
// ----------------------------------------------------------------------------
__device__ float g_qtmp[(BATCH*LQ)*DIM];   // Q proj out (fp32)
__device__ float g_ktmp[(BATCH*LKV)*DIM];  // K proj out (fp32)
__device__ float g_v   [(BATCH*LKV)*DIM];  // V proj out (fp32)

__device__ __nv_bfloat16 g_qhi[(BATCH*LQ)*DIM],  g_qlo[(BATCH*LQ)*DIM];
__device__ __nv_bfloat16 g_khi[(BATCH*LKV)*DIM], g_klo[(BATCH*LKV)*DIM];
__device__ __nv_bfloat16 g_vthi[(BATCH*LKV)*DIM], g_vtlo[(BATCH*LKV)*DIM]; // V^T [b,h,d,c]

__device__ __nv_bfloat16 g_xhi[(BATCH*LQ)*DIM],  g_xlo[(BATCH*LQ)*DIM];   // x split; later attn-out split
__device__ __nv_bfloat16 g_yhi[(BATCH*LKV)*KV_DIM], g_ylo[(BATCH*LKV)*KV_DIM];
__device__ __nv_bfloat16 g_wqt_hi[DIM*DIM],    g_wqt_lo[DIM*DIM];
__device__ __nv_bfloat16 g_wkt_hi[DIM*KV_DIM], g_wkt_lo[DIM*KV_DIM];
__device__ __nv_bfloat16 g_wvt_hi[DIM*KV_DIM], g_wvt_lo[DIM*KV_DIM];
__device__ __nv_bfloat16 g_wot_hi[DIM*DIM],    g_wot_lo[DIM*DIM];

// ----------------------------------------------------------------------------
// mma.sync / cp.async / ldmatrix helpers (baseline PTX)
// ----------------------------------------------------------------------------
#define MMA16816(d, a, b) \
    asm volatile("mma.sync.aligned.m16n8k16.row.col.f32.bf16.bf16.f32 " \
        "{%0,%1,%2,%3}, {%4,%5,%6,%7}, {%8,%9}, {%0,%1,%2,%3};" \
        : "+f"((d)[0]), "+f"((d)[1]), "+f"((d)[2]), "+f"((d)[3]) \
        : "r"((a)[0]), "r"((a)[1]), "r"((a)[2]), "r"((a)[3]), \
          "r"((b)[0]), "r"((b)[1]))

#define CP16(sp, gp) do { \
    uint32_t _s = (uint32_t)__cvta_generic_to_shared(sp); \
    asm volatile("cp.async.cg.shared.global [%0], [%1], 16;" :: "r"(_s), "l"(gp)); \
} while (0)
#define CP_COMMIT()  asm volatile("cp.async.commit_group;" ::: "memory")
#define CP_WAIT1()   asm volatile("cp.async.wait_group 1;" ::: "memory")

#define LDSM_X4(r, addr) \
    asm volatile("ldmatrix.sync.aligned.m8n8.x4.shared.b16 {%0,%1,%2,%3}, [%4];" \
        : "=r"((r)[0]), "=r"((r)[1]), "=r"((r)[2]), "=r"((r)[3]) : "r"(addr))
#define LDSM_X2(r, addr) \
    asm volatile("ldmatrix.sync.aligned.m8n8.x2.shared.b16 {%0,%1}, [%2];" \
        : "=r"((r)[0]), "=r"((r)[1]) : "r"(addr))

__device__ __forceinline__ uint32_t packbf2(float x, float y) {
    __nv_bfloat162 t = __float22bfloat162_rn(make_float2(x, y));
    return *reinterpret_cast<uint32_t*>(&t);
}

// ----------------------------------------------------------------------------
// bf16x3 GEMM, 2-stage cp.async pipeline + ldmatrix fragment loads:
//   C[M,N] = A[M,K] @ Bt[N,K]^T + bias
//   CTA tile 128x128, BK=32, 256 threads (2x4 warps), warp tile 64x32.
// ----------------------------------------------------------------------------
#define SSTR 40
#define GEMM_STAGE_ELEMS (4 * 128 * SSTR)
#define GEMM_STAGE_BYTES (GEMM_STAGE_ELEMS * 2)
#define GEMM_TILE_BYTES  (128 * SSTR * 2)
#define GEMM_SMEM_BYTES  (2 * GEMM_STAGE_BYTES)           // 81920 B

__global__ __launch_bounds__(256, 2) void gemm_bf16x3_mma_kernel(
    const __nv_bfloat16* __restrict__ Ahi, const __nv_bfloat16* __restrict__ Alo,
    const __nv_bfloat16* __restrict__ Bhi, const __nv_bfloat16* __restrict__ Blo,
    const float* __restrict__ bias, float* __restrict__ C,
    int M, int N, int K)
{
    extern __shared__ __nv_bfloat16 dsm[];
    const uint32_t dsmAddr = (uint32_t)__cvta_generic_to_shared(dsm);

    const int tid  = threadIdx.x;
    const int wid  = tid >> 5;
    const int lane = tid & 31;
    const int warpM = wid >> 2;
    const int warpN = wid & 3;
    const int bm = blockIdx.y * 128;
    const int bn = blockIdx.x * 128;
    const int tq = lane >> 2;
    const int tr = lane & 3;

    // gmem loader mapping
    const int r0g = tid >> 2;
    const int r1g = r0g + 64;
    const int c0g = (tid & 3) * 8;

    // ldmatrix per-lane byte offsets within a tile
    const uint32_t aRowOff = (uint32_t)(((warpM * 64 + (lane & 15)) * SSTR + ((lane >> 4) << 3)) * 2);
    const uint32_t bRowOff = (uint32_t)(((warpN * 32 + (lane & 7))  * SSTR + (((lane >> 3) & 1) << 3)) * 2);

    float acc[4][4][4];
#pragma unroll
    for (int i = 0; i < 4; i++)
#pragma unroll
        for (int j = 0; j < 4; j++)
#pragma unroll
            for (int r = 0; r < 4; r++) acc[i][j][r] = 0.f;

    const int nchunks = K >> 5;

    auto issue = [&](int c, int s) {
        __nv_bfloat16* sAh = dsm + s * GEMM_STAGE_ELEMS;
        __nv_bfloat16* sAl = sAh + 128 * SSTR;
        __nv_bfloat16* sBh = sAl + 128 * SSTR;
        __nv_bfloat16* sBl = sBh + 128 * SSTR;
        const int k0 = c << 5;
        const long a0 = (long)(bm + r0g) * K + k0 + c0g;
        const long a1 = (long)(bm + r1g) * K + k0 + c0g;
        const long b0 = (long)(bn + r0g) * K + k0 + c0g;
        const long b1 = (long)(bn + r1g) * K + k0 + c0g;
        CP16(&sAh[r0g * SSTR + c0g], &Ahi[a0]);
        CP16(&sAh[r1g * SSTR + c0g], &Ahi[a1]);
        CP16(&sAl[r0g * SSTR + c0g], &Alo[a0]);
        CP16(&sAl[r1g * SSTR + c0g], &Alo[a1]);
        CP16(&sBh[r0g * SSTR + c0g], &Bhi[b0]);
        CP16(&sBh[r1g * SSTR + c0g], &Bhi[b1]);
        CP16(&sBl[r0g * SSTR + c0g], &Blo[b0]);
        CP16(&sBl[r1g * SSTR + c0g], &Blo[b1]);
    };

    issue(0, 0);
    CP_COMMIT();

    for (int c = 0; c < nchunks; c++) {
        if (c + 1 < nchunks) issue(c + 1, (c + 1) & 1);
        CP_COMMIT();
        CP_WAIT1();
        __syncthreads();

        const uint32_t stAh = dsmAddr + (c & 1) * GEMM_STAGE_BYTES;
        const uint32_t stAl = stAh + GEMM_TILE_BYTES;
        const uint32_t stBh = stAl + GEMM_TILE_BYTES;
        const uint32_t stBl = stBh + GEMM_TILE_BYTES;

#pragma unroll
        for (int ks = 0; ks < 2; ks++) {
            const uint32_t ksOff = (uint32_t)(ks * 16 * 2);
            uint32_t ah[4][4], al[4][4];
#pragma unroll
            for (int mf = 0; mf < 4; mf++) {
                const uint32_t mOff = (uint32_t)(mf * 16 * SSTR * 2) + aRowOff + ksOff;
                LDSM_X4(ah[mf], stAh + mOff);
                LDSM_X4(al[mf], stAl + mOff);
            }
#pragma unroll
            for (int nf = 0; nf < 4; nf++) {
                const uint32_t nOff = (uint32_t)(nf * 8 * SSTR * 2) + bRowOff + ksOff;
                uint32_t bh[2], bl[2];
                LDSM_X2(bh, stBh + nOff);
                LDSM_X2(bl, stBl + nOff);
#pragma unroll
                for (int mf = 0; mf < 4; mf++) {
                    MMA16816(acc[mf][nf], ah[mf], bh);
                    MMA16816(acc[mf][nf], ah[mf], bl);
                    MMA16816(acc[mf][nf], al[mf], bh);
                }
            }
        }
        __syncthreads();
    }

#pragma unroll
    for (int mf = 0; mf < 4; mf++) {
        const int row = bm + warpM * 64 + mf * 16 + tq;
#pragma unroll
        for (int nf = 0; nf < 4; nf++) {
            const int col = bn + warpN * 32 + nf * 8 + tr * 2;
            const float b0 = bias[col], b1 = bias[col + 1];
            float2 v0 = make_float2(acc[mf][nf][0] + b0, acc[mf][nf][1] + b1);
            float2 v1 = make_float2(acc[mf][nf][2] + b0, acc[mf][nf][3] + b1);
            *(float2*)&C[(long)row * N + col]       = v0;
            *(float2*)&C[(long)(row + 8) * N + col] = v1;
        }
    }
}

// ----------------------------------------------------------------------------
// Split fp32 -> bf16 hi + lo (elementwise)
// ----------------------------------------------------------------------------
__global__ __launch_bounds__(256) void split_bf16_kernel(
    const float* __restrict__ src, __nv_bfloat16* __restrict__ hi,
    __nv_bfloat16* __restrict__ lo, int n4)
{
    int i = blockIdx.x * blockDim.x + threadIdx.x;
    if (i >= n4) return;
    float4 v = *(const float4*)&src[(long)i * 4];
    __nv_bfloat16 h0 = __float2bfloat16(v.x), h1 = __float2bfloat16(v.y);
    __nv_bfloat16 h2 = __float2bfloat16(v.z), h3 = __float2bfloat16(v.w);
    uint32_t ph0 = packbf2(v.x, v.y), ph1 = packbf2(v.z, v.w);
    uint32_t pl0 = packbf2(v.x - __bfloat162float(h0), v.y - __bfloat162float(h1));
    uint32_t pl1 = packbf2(v.z - __bfloat162float(h2), v.w - __bfloat162float(h3));
    *(uint2*)&hi[(long)i * 4] = make_uint2(ph0, ph1);
    *(uint2*)&lo[(long)i * 4] = make_uint2(pl0, pl1);
}

// ----------------------------------------------------------------------------
// Split + transpose, batched pair: z=0 -> (W0,...), z=1 -> (W1,...)
// ----------------------------------------------------------------------------
__global__ __launch_bounds__(256) void split_transpose2_kernel(
    const float* __restrict__ W0, __nv_bfloat16* __restrict__ T0hi, __nv_bfloat16* __restrict__ T0lo,
    const float* __restrict__ W1, __nv_bfloat16* __restrict__ T1hi, __nv_bfloat16* __restrict__ T1lo,
    int K, int N)
{
    const float* W = blockIdx.z ? W1 : W0;
    __nv_bfloat16* Thi = blockIdx.z ? T1hi : T0hi;
    __nv_bfloat16* Tlo = blockIdx.z ? T1lo : T0lo;

    __shared__ float tile[32][33];
    const int bx = blockIdx.x * 32;
    const int by = blockIdx.y * 32;
    const int tx = threadIdx.x & 31;
    const int ty = threadIdx.x >> 5;
#pragma unroll
    for (int i = 0; i < 4; i++) {
        int kk = by + ty + i * 8;
        tile[ty + i * 8][tx] = W[(long)kk * N + bx + tx];
    }
    __syncthreads();
#pragma unroll
    for (int i = 0; i < 4; i++) {
        int nn = bx + ty + i * 8;
        float v = tile[tx][ty + i * 8];
        __nv_bfloat16 h = __float2bfloat16(v);
        __nv_bfloat16 l = __float2bfloat16(v - __bfloat162float(h));
        Thi[(long)nn * K + by + tx] = h;
        Tlo[(long)nn * K + by + tx] = l;
    }
}

// ----------------------------------------------------------------------------
// V transpose-split: V [B*Lkv, DIM] fp32 -> Vt hi/lo [b,h,d][Lkv] bf16
// ----------------------------------------------------------------------------
__global__ __launch_bounds__(256) void vtrans_split_kernel(
    const float* __restrict__ V, __nv_bfloat16* __restrict__ Thi,
    __nv_bfloat16* __restrict__ Tlo)
{
    __shared__ float tile[32][33];
    const int bx = blockIdx.x * 32;
    const int by = blockIdx.y * 32;
    const int tx = threadIdx.x & 31;
    const int ty = threadIdx.x >> 5;
#pragma unroll
    for (int i = 0; i < 4; i++) {
        int rr = by + ty + i * 8;
        tile[ty + i * 8][tx] = V[(long)rr * DIM + bx + tx];
    }
    __syncthreads();
#pragma unroll
    for (int i = 0; i < 4; i++) {
        int colg = bx + ty + i * 8;
        int rowg = by + tx;
        int b = rowg >> 10, c = rowg & 1023;
        int h = colg >> 6,  d = colg & 63;
        float v = tile[tx][ty + i * 8];
        __nv_bfloat16 hh = __float2bfloat16(v);
        __nv_bfloat16 ll = __float2bfloat16(v - __bfloat162float(hh));
        long o = ((long)((b * NHEADS + h) * HDIM + d)) * LKV + c;
        Thi[o] = hh;
        Tlo[o] = ll;
    }
}

// ----------------------------------------------------------------------------
// Fused RMSNorm + RoPE -> bf16 hi/lo outputs
// ----------------------------------------------------------------------------
__global__ __launch_bounds__(256) void normrope_bf16_kernel(
    const float* __restrict__ in, __nv_bfloat16* __restrict__ outhi,
    __nv_bfloat16* __restrict__ outlo,
    const float* __restrict__ g, const float* __restrict__ cosb,
    const float* __restrict__ sinb)
{
    const int row = blockIdx.x;
    const float* h = in + (long)row * DIM;
    const int tid = threadIdx.x;
    const int e = tid << 2;

    float4 t = *(const float4*)&h[e];
    float ss = t.x * t.x + t.y * t.y + t.z * t.z + t.w * t.w;
#pragma unroll
    for (int o = 16; o > 0; o >>= 1)
        ss += __shfl_xor_sync(0xffffffffu, ss, o);
    __shared__ float red[8];
    if ((tid & 31) == 0) red[tid >> 5] = ss;
    __syncthreads();
    float tot = red[0] + red[1] + red[2] + red[3] + red[4] + red[5] + red[6] + red[7];
    float inv = rsqrtf(tot * (1.0f / (float)DIM) + 1e-6f);

    const int d   = e & (HDIM - 1);
    const int po  = (d < 32) ? 32 : -32;
    const float sgn = (d < 32) ? -1.0f : 1.0f;

    float4 tp  = *(const float4*)&h[e + po];
    float4 g4  = *(const float4*)&g[e];
    float4 gp4 = *(const float4*)&g[e + po];
    float4 c4  = *(const float4*)&cosb[(long)row * HDIM + d];
    float4 s4  = *(const float4*)&sinb[(long)row * HDIM + d];

    float4 o4;
    o4.x = t.x * inv * g4.x * c4.x + sgn * tp.x * inv * gp4.x * s4.x;
    o4.y = t.y * inv * g4.y * c4.y + sgn * tp.y * inv * gp4.y * s4.y;
    o4.z = t.z * inv * g4.z * c4.z + sgn * tp.z * inv * gp4.z * s4.z;
    o4.w = t.w * inv * g4.w * c4.w + sgn * tp.w * inv * gp4.w * s4.w;

    __nv_bfloat16 h0 = __float2bfloat16(o4.x), h1 = __float2bfloat16(o4.y);
    __nv_bfloat16 h2 = __float2bfloat16(o4.z), h3 = __float2bfloat16(o4.w);
    uint32_t ph0 = packbf2(o4.x, o4.y), ph1 = packbf2(o4.z, o4.w);
    uint32_t pl0 = packbf2(o4.x - __bfloat162float(h0), o4.y - __bfloat162float(h1));
    uint32_t pl1 = packbf2(o4.z - __bfloat162float(h2), o4.w - __bfloat162float(h3));
    *(uint2*)&outhi[(long)row * DIM + e] = make_uint2(ph0, ph1);
    *(uint2*)&outlo[(long)row * DIM + e] = make_uint2(pl0, pl1);
}

// ----------------------------------------------------------------------------
// Flash attention, bf16x3 mma.sync, 2-stage cp.async pipeline.
// CTA = 128 threads (4 warps), 64 q-rows per CTA. KV chunks of 64.
// (Reverted to the proven R8 configuration — 256-thread variant spilled.)
// ----------------------------------------------------------------------------
#define SK 72
#define ATT_STAGE_ELEMS (4 * 64 * SK)
#define ATT_SMEM_BYTES  (2 * ATT_STAGE_ELEMS * 2)     // 73728 B

__global__ __launch_bounds__(128, 3) void attn_mma_kernel(
    const __nv_bfloat16* __restrict__ qhi, const __nv_bfloat16* __restrict__ qlo,
    const __nv_bfloat16* __restrict__ khi, const __nv_bfloat16* __restrict__ klo,
    const __nv_bfloat16* __restrict__ vthi, const __nv_bfloat16* __restrict__ vtlo,
    __nv_bfloat16* __restrict__ ohi, __nv_bfloat16* __restrict__ olo)
{
    extern __shared__ __nv_bfloat16 dsm[];

    const int tid  = threadIdx.x;
    const int w    = tid >> 5;
    const int lane = tid & 31;
    const int tq   = lane >> 2;
    const int tr   = lane & 3;
    const int b    = blockIdx.x >> 4;
    const int h    = blockIdx.x & 15;
    const int q0   = blockIdx.y * 64;
    const float SCALE = 0.125f;

    const int lrow = tid >> 1, lhalf = (tid & 1) * 32;

    auto issue = [&](int c, int s) {
        __nv_bfloat16* sKh = dsm + s * ATT_STAGE_ELEMS;
        __nv_bfloat16* sKl = sKh + 64 * SK;
        __nv_bfloat16* sVh = sKl + 64 * SK;
        __nv_bfloat16* sVl = sVh + 64 * SK;
        const int j0 = c << 6;
        const __nv_bfloat16* kh_g = khi + ((long)(b * LKV + j0 + lrow)) * DIM + h * HDIM + lhalf;
        const __nv_bfloat16* kl_g = klo + ((long)(b * LKV + j0 + lrow)) * DIM + h * HDIM + lhalf;
        const long vo = ((long)((b * NHEADS + h) * HDIM + lrow)) * LKV + j0 + lhalf;
        const __nv_bfloat16* vh_g = vthi + vo;
        const __nv_bfloat16* vl_g = vtlo + vo;
#pragma unroll
        for (int u = 0; u < 4; u++) {
            const int so = lrow * SK + lhalf + u * 8;
            CP16(&sKh[so], &kh_g[u * 8]);
            CP16(&sKl[so], &kl_g[u * 8]);
            CP16(&sVh[so], &vh_g[u * 8]);
            CP16(&sVl[so], &vl_g[u * 8]);
        }
    };

    const long grow0 = (long)(b * LQ + q0 + w * 16 + tq);
    const __nv_bfloat16* qh0 = qhi + grow0 * DIM + h * HDIM;
    const __nv_bfloat16* ql0 = qlo + grow0 * DIM + h * HDIM;
    uint32_t aQh[4][4], aQl[4][4];
#pragma unroll
    for (int ks = 0; ks < 4; ks++) {
        const int c0 = ks * 16 + 2 * tr;
        aQh[ks][0] = *(const uint32_t*)&qh0[c0];
        aQh[ks][1] = *(const uint32_t*)&qh0[8 * DIM + c0];
        aQh[ks][2] = *(const uint32_t*)&qh0[c0 + 8];
        aQh[ks][3] = *(const uint32_t*)&qh0[8 * DIM + c0 + 8];
        aQl[ks][0] = *(const uint32_t*)&ql0[c0];
        aQl[ks][1] = *(const uint32_t*)&ql0[8 * DIM + c0];
        aQl[ks][2] = *(const uint32_t*)&ql0[c0 + 8];
        aQl[ks][3] = *(const uint32_t*)&ql0[8 * DIM + c0 + 8];
    }

    float oacc[8][4];
#pragma unroll
    for (int i = 0; i < 8; i++)
#pragma unroll
        for (int j = 0; j < 4; j++) oacc[i][j] = 0.f;
    float m[2] = {-1e30f, -1e30f}, l[2] = {0.f, 0.f};

    issue(0, 0);
    CP_COMMIT();

    const int NCH = LKV / 64;
    for (int c = 0; c < NCH; c++) {
        if (c + 1 < NCH) issue(c + 1, (c + 1) & 1);
        CP_COMMIT();
        CP_WAIT1();
        __syncthreads();

        const __nv_bfloat16* sKh = dsm + (c & 1) * ATT_STAGE_ELEMS;
        const __nv_bfloat16* sKl = sKh + 64 * SK;
        const __nv_bfloat16* sVh = sKl + 64 * SK;
        const __nv_bfloat16* sVl = sVh + 64 * SK;

        float s[8][4];
#pragma unroll
        for (int i = 0; i < 8; i++)
#pragma unroll
            for (int j = 0; j < 4; j++) s[i][j] = 0.f;

#pragma unroll
        for (int ks = 0; ks < 4; ks++) {
            const int kb = ks * 16 + 2 * tr;
#pragma unroll
            for (int nf = 0; nf < 8; nf++) {
                const int rB = (nf * 8 + tq) * SK + kb;
                uint32_t bh[2], bl[2];
                bh[0] = *(const uint32_t*)&sKh[rB];
                bh[1] = *(const uint32_t*)&sKh[rB + 8];
                bl[0] = *(const uint32_t*)&sKl[rB];
                bl[1] = *(const uint32_t*)&sKl[rB + 8];
                MMA16816(s[nf], aQh[ks], bh);
                MMA16816(s[nf], aQh[ks], bl);
                MMA16816(s[nf], aQl[ks], bh);
            }
        }

#pragma unroll
        for (int r = 0; r < 2; r++) {
            float mx = -1e30f;
#pragma unroll
            for (int nf = 0; nf < 8; nf++)
                mx = fmaxf(mx, fmaxf(s[nf][2 * r], s[nf][2 * r + 1]));
            mx = fmaxf(mx, __shfl_xor_sync(0xffffffffu, mx, 1));
            mx = fmaxf(mx, __shfl_xor_sync(0xffffffffu, mx, 2));
            const float mn = fmaxf(m[r], mx);
            const float f  = __expf((m[r] - mn) * SCALE);
            float rs = 0.f;
#pragma unroll
            for (int nf = 0; nf < 8; nf++) {
                s[nf][2 * r]     = __expf((s[nf][2 * r]     - mn) * SCALE);
                s[nf][2 * r + 1] = __expf((s[nf][2 * r + 1] - mn) * SCALE);
                rs += s[nf][2 * r] + s[nf][2 * r + 1];
            }
            rs += __shfl_xor_sync(0xffffffffu, rs, 1);
            rs += __shfl_xor_sync(0xffffffffu, rs, 2);
            m[r] = mn;
            l[r] = l[r] * f + rs;
#pragma unroll
            for (int nf = 0; nf < 8; nf++) {
                oacc[nf][2 * r]     *= f;
                oacc[nf][2 * r + 1] *= f;
            }
        }

#pragma unroll
        for (int ks = 0; ks < 4; ks++) {
            float v0 = s[2 * ks][0],     v1 = s[2 * ks][1];
            float v2 = s[2 * ks][2],     v3 = s[2 * ks][3];
            float v4 = s[2 * ks + 1][0], v5 = s[2 * ks + 1][1];
            float v6 = s[2 * ks + 1][2], v7 = s[2 * ks + 1][3];
            __nv_bfloat16 h0 = __float2bfloat16(v0), h1 = __float2bfloat16(v1);
            __nv_bfloat16 h2 = __float2bfloat16(v2), h3 = __float2bfloat16(v3);
            __nv_bfloat16 h4 = __float2bfloat16(v4), h5 = __float2bfloat16(v5);
            __nv_bfloat16 h6 = __float2bfloat16(v6), h7 = __float2bfloat16(v7);
            uint32_t aPh[4], aPl[4];
            aPh[0] = packbf2(v0, v1); aPh[1] = packbf2(v2, v3);
            aPh[2] = packbf2(v4, v5); aPh[3] = packbf2(v6, v7);
            aPl[0] = packbf2(v0 - __bfloat162float(h0), v1 - __bfloat162float(h1));
            aPl[1] = packbf2(v2 - __bfloat162float(h2), v3 - __bfloat162float(h3));
            aPl[2] = packbf2(v4 - __bfloat162float(h4), v5 - __bfloat162float(h5));
            aPl[3] = packbf2(v6 - __bfloat162float(h6), v7 - __bfloat162float(h7));

            const int kb = ks * 16 + 2 * tr;
#pragma unroll
            for (int nf = 0; nf < 8; nf++) {
                const int rB = (nf * 8 + tq) * SK + kb;
                uint32_t bh[2], bl[2];
                bh[0] = *(const uint32_t*)&sVh[rB];
                bh[1] = *(const uint32_t*)&sVh[rB + 8];
                bl[0] = *(const uint32_t*)&sVl[rB];
                bl[1] = *(const uint32_t*)&sVl[rB + 8];
                MMA16816(oacc[nf], aPh, bh);
                MMA16816(oacc[nf], aPh, bl);
                MMA16816(oacc[nf], aPl, bh);
            }
        }
        __syncthreads();
    }

    const float inv0 = 1.f / l[0], inv1 = 1.f / l[1];
    __nv_bfloat16* oh0 = ohi + grow0 * DIM + h * HDIM;
    __nv_bfloat16* ol0 = olo + grow0 * DIM + h * HDIM;
#pragma unroll
    for (int nf = 0; nf < 8; nf++) {
        const int col = nf * 8 + 2 * tr;
        float x0 = oacc[nf][0] * inv0, y0 = oacc[nf][1] * inv0;
        float x1 = oacc[nf][2] * inv1, y1 = oacc[nf][3] * inv1;
        __nv_bfloat16 hx0 = __float2bfloat16(x0), hy0 = __float2bfloat16(y0);
        __nv_bfloat16 hx1 = __float2bfloat16(x1), hy1 = __float2bfloat16(y1);
        *(uint32_t*)&oh0[col]           = packbf2(x0, y0);
        *(uint32_t*)&oh0[8 * DIM + col] = packbf2(x1, y1);
        *(uint32_t*)&ol0[col]           = packbf2(x0 - __bfloat162float(hx0), y0 - __bfloat162float(hy0));
        *(uint32_t*)&ol0[8 * DIM + col] = packbf2(x1 - __bfloat162float(hx1), y1 - __bfloat162float(hy1));
    }
}

// ----------------------------------------------------------------------------
// Launch
// ----------------------------------------------------------------------------
extern "C" void kernel_launch(void* const* d_in, const int* in_sizes, int n_in,
                              void* d_out, int out_size)
{
    const float* x     = (const float*)d_in[0];
    const float* y     = (const float*)d_in[1];
    const float* x_cos = (const float*)d_in[2];
    const float* x_sin = (const float*)d_in[3];
    const float* y_cos = (const float*)d_in[4];
    const float* y_sin = (const float*)d_in[5];
    const float* Wq    = (const float*)d_in[6];
    const float* bq    = (const float*)d_in[7];
    const float* Wk    = (const float*)d_in[8];
    const float* bk    = (const float*)d_in[9];
    const float* Wv    = (const float*)d_in[10];
    const float* bv    = (const float*)d_in[11];
    const float* Wo    = (const float*)d_in[12];
    const float* bo    = (const float*)d_in[13];
    const float* gq    = (const float*)d_in[14];
    const float* gk    = (const float*)d_in[15];
    float* out = (float*)d_out;

    float *qtmp, *ktmp, *vb;
    cudaGetSymbolAddress((void**)&qtmp, g_qtmp);
    cudaGetSymbolAddress((void**)&ktmp, g_ktmp);
    cudaGetSymbolAddress((void**)&vb,   g_v);

    __nv_bfloat16 *qhi, *qlo, *khi, *klo, *vthi, *vtlo;
    __nv_bfloat16 *xhi, *xlo, *yhi, *ylo;
    __nv_bfloat16 *wqh, *wql, *wkh, *wkl, *wvh, *wvl, *woh, *wol;
    cudaGetSymbolAddress((void**)&qhi, g_qhi);
    cudaGetSymbolAddress((void**)&qlo, g_qlo);
    cudaGetSymbolAddress((void**)&khi, g_khi);
    cudaGetSymbolAddress((void**)&klo, g_klo);
    cudaGetSymbolAddress((void**)&vthi, g_vthi);
    cudaGetSymbolAddress((void**)&vtlo, g_vtlo);
    cudaGetSymbolAddress((void**)&xhi, g_xhi);
    cudaGetSymbolAddress((void**)&xlo, g_xlo);
    cudaGetSymbolAddress((void**)&yhi, g_yhi);
    cudaGetSymbolAddress((void**)&ylo, g_ylo);
    cudaGetSymbolAddress((void**)&wqh, g_wqt_hi);
    cudaGetSymbolAddress((void**)&wql, g_wqt_lo);
    cudaGetSymbolAddress((void**)&wkh, g_wkt_hi);
    cudaGetSymbolAddress((void**)&wkl, g_wkt_lo);
    cudaGetSymbolAddress((void**)&wvh, g_wvt_hi);
    cudaGetSymbolAddress((void**)&wvl, g_wvt_lo);
    cudaGetSymbolAddress((void**)&woh, g_wot_hi);
    cudaGetSymbolAddress((void**)&wol, g_wot_lo);

    cudaFuncSetAttribute(gemm_bf16x3_mma_kernel,
                         cudaFuncAttributeMaxDynamicSharedMemorySize, GEMM_SMEM_BYTES);
    cudaFuncSetAttribute(attn_mma_kernel,
                         cudaFuncAttributeMaxDynamicSharedMemorySize, ATT_SMEM_BYTES);

    const int Mq = BATCH * LQ;    // 8192
    const int Mk = BATCH * LKV;   // 2048

    // Split activations + weights (weight transposes batched in pairs)
    split_bf16_kernel<<<(Mq * DIM / 4 + 255) / 256, 256>>>(x, xhi, xlo, Mq * DIM / 4);
    split_bf16_kernel<<<(Mk * KV_DIM / 4 + 255) / 256, 256>>>(y, yhi, ylo, Mk * KV_DIM / 4);
    split_transpose2_kernel<<<dim3(DIM / 32, DIM / 32, 2), 256>>>(
        Wq, wqh, wql, Wo, woh, wol, DIM, DIM);
    split_transpose2_kernel<<<dim3(DIM / 32, KV_DIM / 32, 2), 256>>>(
        Wk, wkh, wkl, Wv, wvh, wvl, KV_DIM, DIM);

    // Projections (mma.sync bf16x3, cp.async pipelined, ldmatrix frags)
    gemm_bf16x3_mma_kernel<<<dim3(DIM / 128, Mq / 128), 256, GEMM_SMEM_BYTES>>>(
        xhi, xlo, wqh, wql, bq, qtmp, Mq, DIM, DIM);
    gemm_bf16x3_mma_kernel<<<dim3(DIM / 128, Mk / 128), 256, GEMM_SMEM_BYTES>>>(
        yhi, ylo, wkh, wkl, bk, ktmp, Mk, DIM, KV_DIM);
    gemm_bf16x3_mma_kernel<<<dim3(DIM / 128, Mk / 128), 256, GEMM_SMEM_BYTES>>>(
        yhi, ylo, wvh, wvl, bv, vb, Mk, DIM, KV_DIM);

    // RMSNorm + RoPE -> bf16 hi/lo; V -> transposed bf16 hi/lo
    normrope_bf16_kernel<<<Mq, 256>>>(qtmp, qhi, qlo, gq, x_cos, x_sin);
    normrope_bf16_kernel<<<Mk, 256>>>(ktmp, khi, klo, gk, y_cos, y_sin);
    vtrans_split_kernel<<<dim3(DIM / 32, Mk / 32), 256>>>(vb, vthi, vtlo);

    // Flash attention (tensor cores, cp.async pipelined, 64 q-rows/CTA)
    attn_mma_kernel<<<dim3(BATCH * NHEADS, LQ / 64), 128, ATT_SMEM_BYTES>>>(
        qhi, qlo, khi, klo, vthi, vtlo, xhi, xlo);

    // Output projection
    gemm_bf16x3_mma_kernel<<<dim3(DIM / 128, Mq / 128), 256, GEMM_SMEM_BYTES>>>(
        xhi, xlo, woh, wol, bo, out, Mq, DIM, DIM);
}

// round 11
// speedup vs baseline: 1.4205x; 1.0025x over previous
#include <cuda_runtime.h>
#include <cuda_bf16.h>
#include <cstdint>

// ----------------------------------------------------------------------------
// Problem constants
// ----------------------------------------------------------------------------
#define BATCH   2
#define LQ      4096
#define LKV     1024
#define DIM     1024
#define KV_DIM  768
#define NHEADS  16
#define HDIM    64

// ----------------------------------------------------------------------------
// Scratch (device globals; allocation-free per harness rules)
// ----------------------------------------------------------------------------
__device__ float g_qtmp[(BATCH*LQ)*DIM];
__device__ float g_ktmp[(BATCH*LKV)*DIM];
__device__ float g_v   [(BATCH*LKV)*DIM];

__device__ __nv_bfloat16 g_qhi[(BATCH*LQ)*DIM],  g_qlo[(BATCH*LQ)*DIM];
__device__ __nv_bfloat16 g_khi[(BATCH*LKV)*DIM], g_klo[(BATCH*LKV)*DIM];
__device__ __nv_bfloat16 g_vthi[(BATCH*LKV)*DIM], g_vtlo[(BATCH*LKV)*DIM];

__device__ __nv_bfloat16 g_xhi[(BATCH*LQ)*DIM],  g_xlo[(BATCH*LQ)*DIM];
__device__ __nv_bfloat16 g_yhi[(BATCH*LKV)*KV_DIM], g_ylo[(BATCH*LKV)*KV_DIM];
__device__ __nv_bfloat16 g_wqt_hi[DIM*DIM],    g_wqt_lo[DIM*DIM];
__device__ __nv_bfloat16 g_wkt_hi[DIM*KV_DIM], g_wkt_lo[DIM*KV_DIM];
__device__ __nv_bfloat16 g_wvt_hi[DIM*KV_DIM], g_wvt_lo[DIM*KV_DIM];
__device__ __nv_bfloat16 g_wot_hi[DIM*DIM],    g_wot_lo[DIM*DIM];

// ----------------------------------------------------------------------------
// mma.sync / cp.async / ldmatrix helpers (baseline PTX)
// ----------------------------------------------------------------------------
#define MMA16816(d, a, b) \
    asm volatile("mma.sync.aligned.m16n8k16.row.col.f32.bf16.bf16.f32 " \
        "{%0,%1,%2,%3}, {%4,%5,%6,%7}, {%8,%9}, {%0,%1,%2,%3};" \
        : "+f"((d)[0]), "+f"((d)[1]), "+f"((d)[2]), "+f"((d)[3]) \
        : "r"((a)[0]), "r"((a)[1]), "r"((a)[2]), "r"((a)[3]), \
          "r"((b)[0]), "r"((b)[1]))

#define CP16(sp, gp) do { \
    uint32_t _s = (uint32_t)__cvta_generic_to_shared(sp); \
    asm volatile("cp.async.cg.shared.global [%0], [%1], 16;" :: "r"(_s), "l"(gp)); \
} while (0)
#define CP_COMMIT()  asm volatile("cp.async.commit_group;" ::: "memory")
#define CP_WAIT1()   asm volatile("cp.async.wait_group 1;" ::: "memory")

#define LDSM_X4(r, addr) \
    asm volatile("ldmatrix.sync.aligned.m8n8.x4.shared.b16 {%0,%1,%2,%3}, [%4];" \
        : "=r"((r)[0]), "=r"((r)[1]), "=r"((r)[2]), "=r"((r)[3]) : "r"(addr))
#define LDSM_X2(r, addr) \
    asm volatile("ldmatrix.sync.aligned.m8n8.x2.shared.b16 {%0,%1}, [%2];" \
        : "=r"((r)[0]), "=r"((r)[1]) : "r"(addr))

__device__ __forceinline__ uint32_t packbf2(float x, float y) {
    __nv_bfloat162 t = __float22bfloat162_rn(make_float2(x, y));
    return *reinterpret_cast<uint32_t*>(&t);
}

// ----------------------------------------------------------------------------
// bf16x3 GEMM, 2-stage cp.async pipeline + ldmatrix, split-major MMA order
// ----------------------------------------------------------------------------
#define SSTR 40
#define GEMM_STAGE_ELEMS (4 * 128 * SSTR)
#define GEMM_STAGE_BYTES (GEMM_STAGE_ELEMS * 2)
#define GEMM_TILE_BYTES  (128 * SSTR * 2)
#define GEMM_SMEM_BYTES  (2 * GEMM_STAGE_BYTES)           // 81920 B

__global__ __launch_bounds__(256, 2) void gemm_bf16x3_mma_kernel(
    const __nv_bfloat16* __restrict__ Ahi, const __nv_bfloat16* __restrict__ Alo,
    const __nv_bfloat16* __restrict__ Bhi, const __nv_bfloat16* __restrict__ Blo,
    const float* __restrict__ bias, float* __restrict__ C,
    int M, int N, int K)
{
    extern __shared__ __nv_bfloat16 dsm[];
    const uint32_t dsmAddr = (uint32_t)__cvta_generic_to_shared(dsm);

    const int tid  = threadIdx.x;
    const int wid  = tid >> 5;
    const int lane = tid & 31;
    const int warpM = wid >> 2;
    const int warpN = wid & 3;
    const int bm = blockIdx.y * 128;
    const int bn = blockIdx.x * 128;
    const int tq = lane >> 2;
    const int tr = lane & 3;

    const int r0g = tid >> 2;
    const int r1g = r0g + 64;
    const int c0g = (tid & 3) * 8;

    const uint32_t aRowOff = (uint32_t)(((warpM * 64 + (lane & 15)) * SSTR + ((lane >> 4) << 3)) * 2);
    const uint32_t bRowOff = (uint32_t)(((warpN * 32 + (lane & 7))  * SSTR + (((lane >> 3) & 1) << 3)) * 2);

    float acc[4][4][4];
#pragma unroll
    for (int i = 0; i < 4; i++)
#pragma unroll
        for (int j = 0; j < 4; j++)
#pragma unroll
            for (int r = 0; r < 4; r++) acc[i][j][r] = 0.f;

    const int nchunks = K >> 5;

    auto issue = [&](int c, int s) {
        __nv_bfloat16* sAh = dsm + s * GEMM_STAGE_ELEMS;
        __nv_bfloat16* sAl = sAh + 128 * SSTR;
        __nv_bfloat16* sBh = sAl + 128 * SSTR;
        __nv_bfloat16* sBl = sBh + 128 * SSTR;
        const int k0 = c << 5;
        const long a0 = (long)(bm + r0g) * K + k0 + c0g;
        const long a1 = (long)(bm + r1g) * K + k0 + c0g;
        const long b0 = (long)(bn + r0g) * K + k0 + c0g;
        const long b1 = (long)(bn + r1g) * K + k0 + c0g;
        CP16(&sAh[r0g * SSTR + c0g], &Ahi[a0]);
        CP16(&sAh[r1g * SSTR + c0g], &Ahi[a1]);
        CP16(&sAl[r0g * SSTR + c0g], &Alo[a0]);
        CP16(&sAl[r1g * SSTR + c0g], &Alo[a1]);
        CP16(&sBh[r0g * SSTR + c0g], &Bhi[b0]);
        CP16(&sBh[r1g * SSTR + c0g], &Bhi[b1]);
        CP16(&sBl[r0g * SSTR + c0g], &Blo[b0]);
        CP16(&sBl[r1g * SSTR + c0g], &Blo[b1]);
    };

    issue(0, 0);
    CP_COMMIT();

    for (int c = 0; c < nchunks; c++) {
        if (c + 1 < nchunks) issue(c + 1, (c + 1) & 1);
        CP_COMMIT();
        CP_WAIT1();
        __syncthreads();

        const uint32_t stAh = dsmAddr + (c & 1) * GEMM_STAGE_BYTES;
        const uint32_t stAl = stAh + GEMM_TILE_BYTES;
        const uint32_t stBh = stAl + GEMM_TILE_BYTES;
        const uint32_t stBl = stBh + GEMM_TILE_BYTES;

#pragma unroll
        for (int ks = 0; ks < 2; ks++) {
            const uint32_t ksOff = (uint32_t)(ks * 16 * 2);
            uint32_t ah[4][4], al[4][4];
#pragma unroll
            for (int mf = 0; mf < 4; mf++) {
                const uint32_t mOff = (uint32_t)(mf * 16 * SSTR * 2) + aRowOff + ksOff;
                LDSM_X4(ah[mf], stAh + mOff);
                LDSM_X4(al[mf], stAl + mOff);
            }
#pragma unroll
            for (int nf = 0; nf < 4; nf++) {
                const uint32_t nOff = (uint32_t)(nf * 8 * SSTR * 2) + bRowOff + ksOff;
                uint32_t bh[2], bl[2];
                LDSM_X2(bh, stBh + nOff);
                LDSM_X2(bl, stBl + nOff);
                // split-major order: consecutive HMMAs target different accumulators
#pragma unroll
                for (int mf = 0; mf < 4; mf++) MMA16816(acc[mf][nf], ah[mf], bh);
#pragma unroll
                for (int mf = 0; mf < 4; mf++) MMA16816(acc[mf][nf], ah[mf], bl);
#pragma unroll
                for (int mf = 0; mf < 4; mf++) MMA16816(acc[mf][nf], al[mf], bh);
            }
        }
        __syncthreads();
    }

#pragma unroll
    for (int mf = 0; mf < 4; mf++) {
        const int row = bm + warpM * 64 + mf * 16 + tq;
#pragma unroll
        for (int nf = 0; nf < 4; nf++) {
            const int col = bn + warpN * 32 + nf * 8 + tr * 2;
            const float b0 = bias[col], b1 = bias[col + 1];
            float2 v0 = make_float2(acc[mf][nf][0] + b0, acc[mf][nf][1] + b1);
            float2 v1 = make_float2(acc[mf][nf][2] + b0, acc[mf][nf][3] + b1);
            *(float2*)&C[(long)row * N + col]       = v0;
            *(float2*)&C[(long)(row + 8) * N + col] = v1;
        }
    }
}

// ----------------------------------------------------------------------------
// Split fp32 -> bf16 hi + lo (elementwise)
// ----------------------------------------------------------------------------
__global__ __launch_bounds__(256) void split_bf16_kernel(
    const float* __restrict__ src, __nv_bfloat16* __restrict__ hi,
    __nv_bfloat16* __restrict__ lo, int n4)
{
    int i = blockIdx.x * blockDim.x + threadIdx.x;
    if (i >= n4) return;
    float4 v = *(const float4*)&src[(long)i * 4];
    __nv_bfloat16 h0 = __float2bfloat16(v.x), h1 = __float2bfloat16(v.y);
    __nv_bfloat16 h2 = __float2bfloat16(v.z), h3 = __float2bfloat16(v.w);
    uint32_t ph0 = packbf2(v.x, v.y), ph1 = packbf2(v.z, v.w);
    uint32_t pl0 = packbf2(v.x - __bfloat162float(h0), v.y - __bfloat162float(h1));
    uint32_t pl1 = packbf2(v.z - __bfloat162float(h2), v.w - __bfloat162float(h3));
    *(uint2*)&hi[(long)i * 4] = make_uint2(ph0, ph1);
    *(uint2*)&lo[(long)i * 4] = make_uint2(pl0, pl1);
}

// ----------------------------------------------------------------------------
// Split + transpose, batched pair
// ----------------------------------------------------------------------------
__global__ __launch_bounds__(256) void split_transpose2_kernel(
    const float* __restrict__ W0, __nv_bfloat16* __restrict__ T0hi, __nv_bfloat16* __restrict__ T0lo,
    const float* __restrict__ W1, __nv_bfloat16* __restrict__ T1hi, __nv_bfloat16* __restrict__ T1lo,
    int K, int N)
{
    const float* W = blockIdx.z ? W1 : W0;
    __nv_bfloat16* Thi = blockIdx.z ? T1hi : T0hi;
    __nv_bfloat16* Tlo = blockIdx.z ? T1lo : T0lo;

    __shared__ float tile[32][33];
    const int bx = blockIdx.x * 32;
    const int by = blockIdx.y * 32;
    const int tx = threadIdx.x & 31;
    const int ty = threadIdx.x >> 5;
#pragma unroll
    for (int i = 0; i < 4; i++) {
        int kk = by + ty + i * 8;
        tile[ty + i * 8][tx] = W[(long)kk * N + bx + tx];
    }
    __syncthreads();
#pragma unroll
    for (int i = 0; i < 4; i++) {
        int nn = bx + ty + i * 8;
        float v = tile[tx][ty + i * 8];
        __nv_bfloat16 h = __float2bfloat16(v);
        __nv_bfloat16 l = __float2bfloat16(v - __bfloat162float(h));
        Thi[(long)nn * K + by + tx] = h;
        Tlo[(long)nn * K + by + tx] = l;
    }
}

// ----------------------------------------------------------------------------
// V transpose-split
// ----------------------------------------------------------------------------
__global__ __launch_bounds__(256) void vtrans_split_kernel(
    const float* __restrict__ V, __nv_bfloat16* __restrict__ Thi,
    __nv_bfloat16* __restrict__ Tlo)
{
    __shared__ float tile[32][33];
    const int bx = blockIdx.x * 32;
    const int by = blockIdx.y * 32;
    const int tx = threadIdx.x & 31;
    const int ty = threadIdx.x >> 5;
#pragma unroll
    for (int i = 0; i < 4; i++) {
        int rr = by + ty + i * 8;
        tile[ty + i * 8][tx] = V[(long)rr * DIM + bx + tx];
    }
    __syncthreads();
#pragma unroll
    for (int i = 0; i < 4; i++) {
        int colg = bx + ty + i * 8;
        int rowg = by + tx;
        int b = rowg >> 10, c = rowg & 1023;
        int h = colg >> 6,  d = colg & 63;
        float v = tile[tx][ty + i * 8];
        __nv_bfloat16 hh = __float2bfloat16(v);
        __nv_bfloat16 ll = __float2bfloat16(v - __bfloat162float(hh));
        long o = ((long)((b * NHEADS + h) * HDIM + d)) * LKV + c;
        Thi[o] = hh;
        Tlo[o] = ll;
    }
}

// ----------------------------------------------------------------------------
// Fused RMSNorm + RoPE -> bf16 hi/lo outputs
// ----------------------------------------------------------------------------
__global__ __launch_bounds__(256) void normrope_bf16_kernel(
    const float* __restrict__ in, __nv_bfloat16* __restrict__ outhi,
    __nv_bfloat16* __restrict__ outlo,
    const float* __restrict__ g, const float* __restrict__ cosb,
    const float* __restrict__ sinb)
{
    const int row = blockIdx.x;
    const float* h = in + (long)row * DIM;
    const int tid = threadIdx.x;
    const int e = tid << 2;

    float4 t = *(const float4*)&h[e];
    float ss = t.x * t.x + t.y * t.y + t.z * t.z + t.w * t.w;
#pragma unroll
    for (int o = 16; o > 0; o >>= 1)
        ss += __shfl_xor_sync(0xffffffffu, ss, o);
    __shared__ float red[8];
    if ((tid & 31) == 0) red[tid >> 5] = ss;
    __syncthreads();
    float tot = red[0] + red[1] + red[2] + red[3] + red[4] + red[5] + red[6] + red[7];
    float inv = rsqrtf(tot * (1.0f / (float)DIM) + 1e-6f);

    const int d   = e & (HDIM - 1);
    const int po  = (d < 32) ? 32 : -32;
    const float sgn = (d < 32) ? -1.0f : 1.0f;

    float4 tp  = *(const float4*)&h[e + po];
    float4 g4  = *(const float4*)&g[e];
    float4 gp4 = *(const float4*)&g[e + po];
    float4 c4  = *(const float4*)&cosb[(long)row * HDIM + d];
    float4 s4  = *(const float4*)&sinb[(long)row * HDIM + d];

    float4 o4;
    o4.x = t.x * inv * g4.x * c4.x + sgn * tp.x * inv * gp4.x * s4.x;
    o4.y = t.y * inv * g4.y * c4.y + sgn * tp.y * inv * gp4.y * s4.y;
    o4.z = t.z * inv * g4.z * c4.z + sgn * tp.z * inv * gp4.z * s4.z;
    o4.w = t.w * inv * g4.w * c4.w + sgn * tp.w * inv * gp4.w * s4.w;

    __nv_bfloat16 h0 = __float2bfloat16(o4.x), h1 = __float2bfloat16(o4.y);
    __nv_bfloat16 h2 = __float2bfloat16(o4.z), h3 = __float2bfloat16(o4.w);
    uint32_t ph0 = packbf2(o4.x, o4.y), ph1 = packbf2(o4.z, o4.w);
    uint32_t pl0 = packbf2(o4.x - __bfloat162float(h0), o4.y - __bfloat162float(h1));
    uint32_t pl1 = packbf2(o4.z - __bfloat162float(h2), o4.w - __bfloat162float(h3));
    *(uint2*)&outhi[(long)row * DIM + e] = make_uint2(ph0, ph1);
    *(uint2*)&outlo[(long)row * DIM + e] = make_uint2(pl0, pl1);
}

// ----------------------------------------------------------------------------
// Flash attention, bf16x3 mma.sync, 2-stage cp.async pipeline + ldmatrix.
// CTA = 128 threads (4 warps), 64 q-rows per CTA. KV chunks of 64.
// ----------------------------------------------------------------------------
#define SK 72
#define ATT_STAGE_ELEMS (4 * 64 * SK)
#define ATT_STAGE_BYTES (ATT_STAGE_ELEMS * 2)
#define ATT_TILE_BYTES  (64 * SK * 2)
#define ATT_SMEM_BYTES  (2 * ATT_STAGE_BYTES)     // 73728 B

__global__ __launch_bounds__(128, 3) void attn_mma_kernel(
    const __nv_bfloat16* __restrict__ qhi, const __nv_bfloat16* __restrict__ qlo,
    const __nv_bfloat16* __restrict__ khi, const __nv_bfloat16* __restrict__ klo,
    const __nv_bfloat16* __restrict__ vthi, const __nv_bfloat16* __restrict__ vtlo,
    __nv_bfloat16* __restrict__ ohi, __nv_bfloat16* __restrict__ olo)
{
    extern __shared__ __nv_bfloat16 dsm[];
    const uint32_t dsmAddr = (uint32_t)__cvta_generic_to_shared(dsm);

    const int tid  = threadIdx.x;
    const int w    = tid >> 5;
    const int lane = tid & 31;
    const int tq   = lane >> 2;
    const int tr   = lane & 3;
    const int b    = blockIdx.x >> 4;
    const int h    = blockIdx.x & 15;
    const int q0   = blockIdx.y * 64;
    const float SCALE = 0.125f;

    const int lrow = tid >> 1, lhalf = (tid & 1) * 32;

    // ldmatrix per-lane byte offset within a K/V tile (rows n, col halves of 8)
    const uint32_t fragOff = (uint32_t)((((lane & 7) * SK) + (((lane >> 3) & 1) << 3)) * 2);

    auto issue = [&](int c, int s) {
        __nv_bfloat16* sKh = dsm + s * ATT_STAGE_ELEMS;
        __nv_bfloat16* sKl = sKh + 64 * SK;
        __nv_bfloat16* sVh = sKl + 64 * SK;
        __nv_bfloat16* sVl = sVh + 64 * SK;
        const int j0 = c << 6;
        const __nv_bfloat16* kh_g = khi + ((long)(b * LKV + j0 + lrow)) * DIM + h * HDIM + lhalf;
        const __nv_bfloat16* kl_g = klo + ((long)(b * LKV + j0 + lrow)) * DIM + h * HDIM + lhalf;
        const long vo = ((long)((b * NHEADS + h) * HDIM + lrow)) * LKV + j0 + lhalf;
        const __nv_bfloat16* vh_g = vthi + vo;
        const __nv_bfloat16* vl_g = vtlo + vo;
#pragma unroll
        for (int u = 0; u < 4; u++) {
            const int so = lrow * SK + lhalf + u * 8;
            CP16(&sKh[so], &kh_g[u * 8]);
            CP16(&sKl[so], &kl_g[u * 8]);
            CP16(&sVh[so], &vh_g[u * 8]);
            CP16(&sVl[so], &vl_g[u * 8]);
        }
    };

    const long grow0 = (long)(b * LQ + q0 + w * 16 + tq);
    const __nv_bfloat16* qh0 = qhi + grow0 * DIM + h * HDIM;
    const __nv_bfloat16* ql0 = qlo + grow0 * DIM + h * HDIM;
    uint32_t aQh[4][4], aQl[4][4];
#pragma unroll
    for (int ks = 0; ks < 4; ks++) {
        const int c0 = ks * 16 + 2 * tr;
        aQh[ks][0] = *(const uint32_t*)&qh0[c0];
        aQh[ks][1] = *(const uint32_t*)&qh0[8 * DIM + c0];
        aQh[ks][2] = *(const uint32_t*)&qh0[c0 + 8];
        aQh[ks][3] = *(const uint32_t*)&qh0[8 * DIM + c0 + 8];
        aQl[ks][0] = *(const uint32_t*)&ql0[c0];
        aQl[ks][1] = *(const uint32_t*)&ql0[8 * DIM + c0];
        aQl[ks][2] = *(const uint32_t*)&ql0[c0 + 8];
        aQl[ks][3] = *(const uint32_t*)&ql0[8 * DIM + c0 + 8];
    }

    float oacc[8][4];
#pragma unroll
    for (int i = 0; i < 8; i++)
#pragma unroll
        for (int j = 0; j < 4; j++) oacc[i][j] = 0.f;
    float m[2] = {-1e30f, -1e30f}, l[2] = {0.f, 0.f};

    issue(0, 0);
    CP_COMMIT();

    const int NCH = LKV / 64;
    for (int c = 0; c < NCH; c++) {
        if (c + 1 < NCH) issue(c + 1, (c + 1) & 1);
        CP_COMMIT();
        CP_WAIT1();
        __syncthreads();

        const uint32_t stKh = dsmAddr + (c & 1) * ATT_STAGE_BYTES;
        const uint32_t stKl = stKh + ATT_TILE_BYTES;
        const uint32_t stVh = stKl + ATT_TILE_BYTES;
        const uint32_t stVl = stVh + ATT_TILE_BYTES;

        // ---- S = Q K^T (bf16x3, ldmatrix frags, interleaved nf pairs) ----
        float s[8][4];
#pragma unroll
        for (int i = 0; i < 8; i++)
#pragma unroll
            for (int j = 0; j < 4; j++) s[i][j] = 0.f;

#pragma unroll
        for (int ks = 0; ks < 4; ks++) {
            const uint32_t ksOff = (uint32_t)(ks * 32);   // 16 elems * 2B
#pragma unroll
            for (int nf = 0; nf < 8; nf += 2) {
                const uint32_t base0 = stKh + (uint32_t)(nf * 8 * SK * 2) + fragOff + ksOff;
                const uint32_t base1 = base0 + (uint32_t)(8 * SK * 2);
                const uint32_t lbase0 = base0 + (uint32_t)(ATT_TILE_BYTES);
                const uint32_t lbase1 = lbase0 + (uint32_t)(8 * SK * 2);
                uint32_t bh0[2], bh1[2], bl0[2], bl1[2];
                LDSM_X2(bh0, base0);  LDSM_X2(bh1, base1);
                LDSM_X2(bl0, lbase0); LDSM_X2(bl1, lbase1);
                MMA16816(s[nf],     aQh[ks], bh0);
                MMA16816(s[nf + 1], aQh[ks], bh1);
                MMA16816(s[nf],     aQh[ks], bl0);
                MMA16816(s[nf + 1], aQh[ks], bl1);
                MMA16816(s[nf],     aQl[ks], bh0);
                MMA16816(s[nf + 1], aQl[ks], bh1);
            }
        }

        // ---- online softmax (rows tq and tq+8) ----
#pragma unroll
        for (int r = 0; r < 2; r++) {
            float mx = -1e30f;
#pragma unroll
            for (int nf = 0; nf < 8; nf++)
                mx = fmaxf(mx, fmaxf(s[nf][2 * r], s[nf][2 * r + 1]));
            mx = fmaxf(mx, __shfl_xor_sync(0xffffffffu, mx, 1));
            mx = fmaxf(mx, __shfl_xor_sync(0xffffffffu, mx, 2));
            const float mn = fmaxf(m[r], mx);
            const float f  = __expf((m[r] - mn) * SCALE);
            float rs = 0.f;
#pragma unroll
            for (int nf = 0; nf < 8; nf++) {
                s[nf][2 * r]     = __expf((s[nf][2 * r]     - mn) * SCALE);
                s[nf][2 * r + 1] = __expf((s[nf][2 * r + 1] - mn) * SCALE);
                rs += s[nf][2 * r] + s[nf][2 * r + 1];
            }
            rs += __shfl_xor_sync(0xffffffffu, rs, 1);
            rs += __shfl_xor_sync(0xffffffffu, rs, 2);
            m[r] = mn;
            l[r] = l[r] * f + rs;
#pragma unroll
            for (int nf = 0; nf < 8; nf++) {
                oacc[nf][2 * r]     *= f;
                oacc[nf][2 * r + 1] *= f;
            }
        }

        // ---- O += P V (P hi/lo in registers; bf16x3, ldmatrix V frags) ----
#pragma unroll
        for (int ks = 0; ks < 4; ks++) {
            float v0 = s[2 * ks][0],     v1 = s[2 * ks][1];
            float v2 = s[2 * ks][2],     v3 = s[2 * ks][3];
            float v4 = s[2 * ks + 1][0], v5 = s[2 * ks + 1][1];
            float v6 = s[2 * ks + 1][2], v7 = s[2 * ks + 1][3];
            __nv_bfloat16 h0 = __float2bfloat16(v0), h1 = __float2bfloat16(v1);
            __nv_bfloat16 h2 = __float2bfloat16(v2), h3 = __float2bfloat16(v3);
            __nv_bfloat16 h4 = __float2bfloat16(v4), h5 = __float2bfloat16(v5);
            __nv_bfloat16 h6 = __float2bfloat16(v6), h7 = __float2bfloat16(v7);
            uint32_t aPh[4], aPl[4];
            aPh[0] = packbf2(v0, v1); aPh[1] = packbf2(v2, v3);
            aPh[2] = packbf2(v4, v5); aPh[3] = packbf2(v6, v7);
            aPl[0] = packbf2(v0 - __bfloat162float(h0), v1 - __bfloat162float(h1));
            aPl[1] = packbf2(v2 - __bfloat162float(h2), v3 - __bfloat162float(h3));
            aPl[2] = packbf2(v4 - __bfloat162float(h4), v5 - __bfloat162float(h5));
            aPl[3] = packbf2(v6 - __bfloat162float(h6), v7 - __bfloat162float(h7));

            const uint32_t ksOff = (uint32_t)(ks * 32);
#pragma unroll
            for (int nf = 0; nf < 8; nf += 2) {
                const uint32_t base0 = stVh + (uint32_t)(nf * 8 * SK * 2) + fragOff + ksOff;
                const uint32_t base1 = base0 + (uint32_t)(8 * SK * 2);
                const uint32_t lbase0 = base0 + (uint32_t)(ATT_TILE_BYTES);
                const uint32_t lbase1 = lbase0 + (uint32_t)(8 * SK * 2);
                uint32_t bh0[2], bh1[2], bl0[2], bl1[2];
                LDSM_X2(bh0, base0);  LDSM_X2(bh1, base1);
                LDSM_X2(bl0, lbase0); LDSM_X2(bl1, lbase1);
                MMA16816(oacc[nf],     aPh, bh0);
                MMA16816(oacc[nf + 1], aPh, bh1);
                MMA16816(oacc[nf],     aPh, bl0);
                MMA16816(oacc[nf + 1], aPh, bl1);
                MMA16816(oacc[nf],     aPl, bh0);
                MMA16816(oacc[nf + 1], aPl, bh1);
            }
        }
        __syncthreads();
    }

    // ---- epilogue ----
    const float inv0 = 1.f / l[0], inv1 = 1.f / l[1];
    __nv_bfloat16* oh0 = ohi + grow0 * DIM + h * HDIM;
    __nv_bfloat16* ol0 = olo + grow0 * DIM + h * HDIM;
#pragma unroll
    for (int nf = 0; nf < 8; nf++) {
        const int col = nf * 8 + 2 * tr;
        float x0 = oacc[nf][0] * inv0, y0 = oacc[nf][1] * inv0;
        float x1 = oacc[nf][2] * inv1, y1 = oacc[nf][3] * inv1;
        __nv_bfloat16 hx0 = __float2bfloat16(x0), hy0 = __float2bfloat16(y0);
        __nv_bfloat16 hx1 = __float2bfloat16(x1), hy1 = __float2bfloat16(y1);
        *(uint32_t*)&oh0[col]           = packbf2(x0, y0);
        *(uint32_t*)&oh0[8 * DIM + col] = packbf2(x1, y1);
        *(uint32_t*)&ol0[col]           = packbf2(x0 - __bfloat162float(hx0), y0 - __bfloat162float(hy0));
        *(uint32_t*)&ol0[8 * DIM + col] = packbf2(x1 - __bfloat162float(hx1), y1 - __bfloat162float(hy1));
    }
}

// ----------------------------------------------------------------------------
// Launch
// ----------------------------------------------------------------------------
extern "C" void kernel_launch(void* const* d_in, const int* in_sizes, int n_in,
                              void* d_out, int out_size)
{
    const float* x     = (const float*)d_in[0];
    const float* y     = (const float*)d_in[1];
    const float* x_cos = (const float*)d_in[2];
    const float* x_sin = (const float*)d_in[3];
    const float* y_cos = (const float*)d_in[4];
    const float* y_sin = (const float*)d_in[5];
    const float* Wq    = (const float*)d_in[6];
    const float* bq    = (const float*)d_in[7];
    const float* Wk    = (const float*)d_in[8];
    const float* bk    = (const float*)d_in[9];
    const float* Wv    = (const float*)d_in[10];
    const float* bv    = (const float*)d_in[11];
    const float* Wo    = (const float*)d_in[12];
    const float* bo    = (const float*)d_in[13];
    const float* gq    = (const float*)d_in[14];
    const float* gk    = (const float*)d_in[15];
    float* out = (float*)d_out;

    float *qtmp, *ktmp, *vb;
    cudaGetSymbolAddress((void**)&qtmp, g_qtmp);
    cudaGetSymbolAddress((void**)&ktmp, g_ktmp);
    cudaGetSymbolAddress((void**)&vb,   g_v);

    __nv_bfloat16 *qhi, *qlo, *khi, *klo, *vthi, *vtlo;
    __nv_bfloat16 *xhi, *xlo, *yhi, *ylo;
    __nv_bfloat16 *wqh, *wql, *wkh, *wkl, *wvh, *wvl, *woh, *wol;
    cudaGetSymbolAddress((void**)&qhi, g_qhi);
    cudaGetSymbolAddress((void**)&qlo, g_qlo);
    cudaGetSymbolAddress((void**)&khi, g_khi);
    cudaGetSymbolAddress((void**)&klo, g_klo);
    cudaGetSymbolAddress((void**)&vthi, g_vthi);
    cudaGetSymbolAddress((void**)&vtlo, g_vtlo);
    cudaGetSymbolAddress((void**)&xhi, g_xhi);
    cudaGetSymbolAddress((void**)&xlo, g_xlo);
    cudaGetSymbolAddress((void**)&yhi, g_yhi);
    cudaGetSymbolAddress((void**)&ylo, g_ylo);
    cudaGetSymbolAddress((void**)&wqh, g_wqt_hi);
    cudaGetSymbolAddress((void**)&wql, g_wqt_lo);
    cudaGetSymbolAddress((void**)&wkh, g_wkt_hi);
    cudaGetSymbolAddress((void**)&wkl, g_wkt_lo);
    cudaGetSymbolAddress((void**)&wvh, g_wvt_hi);
    cudaGetSymbolAddress((void**)&wvl, g_wvt_lo);
    cudaGetSymbolAddress((void**)&woh, g_wot_hi);
    cudaGetSymbolAddress((void**)&wol, g_wot_lo);

    cudaFuncSetAttribute(gemm_bf16x3_mma_kernel,
                         cudaFuncAttributeMaxDynamicSharedMemorySize, GEMM_SMEM_BYTES);
    cudaFuncSetAttribute(attn_mma_kernel,
                         cudaFuncAttributeMaxDynamicSharedMemorySize, ATT_SMEM_BYTES);

    const int Mq = BATCH * LQ;    // 8192
    const int Mk = BATCH * LKV;   // 2048

    split_bf16_kernel<<<(Mq * DIM / 4 + 255) / 256, 256>>>(x, xhi, xlo, Mq * DIM / 4);
    split_bf16_kernel<<<(Mk * KV_DIM / 4 + 255) / 256, 256>>>(y, yhi, ylo, Mk * KV_DIM / 4);
    split_transpose2_kernel<<<dim3(DIM / 32, DIM / 32, 2), 256>>>(
        Wq, wqh, wql, Wo, woh, wol, DIM, DIM);
    split_transpose2_kernel<<<dim3(DIM / 32, KV_DIM / 32, 2), 256>>>(
        Wk, wkh, wkl, Wv, wvh, wvl, KV_DIM, DIM);

    gemm_bf16x3_mma_kernel<<<dim3(DIM / 128, Mq / 128), 256, GEMM_SMEM_BYTES>>>(
        xhi, xlo, wqh, wql, bq, qtmp, Mq, DIM, DIM);
    gemm_bf16x3_mma_kernel<<<dim3(DIM / 128, Mk / 128), 256, GEMM_SMEM_BYTES>>>(
        yhi, ylo, wkh, wkl, bk, ktmp, Mk, DIM, KV_DIM);
    gemm_bf16x3_mma_kernel<<<dim3(DIM / 128, Mk / 128), 256, GEMM_SMEM_BYTES>>>(
        yhi, ylo, wvh, wvl, bv, vb, Mk, DIM, KV_DIM);

    normrope_bf16_kernel<<<Mq, 256>>>(qtmp, qhi, qlo, gq, x_cos, x_sin);
    normrope_bf16_kernel<<<Mk, 256>>>(ktmp, khi, klo, gk, y_cos, y_sin);
    vtrans_split_kernel<<<dim3(DIM / 32, Mk / 32), 256>>>(vb, vthi, vtlo);

    attn_mma_kernel<<<dim3(BATCH * NHEADS, LQ / 64), 128, ATT_SMEM_BYTES>>>(
        qhi, qlo, khi, klo, vthi, vtlo, xhi, xlo);

    gemm_bf16x3_mma_kernel<<<dim3(DIM / 128, Mq / 128), 256, GEMM_SMEM_BYTES>>>(
        xhi, xlo, woh, wol, bo, out, Mq, DIM, DIM);
}

// round 13
// speedup vs baseline: 1.4605x; 1.0282x over previous
#include <cuda_runtime.h>
#include <cuda_bf16.h>
#include <cstdint>

// ----------------------------------------------------------------------------
// Problem constants
// ----------------------------------------------------------------------------
#define BATCH   2
#define LQ      4096
#define LKV     1024
#define DIM     1024
#define KV_DIM  768
#define NHEADS  16
#define HDIM    64

// ----------------------------------------------------------------------------
// Scratch (device globals; allocation-free per harness rules)
// ----------------------------------------------------------------------------
__device__ float g_qtmp[(BATCH*LQ)*DIM];
__device__ float g_ktmp[(BATCH*LKV)*DIM];
__device__ float g_v   [(BATCH*LKV)*DIM];

__device__ __nv_bfloat16 g_qhi[(BATCH*LQ)*DIM],  g_qlo[(BATCH*LQ)*DIM];
__device__ __nv_bfloat16 g_khi[(BATCH*LKV)*DIM], g_klo[(BATCH*LKV)*DIM];
__device__ __nv_bfloat16 g_vthi[(BATCH*LKV)*DIM], g_vtlo[(BATCH*LKV)*DIM];

__device__ __nv_bfloat16 g_xhi[(BATCH*LQ)*DIM],  g_xlo[(BATCH*LQ)*DIM];
__device__ __nv_bfloat16 g_yhi[(BATCH*LKV)*KV_DIM], g_ylo[(BATCH*LKV)*KV_DIM];
__device__ __nv_bfloat16 g_wqt_hi[DIM*DIM],    g_wqt_lo[DIM*DIM];
__device__ __nv_bfloat16 g_wkt_hi[DIM*KV_DIM], g_wkt_lo[DIM*KV_DIM];
__device__ __nv_bfloat16 g_wvt_hi[DIM*KV_DIM], g_wvt_lo[DIM*KV_DIM];
__device__ __nv_bfloat16 g_wot_hi[DIM*DIM],    g_wot_lo[DIM*DIM];

// ----------------------------------------------------------------------------
// mma.sync / cp.async / ldmatrix helpers (baseline PTX)
// ----------------------------------------------------------------------------
#define MMA16816(d, a, b) \
    asm volatile("mma.sync.aligned.m16n8k16.row.col.f32.bf16.bf16.f32 " \
        "{%0,%1,%2,%3}, {%4,%5,%6,%7}, {%8,%9}, {%0,%1,%2,%3};" \
        : "+f"((d)[0]), "+f"((d)[1]), "+f"((d)[2]), "+f"((d)[3]) \
        : "r"((a)[0]), "r"((a)[1]), "r"((a)[2]), "r"((a)[3]), \
          "r"((b)[0]), "r"((b)[1]))

#define CP16(sp, gp) do { \
    uint32_t _s = (uint32_t)__cvta_generic_to_shared(sp); \
    asm volatile("cp.async.cg.shared.global [%0], [%1], 16;" :: "r"(_s), "l"(gp)); \
} while (0)
#define CP_COMMIT()  asm volatile("cp.async.commit_group;" ::: "memory")
#define CP_WAIT1()   asm volatile("cp.async.wait_group 1;" ::: "memory")

#define LDSM_X4(r, addr) \
    asm volatile("ldmatrix.sync.aligned.m8n8.x4.shared.b16 {%0,%1,%2,%3}, [%4];" \
        : "=r"((r)[0]), "=r"((r)[1]), "=r"((r)[2]), "=r"((r)[3]) : "r"(addr))
#define LDSM_X2(r, addr) \
    asm volatile("ldmatrix.sync.aligned.m8n8.x2.shared.b16 {%0,%1}, [%2];" \
        : "=r"((r)[0]), "=r"((r)[1]) : "r"(addr))

__device__ __forceinline__ uint32_t packbf2(float x, float y) {
    __nv_bfloat162 t = __float22bfloat162_rn(make_float2(x, y));
    return *reinterpret_cast<uint32_t*>(&t);
}

// ----------------------------------------------------------------------------
// Fused QKV bf16x3 GEMM, 2-stage cp.async + ldmatrix.
// One launch packs Q (64 M-tiles, K=1024), K (16 M-tiles, K=768), V (16, K=768)
// into a single wave-packed grid: blockIdx.y in [0,96) selects gemm + tile.
// ----------------------------------------------------------------------------
#define SSTR 40
#define GEMM_STAGE_ELEMS (4 * 128 * SSTR)
#define GEMM_STAGE_BYTES (GEMM_STAGE_ELEMS * 2)
#define GEMM_TILE_BYTES  (128 * SSTR * 2)
#define GEMM_SMEM_BYTES  (2 * GEMM_STAGE_BYTES)           // 81920 B

struct GemmArgs {
    const __nv_bfloat16 *Ahi, *Alo;   // activations [M,K]
    const __nv_bfloat16 *Bhi, *Blo;   // weights^T  [N,K]
    const float *bias;
    float *C;
    int K;                            // N = DIM always
};

__device__ __forceinline__ void gemm_body(
    const __nv_bfloat16* __restrict__ Ahi, const __nv_bfloat16* __restrict__ Alo,
    const __nv_bfloat16* __restrict__ Bhi, const __nv_bfloat16* __restrict__ Blo,
    const float* __restrict__ bias, float* __restrict__ C,
    int N, int K, int bm, int bn, __nv_bfloat16* dsm)
{
    const uint32_t dsmAddr = (uint32_t)__cvta_generic_to_shared(dsm);

    const int tid  = threadIdx.x;
    const int wid  = tid >> 5;
    const int lane = tid & 31;
    const int warpM = wid >> 2;
    const int warpN = wid & 3;
    const int tq = lane >> 2;
    const int tr = lane & 3;

    const int r0g = tid >> 2;
    const int r1g = r0g + 64;
    const int c0g = (tid & 3) * 8;

    const uint32_t aRowOff = (uint32_t)(((warpM * 64 + (lane & 15)) * SSTR + ((lane >> 4) << 3)) * 2);
    const uint32_t bRowOff = (uint32_t)(((warpN * 32 + (lane & 7))  * SSTR + (((lane >> 3) & 1) << 3)) * 2);

    float acc[4][4][4];
#pragma unroll
    for (int i = 0; i < 4; i++)
#pragma unroll
        for (int j = 0; j < 4; j++)
#pragma unroll
            for (int r = 0; r < 4; r++) acc[i][j][r] = 0.f;

    const int nchunks = K >> 5;

    auto issue = [&](int c, int s) {
        __nv_bfloat16* sAh = dsm + s * GEMM_STAGE_ELEMS;
        __nv_bfloat16* sAl = sAh + 128 * SSTR;
        __nv_bfloat16* sBh = sAl + 128 * SSTR;
        __nv_bfloat16* sBl = sBh + 128 * SSTR;
        const int k0 = c << 5;
        const long a0 = (long)(bm + r0g) * K + k0 + c0g;
        const long a1 = (long)(bm + r1g) * K + k0 + c0g;
        const long b0 = (long)(bn + r0g) * K + k0 + c0g;
        const long b1 = (long)(bn + r1g) * K + k0 + c0g;
        CP16(&sAh[r0g * SSTR + c0g], &Ahi[a0]);
        CP16(&sAh[r1g * SSTR + c0g], &Ahi[a1]);
        CP16(&sAl[r0g * SSTR + c0g], &Alo[a0]);
        CP16(&sAl[r1g * SSTR + c0g], &Alo[a1]);
        CP16(&sBh[r0g * SSTR + c0g], &Bhi[b0]);
        CP16(&sBh[r1g * SSTR + c0g], &Bhi[b1]);
        CP16(&sBl[r0g * SSTR + c0g], &Blo[b0]);
        CP16(&sBl[r1g * SSTR + c0g], &Blo[b1]);
    };

    issue(0, 0);
    CP_COMMIT();

    for (int c = 0; c < nchunks; c++) {
        if (c + 1 < nchunks) issue(c + 1, (c + 1) & 1);
        CP_COMMIT();
        CP_WAIT1();
        __syncthreads();

        const uint32_t stAh = dsmAddr + (c & 1) * GEMM_STAGE_BYTES;
        const uint32_t stAl = stAh + GEMM_TILE_BYTES;
        const uint32_t stBh = stAl + GEMM_TILE_BYTES;
        const uint32_t stBl = stBh + GEMM_TILE_BYTES;

#pragma unroll
        for (int ks = 0; ks < 2; ks++) {
            const uint32_t ksOff = (uint32_t)(ks * 16 * 2);
            uint32_t ah[4][4], al[4][4];
#pragma unroll
            for (int mf = 0; mf < 4; mf++) {
                const uint32_t mOff = (uint32_t)(mf * 16 * SSTR * 2) + aRowOff + ksOff;
                LDSM_X4(ah[mf], stAh + mOff);
                LDSM_X4(al[mf], stAl + mOff);
            }
#pragma unroll
            for (int nf = 0; nf < 4; nf++) {
                const uint32_t nOff = (uint32_t)(nf * 8 * SSTR * 2) + bRowOff + ksOff;
                uint32_t bh[2], bl[2];
                LDSM_X2(bh, stBh + nOff);
                LDSM_X2(bl, stBl + nOff);
#pragma unroll
                for (int mf = 0; mf < 4; mf++) MMA16816(acc[mf][nf], ah[mf], bh);
#pragma unroll
                for (int mf = 0; mf < 4; mf++) MMA16816(acc[mf][nf], ah[mf], bl);
#pragma unroll
                for (int mf = 0; mf < 4; mf++) MMA16816(acc[mf][nf], al[mf], bh);
            }
        }
        __syncthreads();
    }

#pragma unroll
    for (int mf = 0; mf < 4; mf++) {
        const int row = bm + warpM * 64 + mf * 16 + tq;
#pragma unroll
        for (int nf = 0; nf < 4; nf++) {
            const int col = bn + warpN * 32 + nf * 8 + tr * 2;
            const float b0 = bias[col], b1 = bias[col + 1];
            float2 v0 = make_float2(acc[mf][nf][0] + b0, acc[mf][nf][1] + b1);
            float2 v1 = make_float2(acc[mf][nf][2] + b0, acc[mf][nf][3] + b1);
            *(float2*)&C[(long)row * N + col]       = v0;
            *(float2*)&C[(long)(row + 8) * N + col] = v1;
        }
    }
}

// Fused Q/K/V projection launch. grid = (8, 96).
//   by in [0,64)  : Q-proj tile by       (A = x splits, K=1024, C=qtmp)
//   by in [64,80) : K-proj tile by-64    (A = y splits, K=768,  C=ktmp)
//   by in [80,96) : V-proj tile by-80    (A = y splits, K=768,  C=vtmp)
__global__ __launch_bounds__(256, 2) void gemm_qkv_kernel(
    const __nv_bfloat16* __restrict__ xhi, const __nv_bfloat16* __restrict__ xlo,
    const __nv_bfloat16* __restrict__ yhi, const __nv_bfloat16* __restrict__ ylo,
    const __nv_bfloat16* __restrict__ wqh, const __nv_bfloat16* __restrict__ wql,
    const __nv_bfloat16* __restrict__ wkh, const __nv_bfloat16* __restrict__ wkl,
    const __nv_bfloat16* __restrict__ wvh, const __nv_bfloat16* __restrict__ wvl,
    const float* __restrict__ bq, const float* __restrict__ bk, const float* __restrict__ bv,
    float* __restrict__ qtmp, float* __restrict__ ktmp, float* __restrict__ vtmp)
{
    extern __shared__ __nv_bfloat16 dsm[];
    const int by = blockIdx.y;
    const int bn = blockIdx.x * 128;

    if (by < 64) {
        gemm_body(xhi, xlo, wqh, wql, bq, qtmp, DIM, DIM,    by * 128,        bn, dsm);
    } else if (by < 80) {
        gemm_body(yhi, ylo, wkh, wkl, bk, ktmp, DIM, KV_DIM, (by - 64) * 128, bn, dsm);
    } else {
        gemm_body(yhi, ylo, wvh, wvl, bv, vtmp, DIM, KV_DIM, (by - 80) * 128, bn, dsm);
    }
}

// Standalone GEMM (O-projection)
__global__ __launch_bounds__(256, 2) void gemm_bf16x3_mma_kernel(
    const __nv_bfloat16* __restrict__ Ahi, const __nv_bfloat16* __restrict__ Alo,
    const __nv_bfloat16* __restrict__ Bhi, const __nv_bfloat16* __restrict__ Blo,
    const float* __restrict__ bias, float* __restrict__ C,
    int M, int N, int K)
{
    extern __shared__ __nv_bfloat16 dsm[];
    gemm_body(Ahi, Alo, Bhi, Blo, bias, C, N, K, blockIdx.y * 128, blockIdx.x * 128, dsm);
}

// ----------------------------------------------------------------------------
// Split fp32 -> bf16 hi + lo (elementwise)
// ----------------------------------------------------------------------------
__global__ __launch_bounds__(256) void split_bf16_kernel(
    const float* __restrict__ src, __nv_bfloat16* __restrict__ hi,
    __nv_bfloat16* __restrict__ lo, int n4)
{
    int i = blockIdx.x * blockDim.x + threadIdx.x;
    if (i >= n4) return;
    float4 v = *(const float4*)&src[(long)i * 4];
    __nv_bfloat16 h0 = __float2bfloat16(v.x), h1 = __float2bfloat16(v.y);
    __nv_bfloat16 h2 = __float2bfloat16(v.z), h3 = __float2bfloat16(v.w);
    uint32_t ph0 = packbf2(v.x, v.y), ph1 = packbf2(v.z, v.w);
    uint32_t pl0 = packbf2(v.x - __bfloat162float(h0), v.y - __bfloat162float(h1));
    uint32_t pl1 = packbf2(v.z - __bfloat162float(h2), v.w - __bfloat162float(h3));
    *(uint2*)&hi[(long)i * 4] = make_uint2(ph0, ph1);
    *(uint2*)&lo[(long)i * 4] = make_uint2(pl0, pl1);
}

// ----------------------------------------------------------------------------
// Split + transpose, batched pair
// ----------------------------------------------------------------------------
__global__ __launch_bounds__(256) void split_transpose2_kernel(
    const float* __restrict__ W0, __nv_bfloat16* __restrict__ T0hi, __nv_bfloat16* __restrict__ T0lo,
    const float* __restrict__ W1, __nv_bfloat16* __restrict__ T1hi, __nv_bfloat16* __restrict__ T1lo,
    int K, int N)
{
    const float* W = blockIdx.z ? W1 : W0;
    __nv_bfloat16* Thi = blockIdx.z ? T1hi : T0hi;
    __nv_bfloat16* Tlo = blockIdx.z ? T1lo : T0lo;

    __shared__ float tile[32][33];
    const int bx = blockIdx.x * 32;
    const int by = blockIdx.y * 32;
    const int tx = threadIdx.x & 31;
    const int ty = threadIdx.x >> 5;
#pragma unroll
    for (int i = 0; i < 4; i++) {
        int kk = by + ty + i * 8;
        tile[ty + i * 8][tx] = W[(long)kk * N + bx + tx];
    }
    __syncthreads();
#pragma unroll
    for (int i = 0; i < 4; i++) {
        int nn = bx + ty + i * 8;
        float v = tile[tx][ty + i * 8];
        __nv_bfloat16 h = __float2bfloat16(v);
        __nv_bfloat16 l = __float2bfloat16(v - __bfloat162float(h));
        Thi[(long)nn * K + by + tx] = h;
        Tlo[(long)nn * K + by + tx] = l;
    }
}

// ----------------------------------------------------------------------------
// V transpose-split
// ----------------------------------------------------------------------------
__global__ __launch_bounds__(256) void vtrans_split_kernel(
    const float* __restrict__ V, __nv_bfloat16* __restrict__ Thi,
    __nv_bfloat16* __restrict__ Tlo)
{
    __shared__ float tile[32][33];
    const int bx = blockIdx.x * 32;
    const int by = blockIdx.y * 32;
    const int tx = threadIdx.x & 31;
    const int ty = threadIdx.x >> 5;
#pragma unroll
    for (int i = 0; i < 4; i++) {
        int rr = by + ty + i * 8;
        tile[ty + i * 8][tx] = V[(long)rr * DIM + bx + tx];
    }
    __syncthreads();
#pragma unroll
    for (int i = 0; i < 4; i++) {
        int colg = bx + ty + i * 8;
        int rowg = by + tx;
        int b = rowg >> 10, c = rowg & 1023;
        int h = colg >> 6,  d = colg & 63;
        float v = tile[tx][ty + i * 8];
        __nv_bfloat16 hh = __float2bfloat16(v);
        __nv_bfloat16 ll = __float2bfloat16(v - __bfloat162float(hh));
        long o = ((long)((b * NHEADS + h) * HDIM + d)) * LKV + c;
        Thi[o] = hh;
        Tlo[o] = ll;
    }
}

// ----------------------------------------------------------------------------
// Fused RMSNorm + RoPE -> bf16 hi/lo outputs
// ----------------------------------------------------------------------------
__global__ __launch_bounds__(256) void normrope_bf16_kernel(
    const float* __restrict__ in, __nv_bfloat16* __restrict__ outhi,
    __nv_bfloat16* __restrict__ outlo,
    const float* __restrict__ g, const float* __restrict__ cosb,
    const float* __restrict__ sinb)
{
    const int row = blockIdx.x;
    const float* h = in + (long)row * DIM;
    const int tid = threadIdx.x;
    const int e = tid << 2;

    float4 t = *(const float4*)&h[e];
    float ss = t.x * t.x + t.y * t.y + t.z * t.z + t.w * t.w;
#pragma unroll
    for (int o = 16; o > 0; o >>= 1)
        ss += __shfl_xor_sync(0xffffffffu, ss, o);
    __shared__ float red[8];
    if ((tid & 31) == 0) red[tid >> 5] = ss;
    __syncthreads();
    float tot = red[0] + red[1] + red[2] + red[3] + red[4] + red[5] + red[6] + red[7];
    float inv = rsqrtf(tot * (1.0f / (float)DIM) + 1e-6f);

    const int d   = e & (HDIM - 1);
    const int po  = (d < 32) ? 32 : -32;
    const float sgn = (d < 32) ? -1.0f : 1.0f;

    float4 tp  = *(const float4*)&h[e + po];
    float4 g4  = *(const float4*)&g[e];
    float4 gp4 = *(const float4*)&g[e + po];
    float4 c4  = *(const float4*)&cosb[(long)row * HDIM + d];
    float4 s4  = *(const float4*)&sinb[(long)row * HDIM + d];

    float4 o4;
    o4.x = t.x * inv * g4.x * c4.x + sgn * tp.x * inv * gp4.x * s4.x;
    o4.y = t.y * inv * g4.y * c4.y + sgn * tp.y * inv * gp4.y * s4.y;
    o4.z = t.z * inv * g4.z * c4.z + sgn * tp.z * inv * gp4.z * s4.z;
    o4.w = t.w * inv * g4.w * c4.w + sgn * tp.w * inv * gp4.w * s4.w;

    __nv_bfloat16 h0 = __float2bfloat16(o4.x), h1 = __float2bfloat16(o4.y);
    __nv_bfloat16 h2 = __float2bfloat16(o4.z), h3 = __float2bfloat16(o4.w);
    uint32_t ph0 = packbf2(o4.x, o4.y), ph1 = packbf2(o4.z, o4.w);
    uint32_t pl0 = packbf2(o4.x - __bfloat162float(h0), o4.y - __bfloat162float(h1));
    uint32_t pl1 = packbf2(o4.z - __bfloat162float(h2), o4.w - __bfloat162float(h3));
    *(uint2*)&outhi[(long)row * DIM + e] = make_uint2(ph0, ph1);
    *(uint2*)&outlo[(long)row * DIM + e] = make_uint2(pl0, pl1);
}

// ----------------------------------------------------------------------------
// Flash attention, bf16x3 mma.sync, 2-stage cp.async pipeline + ldmatrix.
// CTA = 128 threads (4 warps), 64 q-rows per CTA. KV chunks of 64.
// ----------------------------------------------------------------------------
#define SK 72
#define ATT_STAGE_ELEMS (4 * 64 * SK)
#define ATT_STAGE_BYTES (ATT_STAGE_ELEMS * 2)
#define ATT_TILE_BYTES  (64 * SK * 2)
#define ATT_SMEM_BYTES  (2 * ATT_STAGE_BYTES)     // 73728 B

__global__ __launch_bounds__(128, 3) void attn_mma_kernel(
    const __nv_bfloat16* __restrict__ qhi, const __nv_bfloat16* __restrict__ qlo,
    const __nv_bfloat16* __restrict__ khi, const __nv_bfloat16* __restrict__ klo,
    const __nv_bfloat16* __restrict__ vthi, const __nv_bfloat16* __restrict__ vtlo,
    __nv_bfloat16* __restrict__ ohi, __nv_bfloat16* __restrict__ olo)
{
    extern __shared__ __nv_bfloat16 dsm[];
    const uint32_t dsmAddr = (uint32_t)__cvta_generic_to_shared(dsm);

    const int tid  = threadIdx.x;
    const int w    = tid >> 5;
    const int lane = tid & 31;
    const int tq   = lane >> 2;
    const int tr   = lane & 3;
    const int b    = blockIdx.x >> 4;
    const int h    = blockIdx.x & 15;
    const int q0   = blockIdx.y * 64;
    const float SCALE = 0.125f;

    const int lrow = tid >> 1, lhalf = (tid & 1) * 32;
    const uint32_t fragOff = (uint32_t)((((lane & 7) * SK) + (((lane >> 3) & 1) << 3)) * 2);

    auto issue = [&](int c, int s) {
        __nv_bfloat16* sKh = dsm + s * ATT_STAGE_ELEMS;
        __nv_bfloat16* sKl = sKh + 64 * SK;
        __nv_bfloat16* sVh = sKl + 64 * SK;
        __nv_bfloat16* sVl = sVh + 64 * SK;
        const int j0 = c << 6;
        const __nv_bfloat16* kh_g = khi + ((long)(b * LKV + j0 + lrow)) * DIM + h * HDIM + lhalf;
        const __nv_bfloat16* kl_g = klo + ((long)(b * LKV + j0 + lrow)) * DIM + h * HDIM + lhalf;
        const long vo = ((long)((b * NHEADS + h) * HDIM + lrow)) * LKV + j0 + lhalf;
        const __nv_bfloat16* vh_g = vthi + vo;
        const __nv_bfloat16* vl_g = vtlo + vo;
#pragma unroll
        for (int u = 0; u < 4; u++) {
            const int so = lrow * SK + lhalf + u * 8;
            CP16(&sKh[so], &kh_g[u * 8]);
            CP16(&sKl[so], &kl_g[u * 8]);
            CP16(&sVh[so], &vh_g[u * 8]);
            CP16(&sVl[so], &vl_g[u * 8]);
        }
    };

    const long grow0 = (long)(b * LQ + q0 + w * 16 + tq);
    const __nv_bfloat16* qh0 = qhi + grow0 * DIM + h * HDIM;
    const __nv_bfloat16* ql0 = qlo + grow0 * DIM + h * HDIM;
    uint32_t aQh[4][4], aQl[4][4];
#pragma unroll
    for (int ks = 0; ks < 4; ks++) {
        const int c0 = ks * 16 + 2 * tr;
        aQh[ks][0] = *(const uint32_t*)&qh0[c0];
        aQh[ks][1] = *(const uint32_t*)&qh0[8 * DIM + c0];
        aQh[ks][2] = *(const uint32_t*)&qh0[c0 + 8];
        aQh[ks][3] = *(const uint32_t*)&qh0[8 * DIM + c0 + 8];
        aQl[ks][0] = *(const uint32_t*)&ql0[c0];
        aQl[ks][1] = *(const uint32_t*)&ql0[8 * DIM + c0];
        aQl[ks][2] = *(const uint32_t*)&ql0[c0 + 8];
        aQl[ks][3] = *(const uint32_t*)&ql0[8 * DIM + c0 + 8];
    }

    float oacc[8][4];
#pragma unroll
    for (int i = 0; i < 8; i++)
#pragma unroll
        for (int j = 0; j < 4; j++) oacc[i][j] = 0.f;
    float m[2] = {-1e30f, -1e30f}, l[2] = {0.f, 0.f};

    issue(0, 0);
    CP_COMMIT();

    const int NCH = LKV / 64;
    for (int c = 0; c < NCH; c++) {
        if (c + 1 < NCH) issue(c + 1, (c + 1) & 1);
        CP_COMMIT();
        CP_WAIT1();
        __syncthreads();

        const uint32_t stKh = dsmAddr + (c & 1) * ATT_STAGE_BYTES;
        const uint32_t stVh = stKh + 2 * ATT_TILE_BYTES;

        float s[8][4];
#pragma unroll
        for (int i = 0; i < 8; i++)
#pragma unroll
            for (int j = 0; j < 4; j++) s[i][j] = 0.f;

#pragma unroll
        for (int ks = 0; ks < 4; ks++) {
            const uint32_t ksOff = (uint32_t)(ks * 32);
#pragma unroll
            for (int nf = 0; nf < 8; nf += 2) {
                const uint32_t base0 = stKh + (uint32_t)(nf * 8 * SK * 2) + fragOff + ksOff;
                const uint32_t base1 = base0 + (uint32_t)(8 * SK * 2);
                const uint32_t lbase0 = base0 + (uint32_t)(ATT_TILE_BYTES);
                const uint32_t lbase1 = lbase0 + (uint32_t)(8 * SK * 2);
                uint32_t bh0[2], bh1[2], bl0[2], bl1[2];
                LDSM_X2(bh0, base0);  LDSM_X2(bh1, base1);
                LDSM_X2(bl0, lbase0); LDSM_X2(bl1, lbase1);
                MMA16816(s[nf],     aQh[ks], bh0);
                MMA16816(s[nf + 1], aQh[ks], bh1);
                MMA16816(s[nf],     aQh[ks], bl0);
                MMA16816(s[nf + 1], aQh[ks], bl1);
                MMA16816(s[nf],     aQl[ks], bh0);
                MMA16816(s[nf + 1], aQl[ks], bh1);
            }
        }

#pragma unroll
        for (int r = 0; r < 2; r++) {
            float mx = -1e30f;
#pragma unroll
            for (int nf = 0; nf < 8; nf++)
                mx = fmaxf(mx, fmaxf(s[nf][2 * r], s[nf][2 * r + 1]));
            mx = fmaxf(mx, __shfl_xor_sync(0xffffffffu, mx, 1));
            mx = fmaxf(mx, __shfl_xor_sync(0xffffffffu, mx, 2));
            const float mn = fmaxf(m[r], mx);
            const float f  = __expf((m[r] - mn) * SCALE);
            float rs = 0.f;
#pragma unroll
            for (int nf = 0; nf < 8; nf++) {
                s[nf][2 * r]     = __expf((s[nf][2 * r]     - mn) * SCALE);
                s[nf][2 * r + 1] = __expf((s[nf][2 * r + 1] - mn) * SCALE);
                rs += s[nf][2 * r] + s[nf][2 * r + 1];
            }
            rs += __shfl_xor_sync(0xffffffffu, rs, 1);
            rs += __shfl_xor_sync(0xffffffffu, rs, 2);
            m[r] = mn;
            l[r] = l[r] * f + rs;
#pragma unroll
            for (int nf = 0; nf < 8; nf++) {
                oacc[nf][2 * r]     *= f;
                oacc[nf][2 * r + 1] *= f;
            }
        }

#pragma unroll
        for (int ks = 0; ks < 4; ks++) {
            float v0 = s[2 * ks][0],     v1 = s[2 * ks][1];
            float v2 = s[2 * ks][2],     v3 = s[2 * ks][3];
            float v4 = s[2 * ks + 1][0], v5 = s[2 * ks + 1][1];
            float v6 = s[2 * ks + 1][2], v7 = s[2 * ks + 1][3];
            __nv_bfloat16 h0 = __float2bfloat16(v0), h1 = __float2bfloat16(v1);
            __nv_bfloat16 h2 = __float2bfloat16(v2), h3 = __float2bfloat16(v3);
            __nv_bfloat16 h4 = __float2bfloat16(v4), h5 = __float2bfloat16(v5);
            __nv_bfloat16 h6 = __float2bfloat16(v6), h7 = __float2bfloat16(v7);
            uint32_t aPh[4], aPl[4];
            aPh[0] = packbf2(v0, v1); aPh[1] = packbf2(v2, v3);
            aPh[2] = packbf2(v4, v5); aPh[3] = packbf2(v6, v7);
            aPl[0] = packbf2(v0 - __bfloat162float(h0), v1 - __bfloat162float(h1));
            aPl[1] = packbf2(v2 - __bfloat162float(h2), v3 - __bfloat162float(h3));
            aPl[2] = packbf2(v4 - __bfloat162float(h4), v5 - __bfloat162float(h5));
            aPl[3] = packbf2(v6 - __bfloat162float(h6), v7 - __bfloat162float(h7));

            const uint32_t ksOff = (uint32_t)(ks * 32);
#pragma unroll
            for (int nf = 0; nf < 8; nf += 2) {
                const uint32_t base0 = stVh + (uint32_t)(nf * 8 * SK * 2) + fragOff + ksOff;
                const uint32_t base1 = base0 + (uint32_t)(8 * SK * 2);
                const uint32_t lbase0 = base0 + (uint32_t)(ATT_TILE_BYTES);
                const uint32_t lbase1 = lbase0 + (uint32_t)(8 * SK * 2);
                uint32_t bh0[2], bh1[2], bl0[2], bl1[2];
                LDSM_X2(bh0, base0);  LDSM_X2(bh1, base1);
                LDSM_X2(bl0, lbase0); LDSM_X2(bl1, lbase1);
                MMA16816(oacc[nf],     aPh, bh0);
                MMA16816(oacc[nf + 1], aPh, bh1);
                MMA16816(oacc[nf],     aPh, bl0);
                MMA16816(oacc[nf + 1], aPh, bl1);
                MMA16816(oacc[nf],     aPl, bh0);
                MMA16816(oacc[nf + 1], aPl, bh1);
            }
        }
        __syncthreads();
    }

    const float inv0 = 1.f / l[0], inv1 = 1.f / l[1];
    __nv_bfloat16* oh0 = ohi + grow0 * DIM + h * HDIM;
    __nv_bfloat16* ol0 = olo + grow0 * DIM + h * HDIM;
#pragma unroll
    for (int nf = 0; nf < 8; nf++) {
        const int col = nf * 8 + 2 * tr;
        float x0 = oacc[nf][0] * inv0, y0 = oacc[nf][1] * inv0;
        float x1 = oacc[nf][2] * inv1, y1 = oacc[nf][3] * inv1;
        __nv_bfloat16 hx0 = __float2bfloat16(x0), hy0 = __float2bfloat16(y0);
        __nv_bfloat16 hx1 = __float2bfloat16(x1), hy1 = __float2bfloat16(y1);
        *(uint32_t*)&oh0[col]           = packbf2(x0, y0);
        *(uint32_t*)&oh0[8 * DIM + col] = packbf2(x1, y1);
        *(uint32_t*)&ol0[col]           = packbf2(x0 - __bfloat162float(hx0), y0 - __bfloat162float(hy0));
        *(uint32_t*)&ol0[8 * DIM + col] = packbf2(x1 - __bfloat162float(hx1), y1 - __bfloat162float(hy1));
    }
}

// ----------------------------------------------------------------------------
// Launch
// ----------------------------------------------------------------------------
extern "C" void kernel_launch(void* const* d_in, const int* in_sizes, int n_in,
                              void* d_out, int out_size)
{
    const float* x     = (const float*)d_in[0];
    const float* y     = (const float*)d_in[1];
    const float* x_cos = (const float*)d_in[2];
    const float* x_sin = (const float*)d_in[3];
    const float* y_cos = (const float*)d_in[4];
    const float* y_sin = (const float*)d_in[5];
    const float* Wq    = (const float*)d_in[6];
    const float* bq    = (const float*)d_in[7];
    const float* Wk    = (const float*)d_in[8];
    const float* bk    = (const float*)d_in[9];
    const float* Wv    = (const float*)d_in[10];
    const float* bv    = (const float*)d_in[11];
    const float* Wo    = (const float*)d_in[12];
    const float* bo    = (const float*)d_in[13];
    const float* gq    = (const float*)d_in[14];
    const float* gk    = (const float*)d_in[15];
    float* out = (float*)d_out;

    float *qtmp, *ktmp, *vb;
    cudaGetSymbolAddress((void**)&qtmp, g_qtmp);
    cudaGetSymbolAddress((void**)&ktmp, g_ktmp);
    cudaGetSymbolAddress((void**)&vb,   g_v);

    __nv_bfloat16 *qhi, *qlo, *khi, *klo, *vthi, *vtlo;
    __nv_bfloat16 *xhi, *xlo, *yhi, *ylo;
    __nv_bfloat16 *wqh, *wql, *wkh, *wkl, *wvh, *wvl, *woh, *wol;
    cudaGetSymbolAddress((void**)&qhi, g_qhi);
    cudaGetSymbolAddress((void**)&qlo, g_qlo);
    cudaGetSymbolAddress((void**)&khi, g_khi);
    cudaGetSymbolAddress((void**)&klo, g_klo);
    cudaGetSymbolAddress((void**)&vthi, g_vthi);
    cudaGetSymbolAddress((void**)&vtlo, g_vtlo);
    cudaGetSymbolAddress((void**)&xhi, g_xhi);
    cudaGetSymbolAddress((void**)&xlo, g_xlo);
    cudaGetSymbolAddress((void**)&yhi, g_yhi);
    cudaGetSymbolAddress((void**)&ylo, g_ylo);
    cudaGetSymbolAddress((void**)&wqh, g_wqt_hi);
    cudaGetSymbolAddress((void**)&wql, g_wqt_lo);
    cudaGetSymbolAddress((void**)&wkh, g_wkt_hi);
    cudaGetSymbolAddress((void**)&wkl, g_wkt_lo);
    cudaGetSymbolAddress((void**)&wvh, g_wvt_hi);
    cudaGetSymbolAddress((void**)&wvl, g_wvt_lo);
    cudaGetSymbolAddress((void**)&woh, g_wot_hi);
    cudaGetSymbolAddress((void**)&wol, g_wot_lo);

    cudaFuncSetAttribute(gemm_qkv_kernel,
                         cudaFuncAttributeMaxDynamicSharedMemorySize, GEMM_SMEM_BYTES);
    cudaFuncSetAttribute(gemm_bf16x3_mma_kernel,
                         cudaFuncAttributeMaxDynamicSharedMemorySize, GEMM_SMEM_BYTES);
    cudaFuncSetAttribute(attn_mma_kernel,
                         cudaFuncAttributeMaxDynamicSharedMemorySize, ATT_SMEM_BYTES);

    const int Mq = BATCH * LQ;    // 8192
    const int Mk = BATCH * LKV;   // 2048

    split_bf16_kernel<<<(Mq * DIM / 4 + 255) / 256, 256>>>(x, xhi, xlo, Mq * DIM / 4);
    split_bf16_kernel<<<(Mk * KV_DIM / 4 + 255) / 256, 256>>>(y, yhi, ylo, Mk * KV_DIM / 4);
    split_transpose2_kernel<<<dim3(DIM / 32, DIM / 32, 2), 256>>>(
        Wq, wqh, wql, Wo, woh, wol, DIM, DIM);
    split_transpose2_kernel<<<dim3(DIM / 32, KV_DIM / 32, 2), 256>>>(
        Wk, wkh, wkl, Wv, wvh, wvl, KV_DIM, DIM);

    // Fused Q/K/V projections — one wave-packed launch (96 M-tiles total)
    gemm_qkv_kernel<<<dim3(DIM / 128, 96), 256, GEMM_SMEM_BYTES>>>(
        xhi, xlo, yhi, ylo,
        wqh, wql, wkh, wkl, wvh, wvl,
        bq, bk, bv, qtmp, ktmp, vb);

    normrope_bf16_kernel<<<Mq, 256>>>(qtmp, qhi, qlo, gq, x_cos, x_sin);
    normrope_bf16_kernel<<<Mk, 256>>>(ktmp, khi, klo, gk, y_cos, y_sin);
    vtrans_split_kernel<<<dim3(DIM / 32, Mk / 32), 256>>>(vb, vthi, vtlo);

    attn_mma_kernel<<<dim3(BATCH * NHEADS, LQ / 64), 128, ATT_SMEM_BYTES>>>(
        qhi, qlo, khi, klo, vthi, vtlo, xhi, xlo);

    gemm_bf16x3_mma_kernel<<<dim3(DIM / 128, Mq / 128), 256, GEMM_SMEM_BYTES>>>(
        xhi, xlo, woh, wol, bo, out, Mq, DIM, DIM);
}

// round 16
// speedup vs baseline: 1.4679x; 1.0050x over previous
#include <cuda_runtime.h>
#include <cuda_bf16.h>
#include <cstdint>

// ----------------------------------------------------------------------------
// Problem constants
// ----------------------------------------------------------------------------
#define BATCH   2
#define LQ      4096
#define LKV     1024
#define DIM     1024
#define KV_DIM  768
#define NHEADS  16
#define HDIM    64

// ----------------------------------------------------------------------------
// Scratch (device globals; allocation-free per harness rules)
// ----------------------------------------------------------------------------
__device__ float g_qtmp[(BATCH*LQ)*DIM];
__device__ float g_ktmp[(BATCH*LKV)*DIM];

__device__ __nv_bfloat16 g_qhi[(BATCH*LQ)*DIM],  g_qlo[(BATCH*LQ)*DIM];
__device__ __nv_bfloat16 g_khi[(BATCH*LKV)*DIM], g_klo[(BATCH*LKV)*DIM];
__device__ __nv_bfloat16 g_vthi[(BATCH*LKV)*DIM], g_vtlo[(BATCH*LKV)*DIM];

__device__ __nv_bfloat16 g_xhi[(BATCH*LQ)*DIM],  g_xlo[(BATCH*LQ)*DIM];
__device__ __nv_bfloat16 g_yhi[(BATCH*LKV)*KV_DIM], g_ylo[(BATCH*LKV)*KV_DIM];
__device__ __nv_bfloat16 g_wqt_hi[DIM*DIM],    g_wqt_lo[DIM*DIM];
__device__ __nv_bfloat16 g_wkt_hi[DIM*KV_DIM], g_wkt_lo[DIM*KV_DIM];
__device__ __nv_bfloat16 g_wvt_hi[DIM*KV_DIM], g_wvt_lo[DIM*KV_DIM];
__device__ __nv_bfloat16 g_wot_hi[DIM*DIM],    g_wot_lo[DIM*DIM];

// ----------------------------------------------------------------------------
// mma.sync / cp.async / ldmatrix helpers (baseline PTX)
// ----------------------------------------------------------------------------
#define MMA16816(d, a, b) \
    asm volatile("mma.sync.aligned.m16n8k16.row.col.f32.bf16.bf16.f32 " \
        "{%0,%1,%2,%3}, {%4,%5,%6,%7}, {%8,%9}, {%0,%1,%2,%3};" \
        : "+f"((d)[0]), "+f"((d)[1]), "+f"((d)[2]), "+f"((d)[3]) \
        : "r"((a)[0]), "r"((a)[1]), "r"((a)[2]), "r"((a)[3]), \
          "r"((b)[0]), "r"((b)[1]))

#define CP16(sp, gp) do { \
    uint32_t _s = (uint32_t)__cvta_generic_to_shared(sp); \
    asm volatile("cp.async.cg.shared.global [%0], [%1], 16;" :: "r"(_s), "l"(gp)); \
} while (0)
#define CP_COMMIT()  asm volatile("cp.async.commit_group;" ::: "memory")
#define CP_WAIT1()   asm volatile("cp.async.wait_group 1;" ::: "memory")

#define LDSM_X4(r, addr) \
    asm volatile("ldmatrix.sync.aligned.m8n8.x4.shared.b16 {%0,%1,%2,%3}, [%4];" \
        : "=r"((r)[0]), "=r"((r)[1]), "=r"((r)[2]), "=r"((r)[3]) : "r"(addr))
#define LDSM_X2(r, addr) \
    asm volatile("ldmatrix.sync.aligned.m8n8.x2.shared.b16 {%0,%1}, [%2];" \
        : "=r"((r)[0]), "=r"((r)[1]) : "r"(addr))

__device__ __forceinline__ uint32_t packbf2(float x, float y) {
    __nv_bfloat162 t = __float22bfloat162_rn(make_float2(x, y));
    return *reinterpret_cast<uint32_t*>(&t);
}

// ----------------------------------------------------------------------------
// bf16x3 GEMM core (2-stage cp.async + ldmatrix). MODE 0: fp32 C += bias.
// MODE 1 (V-proj): write transposed bf16 hi/lo [b,h,d][c] directly.
// ----------------------------------------------------------------------------
#define SSTR 40
#define GEMM_STAGE_ELEMS (4 * 128 * SSTR)
#define GEMM_STAGE_BYTES (GEMM_STAGE_ELEMS * 2)
#define GEMM_TILE_BYTES  (128 * SSTR * 2)
#define GEMM_SMEM_BYTES  (2 * GEMM_STAGE_BYTES)           // 81920 B

template <int MODE>
__device__ __forceinline__ void gemm_body(
    const __nv_bfloat16* __restrict__ Ahi, const __nv_bfloat16* __restrict__ Alo,
    const __nv_bfloat16* __restrict__ Bhi, const __nv_bfloat16* __restrict__ Blo,
    const float* __restrict__ bias, float* __restrict__ C,
    __nv_bfloat16* __restrict__ Thi, __nv_bfloat16* __restrict__ Tlo,
    int N, int K, int bm, int bn, __nv_bfloat16* dsm)
{
    const uint32_t dsmAddr = (uint32_t)__cvta_generic_to_shared(dsm);

    const int tid  = threadIdx.x;
    const int wid  = tid >> 5;
    const int lane = tid & 31;
    const int warpM = wid >> 2;
    const int warpN = wid & 3;
    const int tq = lane >> 2;
    const int tr = lane & 3;

    const int r0g = tid >> 2;
    const int r1g = r0g + 64;
    const int c0g = (tid & 3) * 8;

    const uint32_t aRowOff = (uint32_t)(((warpM * 64 + (lane & 15)) * SSTR + ((lane >> 4) << 3)) * 2);
    const uint32_t bRowOff = (uint32_t)(((warpN * 32 + (lane & 7))  * SSTR + (((lane >> 3) & 1) << 3)) * 2);

    float acc[4][4][4];
#pragma unroll
    for (int i = 0; i < 4; i++)
#pragma unroll
        for (int j = 0; j < 4; j++)
#pragma unroll
            for (int r = 0; r < 4; r++) acc[i][j][r] = 0.f;

    const int nchunks = K >> 5;

    auto issue = [&](int c, int s) {
        __nv_bfloat16* sAh = dsm + s * GEMM_STAGE_ELEMS;
        __nv_bfloat16* sAl = sAh + 128 * SSTR;
        __nv_bfloat16* sBh = sAl + 128 * SSTR;
        __nv_bfloat16* sBl = sBh + 128 * SSTR;
        const int k0 = c << 5;
        const long a0 = (long)(bm + r0g) * K + k0 + c0g;
        const long a1 = (long)(bm + r1g) * K + k0 + c0g;
        const long b0 = (long)(bn + r0g) * K + k0 + c0g;
        const long b1 = (long)(bn + r1g) * K + k0 + c0g;
        CP16(&sAh[r0g * SSTR + c0g], &Ahi[a0]);
        CP16(&sAh[r1g * SSTR + c0g], &Ahi[a1]);
        CP16(&sAl[r0g * SSTR + c0g], &Alo[a0]);
        CP16(&sAl[r1g * SSTR + c0g], &Alo[a1]);
        CP16(&sBh[r0g * SSTR + c0g], &Bhi[b0]);
        CP16(&sBh[r1g * SSTR + c0g], &Bhi[b1]);
        CP16(&sBl[r0g * SSTR + c0g], &Blo[b0]);
        CP16(&sBl[r1g * SSTR + c0g], &Blo[b1]);
    };

    issue(0, 0);
    CP_COMMIT();

    for (int c = 0; c < nchunks; c++) {
        if (c + 1 < nchunks) issue(c + 1, (c + 1) & 1);
        CP_COMMIT();
        CP_WAIT1();
        __syncthreads();

        const uint32_t stAh = dsmAddr + (c & 1) * GEMM_STAGE_BYTES;
        const uint32_t stAl = stAh + GEMM_TILE_BYTES;
        const uint32_t stBh = stAl + GEMM_TILE_BYTES;
        const uint32_t stBl = stBh + GEMM_TILE_BYTES;

#pragma unroll
        for (int ks = 0; ks < 2; ks++) {
            const uint32_t ksOff = (uint32_t)(ks * 16 * 2);
            uint32_t ah[4][4], al[4][4];
#pragma unroll
            for (int mf = 0; mf < 4; mf++) {
                const uint32_t mOff = (uint32_t)(mf * 16 * SSTR * 2) + aRowOff + ksOff;
                LDSM_X4(ah[mf], stAh + mOff);
                LDSM_X4(al[mf], stAl + mOff);
            }
#pragma unroll
            for (int nf = 0; nf < 4; nf++) {
                const uint32_t nOff = (uint32_t)(nf * 8 * SSTR * 2) + bRowOff + ksOff;
                uint32_t bh[2], bl[2];
                LDSM_X2(bh, stBh + nOff);
                LDSM_X2(bl, stBl + nOff);
#pragma unroll
                for (int mf = 0; mf < 4; mf++) MMA16816(acc[mf][nf], ah[mf], bh);
#pragma unroll
                for (int mf = 0; mf < 4; mf++) MMA16816(acc[mf][nf], ah[mf], bl);
#pragma unroll
                for (int mf = 0; mf < 4; mf++) MMA16816(acc[mf][nf], al[mf], bh);
            }
        }
        __syncthreads();
    }

    if (MODE == 0) {
#pragma unroll
        for (int mf = 0; mf < 4; mf++) {
            const int row = bm + warpM * 64 + mf * 16 + tq;
#pragma unroll
            for (int nf = 0; nf < 4; nf++) {
                const int col = bn + warpN * 32 + nf * 8 + tr * 2;
                const float b0 = bias[col], b1 = bias[col + 1];
                float2 v0 = make_float2(acc[mf][nf][0] + b0, acc[mf][nf][1] + b1);
                float2 v1 = make_float2(acc[mf][nf][2] + b0, acc[mf][nf][3] + b1);
                *(float2*)&C[(long)row * N + col]       = v0;
                *(float2*)&C[(long)(row + 8) * N + col] = v1;
            }
        }
    } else {
        // V-proj: write transposed bf16 hi/lo to [ (b*16+h)*64+d ][ c ], c-stride 1
#pragma unroll
        for (int mf = 0; mf < 4; mf++) {
            const int row0 = bm + warpM * 64 + mf * 16 + tq;   // token index
#pragma unroll
            for (int nf = 0; nf < 4; nf++) {
                const int col = bn + warpN * 32 + nf * 8 + tr * 2;  // h*64+d
                const float b0 = bias[col], b1 = bias[col + 1];
#pragma unroll
                for (int r = 0; r < 2; r++) {
                    const int row = row0 + r * 8;
                    const int bb = row >> 10, cc = row & 1023;
                    const float va = acc[mf][nf][2 * r]     + b0;
                    const float vb = acc[mf][nf][2 * r + 1] + b1;
                    const long o0 = ((long)(bb * (NHEADS * HDIM) + col)) * LKV + cc;
                    const long o1 = o0 + LKV;
                    __nv_bfloat16 ha = __float2bfloat16(va);
                    __nv_bfloat16 hb = __float2bfloat16(vb);
                    Thi[o0] = ha;
                    Thi[o1] = hb;
                    Tlo[o0] = __float2bfloat16(va - __bfloat162float(ha));
                    Tlo[o1] = __float2bfloat16(vb - __bfloat162float(hb));
                }
            }
        }
    }
}

// Fused Q/K/V projection launch. grid = (8, 96).
__global__ __launch_bounds__(256, 2) void gemm_qkv_kernel(
    const __nv_bfloat16* __restrict__ xhi, const __nv_bfloat16* __restrict__ xlo,
    const __nv_bfloat16* __restrict__ yhi, const __nv_bfloat16* __restrict__ ylo,
    const __nv_bfloat16* __restrict__ wqh, const __nv_bfloat16* __restrict__ wql,
    const __nv_bfloat16* __restrict__ wkh, const __nv_bfloat16* __restrict__ wkl,
    const __nv_bfloat16* __restrict__ wvh, const __nv_bfloat16* __restrict__ wvl,
    const float* __restrict__ bq, const float* __restrict__ bk, const float* __restrict__ bv,
    float* __restrict__ qtmp, float* __restrict__ ktmp,
    __nv_bfloat16* __restrict__ vthi, __nv_bfloat16* __restrict__ vtlo)
{
    extern __shared__ __nv_bfloat16 dsm[];
    const int by = blockIdx.y;
    const int bn = blockIdx.x * 128;

    if (by < 64) {
        gemm_body<0>(xhi, xlo, wqh, wql, bq, qtmp, nullptr, nullptr,
                     DIM, DIM, by * 128, bn, dsm);
    } else if (by < 80) {
        gemm_body<0>(yhi, ylo, wkh, wkl, bk, ktmp, nullptr, nullptr,
                     DIM, KV_DIM, (by - 64) * 128, bn, dsm);
    } else {
        gemm_body<1>(yhi, ylo, wvh, wvl, bv, nullptr, vthi, vtlo,
                     DIM, KV_DIM, (by - 80) * 128, bn, dsm);
    }
}

// Standalone GEMM (O-projection)
__global__ __launch_bounds__(256, 2) void gemm_bf16x3_mma_kernel(
    const __nv_bfloat16* __restrict__ Ahi, const __nv_bfloat16* __restrict__ Alo,
    const __nv_bfloat16* __restrict__ Bhi, const __nv_bfloat16* __restrict__ Blo,
    const float* __restrict__ bias, float* __restrict__ C,
    int M, int N, int K)
{
    extern __shared__ __nv_bfloat16 dsm[];
    gemm_body<0>(Ahi, Alo, Bhi, Blo, bias, C, nullptr, nullptr,
                 N, K, blockIdx.y * 128, blockIdx.x * 128, dsm);
}

// ----------------------------------------------------------------------------
// Split fp32 -> bf16 hi + lo: x and y in ONE launch (flat index)
// ----------------------------------------------------------------------------
__global__ __launch_bounds__(256) void split_xy_kernel(
    const float* __restrict__ x, __nv_bfloat16* __restrict__ xhi, __nv_bfloat16* __restrict__ xlo, int n4x,
    const float* __restrict__ y, __nv_bfloat16* __restrict__ yhi, __nv_bfloat16* __restrict__ ylo, int n4y)
{
    int i = blockIdx.x * blockDim.x + threadIdx.x;
    const float* src; __nv_bfloat16 *hi, *lo;
    if (i < n4x) { src = x; hi = xhi; lo = xlo; }
    else {
        i -= n4x;
        if (i >= n4y) return;
        src = y; hi = yhi; lo = ylo;
    }
    float4 v = *(const float4*)&src[(long)i * 4];
    __nv_bfloat16 h0 = __float2bfloat16(v.x), h1 = __float2bfloat16(v.y);
    __nv_bfloat16 h2 = __float2bfloat16(v.z), h3 = __float2bfloat16(v.w);
    uint32_t ph0 = packbf2(v.x, v.y), ph1 = packbf2(v.z, v.w);
    uint32_t pl0 = packbf2(v.x - __bfloat162float(h0), v.y - __bfloat162float(h1));
    uint32_t pl1 = packbf2(v.z - __bfloat162float(h2), v.w - __bfloat162float(h3));
    *(uint2*)&hi[(long)i * 4] = make_uint2(ph0, ph1);
    *(uint2*)&lo[(long)i * 4] = make_uint2(pl0, pl1);
}

// ----------------------------------------------------------------------------
// Split + transpose: all 4 weights in ONE launch (z selects; ragged K early-exit)
// ----------------------------------------------------------------------------
__global__ __launch_bounds__(256) void split_transpose4_kernel(
    const float* __restrict__ Wq, __nv_bfloat16* __restrict__ Tqh, __nv_bfloat16* __restrict__ Tql,
    const float* __restrict__ Wo, __nv_bfloat16* __restrict__ Toh, __nv_bfloat16* __restrict__ Tol,
    const float* __restrict__ Wk, __nv_bfloat16* __restrict__ Tkh, __nv_bfloat16* __restrict__ Tkl,
    const float* __restrict__ Wv, __nv_bfloat16* __restrict__ Tvh, __nv_bfloat16* __restrict__ Tvl)
{
    const int z = blockIdx.z;
    const float* W;
    __nv_bfloat16 *Thi, *Tlo;
    int K;
    switch (z) {
        case 0: W = Wq; Thi = Tqh; Tlo = Tql; K = DIM;    break;
        case 1: W = Wo; Thi = Toh; Tlo = Tol; K = DIM;    break;
        case 2: W = Wk; Thi = Tkh; Tlo = Tkl; K = KV_DIM; break;
        default:W = Wv; Thi = Tvh; Tlo = Tvl; K = KV_DIM; break;
    }
    const int by = blockIdx.y * 32;
    if (by >= K) return;
    const int N = DIM;

    __shared__ float tile[32][33];
    const int bx = blockIdx.x * 32;
    const int tx = threadIdx.x & 31;
    const int ty = threadIdx.x >> 5;
#pragma unroll
    for (int i = 0; i < 4; i++) {
        int kk = by + ty + i * 8;
        tile[ty + i * 8][tx] = W[(long)kk * N + bx + tx];
    }
    __syncthreads();
#pragma unroll
    for (int i = 0; i < 4; i++) {
        int nn = bx + ty + i * 8;
        float v = tile[tx][ty + i * 8];
        __nv_bfloat16 h = __float2bfloat16(v);
        __nv_bfloat16 l = __float2bfloat16(v - __bfloat162float(h));
        Thi[(long)nn * K + by + tx] = h;
        Tlo[(long)nn * K + by + tx] = l;
    }
}

// ----------------------------------------------------------------------------
// Fused RMSNorm + RoPE -> bf16 hi/lo outputs
// ----------------------------------------------------------------------------
__global__ __launch_bounds__(256) void normrope_bf16_kernel(
    const float* __restrict__ in, __nv_bfloat16* __restrict__ outhi,
    __nv_bfloat16* __restrict__ outlo,
    const float* __restrict__ g, const float* __restrict__ cosb,
    const float* __restrict__ sinb)
{
    const int row = blockIdx.x;
    const float* h = in + (long)row * DIM;
    const int tid = threadIdx.x;
    const int e = tid << 2;

    float4 t = *(const float4*)&h[e];
    float ss = t.x * t.x + t.y * t.y + t.z * t.z + t.w * t.w;
#pragma unroll
    for (int o = 16; o > 0; o >>= 1)
        ss += __shfl_xor_sync(0xffffffffu, ss, o);
    __shared__ float red[8];
    if ((tid & 31) == 0) red[tid >> 5] = ss;
    __syncthreads();
    float tot = red[0] + red[1] + red[2] + red[3] + red[4] + red[5] + red[6] + red[7];
    float inv = rsqrtf(tot * (1.0f / (float)DIM) + 1e-6f);

    const int d   = e & (HDIM - 1);
    const int po  = (d < 32) ? 32 : -32;
    const float sgn = (d < 32) ? -1.0f : 1.0f;

    float4 tp  = *(const float4*)&h[e + po];
    float4 g4  = *(const float4*)&g[e];
    float4 gp4 = *(const float4*)&g[e + po];
    float4 c4  = *(const float4*)&cosb[(long)row * HDIM + d];
    float4 s4  = *(const float4*)&sinb[(long)row * HDIM + d];

    float4 o4;
    o4.x = t.x * inv * g4.x * c4.x + sgn * tp.x * inv * gp4.x * s4.x;
    o4.y = t.y * inv * g4.y * c4.y + sgn * tp.y * inv * gp4.y * s4.y;
    o4.z = t.z * inv * g4.z * c4.z + sgn * tp.z * inv * gp4.z * s4.z;
    o4.w = t.w * inv * g4.w * c4.w + sgn * tp.w * inv * gp4.w * s4.w;

    __nv_bfloat16 h0 = __float2bfloat16(o4.x), h1 = __float2bfloat16(o4.y);
    __nv_bfloat16 h2 = __float2bfloat16(o4.z), h3 = __float2bfloat16(o4.w);
    uint32_t ph0 = packbf2(o4.x, o4.y), ph1 = packbf2(o4.z, o4.w);
    uint32_t pl0 = packbf2(o4.x - __bfloat162float(h0), o4.y - __bfloat162float(h1));
    uint32_t pl1 = packbf2(o4.z - __bfloat162float(h2), o4.w - __bfloat162float(h3));
    *(uint2*)&outhi[(long)row * DIM + e] = make_uint2(ph0, ph1);
    *(uint2*)&outlo[(long)row * DIM + e] = make_uint2(pl0, pl1);
}

// ----------------------------------------------------------------------------
// Flash attention, bf16x3 mma.sync, 2-stage cp.async pipeline + ldmatrix.
// CTA = 128 threads (4 warps), 64 q-rows per CTA. KV chunks of 64.
// ----------------------------------------------------------------------------
#define SK 72
#define ATT_STAGE_ELEMS (4 * 64 * SK)
#define ATT_STAGE_BYTES (ATT_STAGE_ELEMS * 2)
#define ATT_TILE_BYTES  (64 * SK * 2)
#define ATT_SMEM_BYTES  (2 * ATT_STAGE_BYTES)     // 73728 B

__global__ __launch_bounds__(128, 3) void attn_mma_kernel(
    const __nv_bfloat16* __restrict__ qhi, const __nv_bfloat16* __restrict__ qlo,
    const __nv_bfloat16* __restrict__ khi, const __nv_bfloat16* __restrict__ klo,
    const __nv_bfloat16* __restrict__ vthi, const __nv_bfloat16* __restrict__ vtlo,
    __nv_bfloat16* __restrict__ ohi, __nv_bfloat16* __restrict__ olo)
{
    extern __shared__ __nv_bfloat16 dsm[];
    const uint32_t dsmAddr = (uint32_t)__cvta_generic_to_shared(dsm);

    const int tid  = threadIdx.x;
    const int w    = tid >> 5;
    const int lane = tid & 31;
    const int tq   = lane >> 2;
    const int tr   = lane & 3;
    const int b    = blockIdx.x >> 4;
    const int h    = blockIdx.x & 15;
    const int q0   = blockIdx.y * 64;
    const float SCALE = 0.125f;

    const int lrow = tid >> 1, lhalf = (tid & 1) * 32;
    const uint32_t fragOff = (uint32_t)((((lane & 7) * SK) + (((lane >> 3) & 1) << 3)) * 2);

    auto issue = [&](int c, int s) {
        __nv_bfloat16* sKh = dsm + s * ATT_STAGE_ELEMS;
        __nv_bfloat16* sKl = sKh + 64 * SK;
        __nv_bfloat16* sVh = sKl + 64 * SK;
        __nv_bfloat16* sVl = sVh + 64 * SK;
        const int j0 = c << 6;
        const __nv_bfloat16* kh_g = khi + ((long)(b * LKV + j0 + lrow)) * DIM + h * HDIM + lhalf;
        const __nv_bfloat16* kl_g = klo + ((long)(b * LKV + j0 + lrow)) * DIM + h * HDIM + lhalf;
        const long vo = ((long)((b * NHEADS + h) * HDIM + lrow)) * LKV + j0 + lhalf;
        const __nv_bfloat16* vh_g = vthi + vo;
        const __nv_bfloat16* vl_g = vtlo + vo;
#pragma unroll
        for (int u = 0; u < 4; u++) {
            const int so = lrow * SK + lhalf + u * 8;
            CP16(&sKh[so], &kh_g[u * 8]);
            CP16(&sKl[so], &kl_g[u * 8]);
            CP16(&sVh[so], &vh_g[u * 8]);
            CP16(&sVl[so], &vl_g[u * 8]);
        }
    };

    const long grow0 = (long)(b * LQ + q0 + w * 16 + tq);
    const __nv_bfloat16* qh0 = qhi + grow0 * DIM + h * HDIM;
    const __nv_bfloat16* ql0 = qlo + grow0 * DIM + h * HDIM;
    uint32_t aQh[4][4], aQl[4][4];
#pragma unroll
    for (int ks = 0; ks < 4; ks++) {
        const int c0 = ks * 16 + 2 * tr;
        aQh[ks][0] = *(const uint32_t*)&qh0[c0];
        aQh[ks][1] = *(const uint32_t*)&qh0[8 * DIM + c0];
        aQh[ks][2] = *(const uint32_t*)&qh0[c0 + 8];
        aQh[ks][3] = *(const uint32_t*)&qh0[8 * DIM + c0 + 8];
        aQl[ks][0] = *(const uint32_t*)&ql0[c0];
        aQl[ks][1] = *(const uint32_t*)&ql0[8 * DIM + c0];
        aQl[ks][2] = *(const uint32_t*)&ql0[c0 + 8];
        aQl[ks][3] = *(const uint32_t*)&ql0[8 * DIM + c0 + 8];
    }

    float oacc[8][4];
#pragma unroll
    for (int i = 0; i < 8; i++)
#pragma unroll
        for (int j = 0; j < 4; j++) oacc[i][j] = 0.f;
    float m[2] = {-1e30f, -1e30f}, l[2] = {0.f, 0.f};

    issue(0, 0);
    CP_COMMIT();

    const int NCH = LKV / 64;
    for (int c = 0; c < NCH; c++) {
        if (c + 1 < NCH) issue(c + 1, (c + 1) & 1);
        CP_COMMIT();
        CP_WAIT1();
        __syncthreads();

        const uint32_t stKh = dsmAddr + (c & 1) * ATT_STAGE_BYTES;
        const uint32_t stVh = stKh + 2 * ATT_TILE_BYTES;

        float s[8][4];
#pragma unroll
        for (int i = 0; i < 8; i++)
#pragma unroll
            for (int j = 0; j < 4; j++) s[i][j] = 0.f;

#pragma unroll
        for (int ks = 0; ks < 4; ks++) {
            const uint32_t ksOff = (uint32_t)(ks * 32);
#pragma unroll
            for (int nf = 0; nf < 8; nf += 2) {
                const uint32_t base0 = stKh + (uint32_t)(nf * 8 * SK * 2) + fragOff + ksOff;
                const uint32_t base1 = base0 + (uint32_t)(8 * SK * 2);
                const uint32_t lbase0 = base0 + (uint32_t)(ATT_TILE_BYTES);
                const uint32_t lbase1 = lbase0 + (uint32_t)(8 * SK * 2);
                uint32_t bh0[2], bh1[2], bl0[2], bl1[2];
                LDSM_X2(bh0, base0);  LDSM_X2(bh1, base1);
                LDSM_X2(bl0, lbase0); LDSM_X2(bl1, lbase1);
                MMA16816(s[nf],     aQh[ks], bh0);
                MMA16816(s[nf + 1], aQh[ks], bh1);
                MMA16816(s[nf],     aQh[ks], bl0);
                MMA16816(s[nf + 1], aQh[ks], bl1);
                MMA16816(s[nf],     aQl[ks], bh0);
                MMA16816(s[nf + 1], aQl[ks], bh1);
            }
        }

#pragma unroll
        for (int r = 0; r < 2; r++) {
            float mx = -1e30f;
#pragma unroll
            for (int nf = 0; nf < 8; nf++)
                mx = fmaxf(mx, fmaxf(s[nf][2 * r], s[nf][2 * r + 1]));
            mx = fmaxf(mx, __shfl_xor_sync(0xffffffffu, mx, 1));
            mx = fmaxf(mx, __shfl_xor_sync(0xffffffffu, mx, 2));
            const float mn = fmaxf(m[r], mx);
            const float f  = __expf((m[r] - mn) * SCALE);
            float rs = 0.f;
#pragma unroll
            for (int nf = 0; nf < 8; nf++) {
                s[nf][2 * r]     = __expf((s[nf][2 * r]     - mn) * SCALE);
                s[nf][2 * r + 1] = __expf((s[nf][2 * r + 1] - mn) * SCALE);
                rs += s[nf][2 * r] + s[nf][2 * r + 1];
            }
            rs += __shfl_xor_sync(0xffffffffu, rs, 1);
            rs += __shfl_xor_sync(0xffffffffu, rs, 2);
            m[r] = mn;
            l[r] = l[r] * f + rs;
#pragma unroll
            for (int nf = 0; nf < 8; nf++) {
                oacc[nf][2 * r]     *= f;
                oacc[nf][2 * r + 1] *= f;
            }
        }

#pragma unroll
        for (int ks = 0; ks < 4; ks++) {
            float v0 = s[2 * ks][0],     v1 = s[2 * ks][1];
            float v2 = s[2 * ks][2],     v3 = s[2 * ks][3];
            float v4 = s[2 * ks + 1][0], v5 = s[2 * ks + 1][1];
            float v6 = s[2 * ks + 1][2], v7 = s[2 * ks + 1][3];
            __nv_bfloat16 h0 = __float2bfloat16(v0), h1 = __float2bfloat16(v1);
            __nv_bfloat16 h2 = __float2bfloat16(v2), h3 = __float2bfloat16(v3);
            __nv_bfloat16 h4 = __float2bfloat16(v4), h5 = __float2bfloat16(v5);
            __nv_bfloat16 h6 = __float2bfloat16(v6), h7 = __float2bfloat16(v7);
            uint32_t aPh[4], aPl[4];
            aPh[0] = packbf2(v0, v1); aPh[1] = packbf2(v2, v3);
            aPh[2] = packbf2(v4, v5); aPh[3] = packbf2(v6, v7);
            aPl[0] = packbf2(v0 - __bfloat162float(h0), v1 - __bfloat162float(h1));
            aPl[1] = packbf2(v2 - __bfloat162float(h2), v3 - __bfloat162float(h3));
            aPl[2] = packbf2(v4 - __bfloat162float(h4), v5 - __bfloat162float(h5));
            aPl[3] = packbf2(v6 - __bfloat162float(h6), v7 - __bfloat162float(h7));

            const uint32_t ksOff = (uint32_t)(ks * 32);
#pragma unroll
            for (int nf = 0; nf < 8; nf += 2) {
                const uint32_t base0 = stVh + (uint32_t)(nf * 8 * SK * 2) + fragOff + ksOff;
                const uint32_t base1 = base0 + (uint32_t)(8 * SK * 2);
                const uint32_t lbase0 = base0 + (uint32_t)(ATT_TILE_BYTES);
                const uint32_t lbase1 = lbase0 + (uint32_t)(8 * SK * 2);
                uint32_t bh0[2], bh1[2], bl0[2], bl1[2];
                LDSM_X2(bh0, base0);  LDSM_X2(bh1, base1);
                LDSM_X2(bl0, lbase0); LDSM_X2(bl1, lbase1);
                MMA16816(oacc[nf],     aPh, bh0);
                MMA16816(oacc[nf + 1], aPh, bh1);
                MMA16816(oacc[nf],     aPh, bl0);
                MMA16816(oacc[nf + 1], aPh, bl1);
                MMA16816(oacc[nf],     aPl, bh0);
                MMA16816(oacc[nf + 1], aPl, bh1);
            }
        }
        __syncthreads();
    }

    const float inv0 = 1.f / l[0], inv1 = 1.f / l[1];
    __nv_bfloat16* oh0 = ohi + grow0 * DIM + h * HDIM;
    __nv_bfloat16* ol0 = olo + grow0 * DIM + h * HDIM;
#pragma unroll
    for (int nf = 0; nf < 8; nf++) {
        const int col = nf * 8 + 2 * tr;
        float x0 = oacc[nf][0] * inv0, y0 = oacc[nf][1] * inv0;
        float x1 = oacc[nf][2] * inv1, y1 = oacc[nf][3] * inv1;
        __nv_bfloat16 hx0 = __float2bfloat16(x0), hy0 = __float2bfloat16(y0);
        __nv_bfloat16 hx1 = __float2bfloat16(x1), hy1 = __float2bfloat16(y1);
        *(uint32_t*)&oh0[col]           = packbf2(x0, y0);
        *(uint32_t*)&oh0[8 * DIM + col] = packbf2(x1, y1);
        *(uint32_t*)&ol0[col]           = packbf2(x0 - __bfloat162float(hx0), y0 - __bfloat162float(hy0));
        *(uint32_t*)&ol0[8 * DIM + col] = packbf2(x1 - __bfloat162float(hx1), y1 - __bfloat162float(hy1));
    }
}

// ----------------------------------------------------------------------------
// Launch
// ----------------------------------------------------------------------------
extern "C" void kernel_launch(void* const* d_in, const int* in_sizes, int n_in,
                              void* d_out, int out_size)
{
    const float* x     = (const float*)d_in[0];
    const float* y     = (const float*)d_in[1];
    const float* x_cos = (const float*)d_in[2];
    const float* x_sin = (const float*)d_in[3];
    const float* y_cos = (const float*)d_in[4];
    const float* y_sin = (const float*)d_in[5];
    const float* Wq    = (const float*)d_in[6];
    const float* bq    = (const float*)d_in[7];
    const float* Wk    = (const float*)d_in[8];
    const float* bk    = (const float*)d_in[9];
    const float* Wv    = (const float*)d_in[10];
    const float* bv    = (const float*)d_in[11];
    const float* Wo    = (const float*)d_in[12];
    const float* bo    = (const float*)d_in[13];
    const float* gq    = (const float*)d_in[14];
    const float* gk    = (const float*)d_in[15];
    float* out = (float*)d_out;

    float *qtmp, *ktmp;
    cudaGetSymbolAddress((void**)&qtmp, g_qtmp);
    cudaGetSymbolAddress((void**)&ktmp, g_ktmp);

    __nv_bfloat16 *qhi, *qlo, *khi, *klo, *vthi, *vtlo;
    __nv_bfloat16 *xhi, *xlo, *yhi, *ylo;
    __nv_bfloat16 *wqh, *wql, *wkh, *wkl, *wvh, *wvl, *woh, *wol;
    cudaGetSymbolAddress((void**)&qhi, g_qhi);
    cudaGetSymbolAddress((void**)&qlo, g_qlo);
    cudaGetSymbolAddress((void**)&khi, g_khi);
    cudaGetSymbolAddress((void**)&klo, g_klo);
    cudaGetSymbolAddress((void**)&vthi, g_vthi);
    cudaGetSymbolAddress((void**)&vtlo, g_vtlo);
    cudaGetSymbolAddress((void**)&xhi, g_xhi);
    cudaGetSymbolAddress((void**)&xlo, g_xlo);
    cudaGetSymbolAddress((void**)&yhi, g_yhi);
    cudaGetSymbolAddress((void**)&ylo, g_ylo);
    cudaGetSymbolAddress((void**)&wqh, g_wqt_hi);
    cudaGetSymbolAddress((void**)&wql, g_wqt_lo);
    cudaGetSymbolAddress((void**)&wkh, g_wkt_hi);
    cudaGetSymbolAddress((void**)&wkl, g_wkt_lo);
    cudaGetSymbolAddress((void**)&wvh, g_wvt_hi);
    cudaGetSymbolAddress((void**)&wvl, g_wvt_lo);
    cudaGetSymbolAddress((void**)&woh, g_wot_hi);
    cudaGetSymbolAddress((void**)&wol, g_wot_lo);

    cudaFuncSetAttribute(gemm_qkv_kernel,
                         cudaFuncAttributeMaxDynamicSharedMemorySize, GEMM_SMEM_BYTES);
    cudaFuncSetAttribute(gemm_bf16x3_mma_kernel,
                         cudaFuncAttributeMaxDynamicSharedMemorySize, GEMM_SMEM_BYTES);
    cudaFuncSetAttribute(attn_mma_kernel,
                         cudaFuncAttributeMaxDynamicSharedMemorySize, ATT_SMEM_BYTES);

    const int Mq = BATCH * LQ;    // 8192
    const int Mk = BATCH * LKV;   // 2048
    const int n4x = Mq * DIM / 4;
    const int n4y = Mk * KV_DIM / 4;

    // Elementwise prep: activations split (1 launch) + weight transposes (1 launch)
    split_xy_kernel<<<(n4x + n4y + 255) / 256, 256>>>(
        x, xhi, xlo, n4x, y, yhi, ylo, n4y);
    split_transpose4_kernel<<<dim3(DIM / 32, DIM / 32, 4), 256>>>(
        Wq, wqh, wql, Wo, woh, wol, Wk, wkh, wkl, Wv, wvh, wvl);

    // Fused Q/K/V projections — one wave-packed launch; V writes transposed hi/lo
    gemm_qkv_kernel<<<dim3(DIM / 128, 96), 256, GEMM_SMEM_BYTES>>>(
        xhi, xlo, yhi, ylo,
        wqh, wql, wkh, wkl, wvh, wvl,
        bq, bk, bv, qtmp, ktmp, vthi, vtlo);

    normrope_bf16_kernel<<<Mq, 256>>>(qtmp, qhi, qlo, gq, x_cos, x_sin);
    normrope_bf16_kernel<<<Mk, 256>>>(ktmp, khi, klo, gk, y_cos, y_sin);

    attn_mma_kernel<<<dim3(BATCH * NHEADS, LQ / 64), 128, ATT_SMEM_BYTES>>>(
        qhi, qlo, khi, klo, vthi, vtlo, xhi, xlo);

    gemm_bf16x3_mma_kernel<<<dim3(DIM / 128, Mq / 128), 256, GEMM_SMEM_BYTES>>>(
        xhi, xlo, woh, wol, bo, out, Mq, DIM, DIM);
}

// round 17
// speedup vs baseline: 1.6957x; 1.1552x over previous
#include <cuda_runtime.h>
#include <cuda_bf16.h>
#include <cuda_fp16.h>
#include <cstdint>

// ----------------------------------------------------------------------------
// Problem constants
// ----------------------------------------------------------------------------
#define BATCH   2
#define LQ      4096
#define LKV     1024
#define DIM     1024
#define KV_DIM  768
#define NHEADS  16
#define HDIM    64

// ----------------------------------------------------------------------------
// Scratch (device globals; allocation-free per harness rules)
// ----------------------------------------------------------------------------
__device__ float g_qtmp[(BATCH*LQ)*DIM];
__device__ float g_ktmp[(BATCH*LKV)*DIM];

__device__ __nv_bfloat16 g_qhi[(BATCH*LQ)*DIM],  g_qlo[(BATCH*LQ)*DIM];
__device__ __nv_bfloat16 g_khi[(BATCH*LKV)*DIM], g_klo[(BATCH*LKV)*DIM];
__device__ __half        g_vthf[(BATCH*LKV)*DIM], g_vtlf[(BATCH*LKV)*DIM]; // V^T fp16 hi/lo

__device__ __nv_bfloat16 g_xhi[(BATCH*LQ)*DIM],  g_xlo[(BATCH*LQ)*DIM];
__device__ __nv_bfloat16 g_yhi[(BATCH*LKV)*KV_DIM], g_ylo[(BATCH*LKV)*KV_DIM];
__device__ __half        g_yh16[(BATCH*LKV)*KV_DIM];   // y single fp16 (V-proj A)
__device__ __half        g_oa[(BATCH*LQ)*DIM];         // attention out, fp16 single

__device__ __nv_bfloat16 g_wqt_hi[DIM*DIM],    g_wqt_lo[DIM*DIM];
__device__ __nv_bfloat16 g_wkt_hi[DIM*KV_DIM], g_wkt_lo[DIM*KV_DIM];
__device__ __half        g_wvt_hi[DIM*KV_DIM], g_wvt_lo[DIM*KV_DIM];
__device__ __half        g_wot_hi[DIM*DIM],    g_wot_lo[DIM*DIM];

// ----------------------------------------------------------------------------
// mma.sync / cp.async / ldmatrix helpers (baseline PTX)
// ----------------------------------------------------------------------------
#define MMA16816(d, a, b) \
    asm volatile("mma.sync.aligned.m16n8k16.row.col.f32.bf16.bf16.f32 " \
        "{%0,%1,%2,%3}, {%4,%5,%6,%7}, {%8,%9}, {%0,%1,%2,%3};" \
        : "+f"((d)[0]), "+f"((d)[1]), "+f"((d)[2]), "+f"((d)[3]) \
        : "r"((a)[0]), "r"((a)[1]), "r"((a)[2]), "r"((a)[3]), \
          "r"((b)[0]), "r"((b)[1]))

#define MMA16816F16(d, a, b) \
    asm volatile("mma.sync.aligned.m16n8k16.row.col.f32.f16.f16.f32 " \
        "{%0,%1,%2,%3}, {%4,%5,%6,%7}, {%8,%9}, {%0,%1,%2,%3};" \
        : "+f"((d)[0]), "+f"((d)[1]), "+f"((d)[2]), "+f"((d)[3]) \
        : "r"((a)[0]), "r"((a)[1]), "r"((a)[2]), "r"((a)[3]), \
          "r"((b)[0]), "r"((b)[1]))

#define CP16(sp, gp) do { \
    uint32_t _s = (uint32_t)__cvta_generic_to_shared(sp); \
    asm volatile("cp.async.cg.shared.global [%0], [%1], 16;" :: "r"(_s), "l"(gp)); \
} while (0)
#define CP_COMMIT()  asm volatile("cp.async.commit_group;" ::: "memory")
#define CP_WAIT1()   asm volatile("cp.async.wait_group 1;" ::: "memory")

#define LDSM_X4(r, addr) \
    asm volatile("ldmatrix.sync.aligned.m8n8.x4.shared.b16 {%0,%1,%2,%3}, [%4];" \
        : "=r"((r)[0]), "=r"((r)[1]), "=r"((r)[2]), "=r"((r)[3]) : "r"(addr))
#define LDSM_X2(r, addr) \
    asm volatile("ldmatrix.sync.aligned.m8n8.x2.shared.b16 {%0,%1}, [%2];" \
        : "=r"((r)[0]), "=r"((r)[1]) : "r"(addr))

__device__ __forceinline__ uint32_t packbf2(float x, float y) {
    __nv_bfloat162 t = __float22bfloat162_rn(make_float2(x, y));
    return *reinterpret_cast<uint32_t*>(&t);
}
__device__ __forceinline__ uint32_t packh2(float x, float y) {
    __half2 t = __float22half2_rn(make_float2(x, y));
    return *reinterpret_cast<uint32_t*>(&t);
}

// ----------------------------------------------------------------------------
// bf16x3 GEMM core (2-stage cp.async + ldmatrix). fp32 C += bias.
// ----------------------------------------------------------------------------
#define SSTR 40
#define GEMM_STAGE_ELEMS (4 * 128 * SSTR)
#define GEMM_STAGE_BYTES (GEMM_STAGE_ELEMS * 2)
#define GEMM_TILE_BYTES  (128 * SSTR * 2)
#define GEMM_SMEM_BYTES  (2 * GEMM_STAGE_BYTES)           // 81920 B

__device__ __forceinline__ void gemm_body(
    const __nv_bfloat16* __restrict__ Ahi, const __nv_bfloat16* __restrict__ Alo,
    const __nv_bfloat16* __restrict__ Bhi, const __nv_bfloat16* __restrict__ Blo,
    const float* __restrict__ bias, float* __restrict__ C,
    int N, int K, int bm, int bn, __nv_bfloat16* dsm)
{
    const uint32_t dsmAddr = (uint32_t)__cvta_generic_to_shared(dsm);

    const int tid  = threadIdx.x;
    const int wid  = tid >> 5;
    const int lane = tid & 31;
    const int warpM = wid >> 2;
    const int warpN = wid & 3;
    const int tq = lane >> 2;
    const int tr = lane & 3;

    const int r0g = tid >> 2;
    const int r1g = r0g + 64;
    const int c0g = (tid & 3) * 8;

    const uint32_t aRowOff = (uint32_t)(((warpM * 64 + (lane & 15)) * SSTR + ((lane >> 4) << 3)) * 2);
    const uint32_t bRowOff = (uint32_t)(((warpN * 32 + (lane & 7))  * SSTR + (((lane >> 3) & 1) << 3)) * 2);

    float acc[4][4][4];
#pragma unroll
    for (int i = 0; i < 4; i++)
#pragma unroll
        for (int j = 0; j < 4; j++)
#pragma unroll
            for (int r = 0; r < 4; r++) acc[i][j][r] = 0.f;

    const int nchunks = K >> 5;

    auto issue = [&](int c, int s) {
        __nv_bfloat16* sAh = dsm + s * GEMM_STAGE_ELEMS;
        __nv_bfloat16* sAl = sAh + 128 * SSTR;
        __nv_bfloat16* sBh = sAl + 128 * SSTR;
        __nv_bfloat16* sBl = sBh + 128 * SSTR;
        const int k0 = c << 5;
        const long a0 = (long)(bm + r0g) * K + k0 + c0g;
        const long a1 = (long)(bm + r1g) * K + k0 + c0g;
        const long b0 = (long)(bn + r0g) * K + k0 + c0g;
        const long b1 = (long)(bn + r1g) * K + k0 + c0g;
        CP16(&sAh[r0g * SSTR + c0g], &Ahi[a0]);
        CP16(&sAh[r1g * SSTR + c0g], &Ahi[a1]);
        CP16(&sAl[r0g * SSTR + c0g], &Alo[a0]);
        CP16(&sAl[r1g * SSTR + c0g], &Alo[a1]);
        CP16(&sBh[r0g * SSTR + c0g], &Bhi[b0]);
        CP16(&sBh[r1g * SSTR + c0g], &Bhi[b1]);
        CP16(&sBl[r0g * SSTR + c0g], &Blo[b0]);
        CP16(&sBl[r1g * SSTR + c0g], &Blo[b1]);
    };

    issue(0, 0);
    CP_COMMIT();

    for (int c = 0; c < nchunks; c++) {
        if (c + 1 < nchunks) issue(c + 1, (c + 1) & 1);
        CP_COMMIT();
        CP_WAIT1();
        __syncthreads();

        const uint32_t stAh = dsmAddr + (c & 1) * GEMM_STAGE_BYTES;
        const uint32_t stAl = stAh + GEMM_TILE_BYTES;
        const uint32_t stBh = stAl + GEMM_TILE_BYTES;
        const uint32_t stBl = stBh + GEMM_TILE_BYTES;

#pragma unroll
        for (int ks = 0; ks < 2; ks++) {
            const uint32_t ksOff = (uint32_t)(ks * 16 * 2);
            uint32_t ah[4][4], al[4][4];
#pragma unroll
            for (int mf = 0; mf < 4; mf++) {
                const uint32_t mOff = (uint32_t)(mf * 16 * SSTR * 2) + aRowOff + ksOff;
                LDSM_X4(ah[mf], stAh + mOff);
                LDSM_X4(al[mf], stAl + mOff);
            }
#pragma unroll
            for (int nf = 0; nf < 4; nf++) {
                const uint32_t nOff = (uint32_t)(nf * 8 * SSTR * 2) + bRowOff + ksOff;
                uint32_t bh[2], bl[2];
                LDSM_X2(bh, stBh + nOff);
                LDSM_X2(bl, stBl + nOff);
#pragma unroll
                for (int mf = 0; mf < 4; mf++) MMA16816(acc[mf][nf], ah[mf], bh);
#pragma unroll
                for (int mf = 0; mf < 4; mf++) MMA16816(acc[mf][nf], ah[mf], bl);
#pragma unroll
                for (int mf = 0; mf < 4; mf++) MMA16816(acc[mf][nf], al[mf], bh);
            }
        }
        __syncthreads();
    }

#pragma unroll
    for (int mf = 0; mf < 4; mf++) {
        const int row = bm + warpM * 64 + mf * 16 + tq;
#pragma unroll
        for (int nf = 0; nf < 4; nf++) {
            const int col = bn + warpN * 32 + nf * 8 + tr * 2;
            const float b0 = bias[col], b1 = bias[col + 1];
            float2 v0 = make_float2(acc[mf][nf][0] + b0, acc[mf][nf][1] + b1);
            float2 v1 = make_float2(acc[mf][nf][2] + b0, acc[mf][nf][3] + b1);
            *(float2*)&C[(long)row * N + col]       = v0;
            *(float2*)&C[(long)(row + 8) * N + col] = v1;
        }
    }
}

// ----------------------------------------------------------------------------
// fp16 asymmetric 2-term GEMM core: A single fp16 [M,K], B fp16 hi/lo [N,K].
// MODE 0: fp32 C += bias.  MODE 1: transposed fp16 hi/lo [b,h,d][c] (V-proj).
// ----------------------------------------------------------------------------
#define F16_STAGE_ELEMS (3 * 128 * SSTR)
#define F16_STAGE_BYTES (F16_STAGE_ELEMS * 2)
#define F16_SMEM_BYTES  (2 * F16_STAGE_BYTES)             // 61440 B

template <int MODE>
__device__ __forceinline__ void gemm_f16_body(
    const __half* __restrict__ A,
    const __half* __restrict__ Bhi, const __half* __restrict__ Blo,
    const float* __restrict__ bias, float* __restrict__ C,
    __half* __restrict__ Thi, __half* __restrict__ Tlo,
    int N, int K, int bm, int bn, __nv_bfloat16* dsm0)
{
    __half* dsm = reinterpret_cast<__half*>(dsm0);
    const uint32_t dsmAddr = (uint32_t)__cvta_generic_to_shared(dsm);

    const int tid  = threadIdx.x;
    const int wid  = tid >> 5;
    const int lane = tid & 31;
    const int warpM = wid >> 2;
    const int warpN = wid & 3;
    const int tq = lane >> 2;
    const int tr = lane & 3;

    const int r0g = tid >> 2;
    const int r1g = r0g + 64;
    const int c0g = (tid & 3) * 8;

    const uint32_t aRowOff = (uint32_t)(((warpM * 64 + (lane & 15)) * SSTR + ((lane >> 4) << 3)) * 2);
    const uint32_t bRowOff = (uint32_t)(((warpN * 32 + (lane & 7))  * SSTR + (((lane >> 3) & 1) << 3)) * 2);

    float acc[4][4][4];
#pragma unroll
    for (int i = 0; i < 4; i++)
#pragma unroll
        for (int j = 0; j < 4; j++)
#pragma unroll
            for (int r = 0; r < 4; r++) acc[i][j][r] = 0.f;

    const int nchunks = K >> 5;

    auto issue = [&](int c, int s) {
        __half* sA  = dsm + s * F16_STAGE_ELEMS;
        __half* sBh = sA  + 128 * SSTR;
        __half* sBl = sBh + 128 * SSTR;
        const int k0 = c << 5;
        const long a0 = (long)(bm + r0g) * K + k0 + c0g;
        const long a1 = (long)(bm + r1g) * K + k0 + c0g;
        const long b0 = (long)(bn + r0g) * K + k0 + c0g;
        const long b1 = (long)(bn + r1g) * K + k0 + c0g;
        CP16(&sA [r0g * SSTR + c0g], &A[a0]);
        CP16(&sA [r1g * SSTR + c0g], &A[a1]);
        CP16(&sBh[r0g * SSTR + c0g], &Bhi[b0]);
        CP16(&sBh[r1g * SSTR + c0g], &Bhi[b1]);
        CP16(&sBl[r0g * SSTR + c0g], &Blo[b0]);
        CP16(&sBl[r1g * SSTR + c0g], &Blo[b1]);
    };

    issue(0, 0);
    CP_COMMIT();

    for (int c = 0; c < nchunks; c++) {
        if (c + 1 < nchunks) issue(c + 1, (c + 1) & 1);
        CP_COMMIT();
        CP_WAIT1();
        __syncthreads();

        const uint32_t stA  = dsmAddr + (c & 1) * F16_STAGE_BYTES;
        const uint32_t stBh = stA  + GEMM_TILE_BYTES;
        const uint32_t stBl = stBh + GEMM_TILE_BYTES;

#pragma unroll
        for (int ks = 0; ks < 2; ks++) {
            const uint32_t ksOff = (uint32_t)(ks * 16 * 2);
            uint32_t ah[4][4];
#pragma unroll
            for (int mf = 0; mf < 4; mf++) {
                const uint32_t mOff = (uint32_t)(mf * 16 * SSTR * 2) + aRowOff + ksOff;
                LDSM_X4(ah[mf], stA + mOff);
            }
#pragma unroll
            for (int nf = 0; nf < 4; nf++) {
                const uint32_t nOff = (uint32_t)(nf * 8 * SSTR * 2) + bRowOff + ksOff;
                uint32_t bh[2], bl[2];
                LDSM_X2(bh, stBh + nOff);
                LDSM_X2(bl, stBl + nOff);
#pragma unroll
                for (int mf = 0; mf < 4; mf++) MMA16816F16(acc[mf][nf], ah[mf], bh);
#pragma unroll
                for (int mf = 0; mf < 4; mf++) MMA16816F16(acc[mf][nf], ah[mf], bl);
            }
        }
        __syncthreads();
    }

    if (MODE == 0) {
#pragma unroll
        for (int mf = 0; mf < 4; mf++) {
            const int row = bm + warpM * 64 + mf * 16 + tq;
#pragma unroll
            for (int nf = 0; nf < 4; nf++) {
                const int col = bn + warpN * 32 + nf * 8 + tr * 2;
                const float b0 = bias[col], b1 = bias[col + 1];
                float2 v0 = make_float2(acc[mf][nf][0] + b0, acc[mf][nf][1] + b1);
                float2 v1 = make_float2(acc[mf][nf][2] + b0, acc[mf][nf][3] + b1);
                *(float2*)&C[(long)row * N + col]       = v0;
                *(float2*)&C[(long)(row + 8) * N + col] = v1;
            }
        }
    } else {
        // V-proj: transposed fp16 hi/lo to [ (b*16+h)*64+d ][ c ]
#pragma unroll
        for (int mf = 0; mf < 4; mf++) {
            const int row0 = bm + warpM * 64 + mf * 16 + tq;
#pragma unroll
            for (int nf = 0; nf < 4; nf++) {
                const int col = bn + warpN * 32 + nf * 8 + tr * 2;
                const float b0 = bias[col], b1 = bias[col + 1];
#pragma unroll
                for (int r = 0; r < 2; r++) {
                    const int row = row0 + r * 8;
                    const int bb = row >> 10, cc = row & 1023;
                    const float va = acc[mf][nf][2 * r]     + b0;
                    const float vb = acc[mf][nf][2 * r + 1] + b1;
                    const long o0 = ((long)(bb * (NHEADS * HDIM) + col)) * LKV + cc;
                    const long o1 = o0 + LKV;
                    __half ha = __float2half_rn(va);
                    __half hb = __float2half_rn(vb);
                    Thi[o0] = ha;
                    Thi[o1] = hb;
                    Tlo[o0] = __float2half_rn(va - __half2float(ha));
                    Tlo[o1] = __float2half_rn(vb - __half2float(hb));
                }
            }
        }
    }
}

// Fused Q/K/V projection launch. grid = (8, 96).
__global__ __launch_bounds__(256, 2) void gemm_qkv_kernel(
    const __nv_bfloat16* __restrict__ xhi, const __nv_bfloat16* __restrict__ xlo,
    const __nv_bfloat16* __restrict__ yhi, const __nv_bfloat16* __restrict__ ylo,
    const __half* __restrict__ yh16,
    const __nv_bfloat16* __restrict__ wqh, const __nv_bfloat16* __restrict__ wql,
    const __nv_bfloat16* __restrict__ wkh, const __nv_bfloat16* __restrict__ wkl,
    const __half* __restrict__ wvh, const __half* __restrict__ wvl,
    const float* __restrict__ bq, const float* __restrict__ bk, const float* __restrict__ bv,
    float* __restrict__ qtmp, float* __restrict__ ktmp,
    __half* __restrict__ vthf, __half* __restrict__ vtlf)
{
    extern __shared__ __nv_bfloat16 dsm[];
    const int by = blockIdx.y;
    const int bn = blockIdx.x * 128;

    if (by < 64) {
        gemm_body(xhi, xlo, wqh, wql, bq, qtmp, DIM, DIM, by * 128, bn, dsm);
    } else if (by < 80) {
        gemm_body(yhi, ylo, wkh, wkl, bk, ktmp, DIM, KV_DIM, (by - 64) * 128, bn, dsm);
    } else {
        gemm_f16_body<1>(yh16, wvh, wvl, bv, nullptr, vthf, vtlf,
                         DIM, KV_DIM, (by - 80) * 128, bn, dsm);
    }
}

// O-projection: fp16 2-term
__global__ __launch_bounds__(256, 2) void gemm_f16_kernel(
    const __half* __restrict__ A,
    const __half* __restrict__ Bhi, const __half* __restrict__ Blo,
    const float* __restrict__ bias, float* __restrict__ C,
    int M, int N, int K)
{
    extern __shared__ __nv_bfloat16 dsm[];
    gemm_f16_body<0>(A, Bhi, Blo, bias, C, nullptr, nullptr,
                     N, K, blockIdx.y * 128, blockIdx.x * 128, dsm);
}

// ----------------------------------------------------------------------------
// Split activations: x -> bf16 hi/lo; y -> bf16 hi/lo AND fp16 single
// ----------------------------------------------------------------------------
__global__ __launch_bounds__(256) void split_xy_kernel(
    const float* __restrict__ x, __nv_bfloat16* __restrict__ xhi, __nv_bfloat16* __restrict__ xlo, int n4x,
    const float* __restrict__ y, __nv_bfloat16* __restrict__ yhi, __nv_bfloat16* __restrict__ ylo,
    __half* __restrict__ yh16, int n4y)
{
    int i = blockIdx.x * blockDim.x + threadIdx.x;
    if (i < n4x) {
        float4 v = *(const float4*)&x[(long)i * 4];
        __nv_bfloat16 h0 = __float2bfloat16(v.x), h1 = __float2bfloat16(v.y);
        __nv_bfloat16 h2 = __float2bfloat16(v.z), h3 = __float2bfloat16(v.w);
        uint32_t ph0 = packbf2(v.x, v.y), ph1 = packbf2(v.z, v.w);
        uint32_t pl0 = packbf2(v.x - __bfloat162float(h0), v.y - __bfloat162float(h1));
        uint32_t pl1 = packbf2(v.z - __bfloat162float(h2), v.w - __bfloat162float(h3));
        *(uint2*)&xhi[(long)i * 4] = make_uint2(ph0, ph1);
        *(uint2*)&xlo[(long)i * 4] = make_uint2(pl0, pl1);
    } else {
        i -= n4x;
        if (i >= n4y) return;
        float4 v = *(const float4*)&y[(long)i * 4];
        __nv_bfloat16 h0 = __float2bfloat16(v.x), h1 = __float2bfloat16(v.y);
        __nv_bfloat16 h2 = __float2bfloat16(v.z), h3 = __float2bfloat16(v.w);
        uint32_t ph0 = packbf2(v.x, v.y), ph1 = packbf2(v.z, v.w);
        uint32_t pl0 = packbf2(v.x - __bfloat162float(h0), v.y - __bfloat162float(h1));
        uint32_t pl1 = packbf2(v.z - __bfloat162float(h2), v.w - __bfloat162float(h3));
        *(uint2*)&yhi[(long)i * 4] = make_uint2(ph0, ph1);
        *(uint2*)&ylo[(long)i * 4] = make_uint2(pl0, pl1);
        *(uint2*)&yh16[(long)i * 4] = make_uint2(packh2(v.x, v.y), packh2(v.z, v.w));
    }
}

// ----------------------------------------------------------------------------
// Split + transpose: all 4 weights in ONE launch. z: 0=Wq(bf16) 1=Wo(fp16)
// 2=Wk(bf16) 3=Wv(fp16). Ragged K -> early exit.
// ----------------------------------------------------------------------------
__global__ __launch_bounds__(256) void split_transpose4_kernel(
    const float* __restrict__ Wq, __nv_bfloat16* __restrict__ Tqh, __nv_bfloat16* __restrict__ Tql,
    const float* __restrict__ Wo, __half* __restrict__ Toh, __half* __restrict__ Tol,
    const float* __restrict__ Wk, __nv_bfloat16* __restrict__ Tkh, __nv_bfloat16* __restrict__ Tkl,
    const float* __restrict__ Wv, __half* __restrict__ Tvh, __half* __restrict__ Tvl)
{
    const int z = blockIdx.z;
    const float* W = (z == 0) ? Wq : (z == 1) ? Wo : (z == 2) ? Wk : Wv;
    const int K = (z < 2) ? DIM : KV_DIM;
    const int by = blockIdx.y * 32;
    if (by >= K) return;
    const int N = DIM;

    __shared__ float tile[32][33];
    const int bx = blockIdx.x * 32;
    const int tx = threadIdx.x & 31;
    const int ty = threadIdx.x >> 5;
#pragma unroll
    for (int i = 0; i < 4; i++) {
        int kk = by + ty + i * 8;
        tile[ty + i * 8][tx] = W[(long)kk * N + bx + tx];
    }
    __syncthreads();
#pragma unroll
    for (int i = 0; i < 4; i++) {
        int nn = bx + ty + i * 8;
        float v = tile[tx][ty + i * 8];
        long o = (long)nn * K + by + tx;
        if (z == 0 || z == 2) {
            __nv_bfloat16 h = __float2bfloat16(v);
            __nv_bfloat16 l = __float2bfloat16(v - __bfloat162float(h));
            if (z == 0) { Tqh[o] = h; Tql[o] = l; }
            else        { Tkh[o] = h; Tkl[o] = l; }
        } else {
            __half h = __float2half_rn(v);
            __half l = __float2half_rn(v - __half2float(h));
            if (z == 1) { Toh[o] = h; Tol[o] = l; }
            else        { Tvh[o] = h; Tvl[o] = l; }
        }
    }
}

// ----------------------------------------------------------------------------
// Fused RMSNorm + RoPE -> bf16 hi/lo outputs
// ----------------------------------------------------------------------------
__global__ __launch_bounds__(256) void normrope_bf16_kernel(
    const float* __restrict__ in, __nv_bfloat16* __restrict__ outhi,
    __nv_bfloat16* __restrict__ outlo,
    const float* __restrict__ g, const float* __restrict__ cosb,
    const float* __restrict__ sinb)
{
    const int row = blockIdx.x;
    const float* h = in + (long)row * DIM;
    const int tid = threadIdx.x;
    const int e = tid << 2;

    float4 t = *(const float4*)&h[e];
    float ss = t.x * t.x + t.y * t.y + t.z * t.z + t.w * t.w;
#pragma unroll
    for (int o = 16; o > 0; o >>= 1)
        ss += __shfl_xor_sync(0xffffffffu, ss, o);
    __shared__ float red[8];
    if ((tid & 31) == 0) red[tid >> 5] = ss;
    __syncthreads();
    float tot = red[0] + red[1] + red[2] + red[3] + red[4] + red[5] + red[6] + red[7];
    float inv = rsqrtf(tot * (1.0f / (float)DIM) + 1e-6f);

    const int d   = e & (HDIM - 1);
    const int po  = (d < 32) ? 32 : -32;
    const float sgn = (d < 32) ? -1.0f : 1.0f;

    float4 tp  = *(const float4*)&h[e + po];
    float4 g4  = *(const float4*)&g[e];
    float4 gp4 = *(const float4*)&g[e + po];
    float4 c4  = *(const float4*)&cosb[(long)row * HDIM + d];
    float4 s4  = *(const float4*)&sinb[(long)row * HDIM + d];

    float4 o4;
    o4.x = t.x * inv * g4.x * c4.x + sgn * tp.x * inv * gp4.x * s4.x;
    o4.y = t.y * inv * g4.y * c4.y + sgn * tp.y * inv * gp4.y * s4.y;
    o4.z = t.z * inv * g4.z * c4.z + sgn * tp.z * inv * gp4.z * s4.z;
    o4.w = t.w * inv * g4.w * c4.w + sgn * tp.w * inv * gp4.w * s4.w;

    __nv_bfloat16 h0 = __float2bfloat16(o4.x), h1 = __float2bfloat16(o4.y);
    __nv_bfloat16 h2 = __float2bfloat16(o4.z), h3 = __float2bfloat16(o4.w);
    uint32_t ph0 = packbf2(o4.x, o4.y), ph1 = packbf2(o4.z, o4.w);
    uint32_t pl0 = packbf2(o4.x - __bfloat162float(h0), o4.y - __bfloat162float(h1));
    uint32_t pl1 = packbf2(o4.z - __bfloat162float(h2), o4.w - __bfloat162float(h3));
    *(uint2*)&outhi[(long)row * DIM + e] = make_uint2(ph0, ph1);
    *(uint2*)&outlo[(long)row * DIM + e] = make_uint2(pl0, pl1);
}

// ----------------------------------------------------------------------------
// Flash attention. S = QK^T in bf16x3 (accuracy-critical). PV in fp16 2-term:
// P single fp16 A-frags, V fp16 hi/lo. Output: single fp16 activations.
// CTA = 128 threads (4 warps), 64 q-rows. KV chunks of 64, 2-stage cp.async.
// ----------------------------------------------------------------------------
#define SK 72
#define ATT_STAGE_ELEMS (4 * 64 * SK)
#define ATT_STAGE_BYTES (ATT_STAGE_ELEMS * 2)
#define ATT_TILE_BYTES  (64 * SK * 2)
#define ATT_SMEM_BYTES  (2 * ATT_STAGE_BYTES)     // 73728 B

__global__ __launch_bounds__(128, 3) void attn_mma_kernel(
    const __nv_bfloat16* __restrict__ qhi, const __nv_bfloat16* __restrict__ qlo,
    const __nv_bfloat16* __restrict__ khi, const __nv_bfloat16* __restrict__ klo,
    const __half* __restrict__ vthf, const __half* __restrict__ vtlf,
    __half* __restrict__ oa)
{
    extern __shared__ __nv_bfloat16 dsm[];
    const uint32_t dsmAddr = (uint32_t)__cvta_generic_to_shared(dsm);

    const int tid  = threadIdx.x;
    const int w    = tid >> 5;
    const int lane = tid & 31;
    const int tq   = lane >> 2;
    const int tr   = lane & 3;
    const int b    = blockIdx.x >> 4;
    const int h    = blockIdx.x & 15;
    const int q0   = blockIdx.y * 64;
    const float SCALE = 0.125f;

    const int lrow = tid >> 1, lhalf = (tid & 1) * 32;
    const uint32_t fragOff = (uint32_t)((((lane & 7) * SK) + (((lane >> 3) & 1) << 3)) * 2);

    auto issue = [&](int c, int s) {
        __nv_bfloat16* sKh = dsm + s * ATT_STAGE_ELEMS;
        __nv_bfloat16* sKl = sKh + 64 * SK;
        __nv_bfloat16* sVh = sKl + 64 * SK;   // holds fp16 bits
        __nv_bfloat16* sVl = sVh + 64 * SK;   // holds fp16 bits
        const int j0 = c << 6;
        const __nv_bfloat16* kh_g = khi + ((long)(b * LKV + j0 + lrow)) * DIM + h * HDIM + lhalf;
        const __nv_bfloat16* kl_g = klo + ((long)(b * LKV + j0 + lrow)) * DIM + h * HDIM + lhalf;
        const long vo = ((long)((b * NHEADS + h) * HDIM + lrow)) * LKV + j0 + lhalf;
        const __half* vh_g = vthf + vo;
        const __half* vl_g = vtlf + vo;
#pragma unroll
        for (int u = 0; u < 4; u++) {
            const int so = lrow * SK + lhalf + u * 8;
            CP16(&sKh[so], &kh_g[u * 8]);
            CP16(&sKl[so], &kl_g[u * 8]);
            CP16(&sVh[so], &vh_g[u * 8]);
            CP16(&sVl[so], &vl_g[u * 8]);
        }
    };

    const long grow0 = (long)(b * LQ + q0 + w * 16 + tq);
    const __nv_bfloat16* qh0 = qhi + grow0 * DIM + h * HDIM;
    const __nv_bfloat16* ql0 = qlo + grow0 * DIM + h * HDIM;
    uint32_t aQh[4][4], aQl[4][4];
#pragma unroll
    for (int ks = 0; ks < 4; ks++) {
        const int c0 = ks * 16 + 2 * tr;
        aQh[ks][0] = *(const uint32_t*)&qh0[c0];
        aQh[ks][1] = *(const uint32_t*)&qh0[8 * DIM + c0];
        aQh[ks][2] = *(const uint32_t*)&qh0[c0 + 8];
        aQh[ks][3] = *(const uint32_t*)&qh0[8 * DIM + c0 + 8];
        aQl[ks][0] = *(const uint32_t*)&ql0[c0];
        aQl[ks][1] = *(const uint32_t*)&ql0[8 * DIM + c0];
        aQl[ks][2] = *(const uint32_t*)&ql0[c0 + 8];
        aQl[ks][3] = *(const uint32_t*)&ql0[8 * DIM + c0 + 8];
    }

    float oacc[8][4];
#pragma unroll
    for (int i = 0; i < 8; i++)
#pragma unroll
        for (int j = 0; j < 4; j++) oacc[i][j] = 0.f;
    float m[2] = {-1e30f, -1e30f}, l[2] = {0.f, 0.f};

    issue(0, 0);
    CP_COMMIT();

    const int NCH = LKV / 64;
    for (int c = 0; c < NCH; c++) {
        if (c + 1 < NCH) issue(c + 1, (c + 1) & 1);
        CP_COMMIT();
        CP_WAIT1();
        __syncthreads();

        const uint32_t stKh = dsmAddr + (c & 1) * ATT_STAGE_BYTES;
        const uint32_t stVh = stKh + 2 * ATT_TILE_BYTES;

        // ---- S = Q K^T (bf16x3) ----
        float s[8][4];
#pragma unroll
        for (int i = 0; i < 8; i++)
#pragma unroll
            for (int j = 0; j < 4; j++) s[i][j] = 0.f;

#pragma unroll
        for (int ks = 0; ks < 4; ks++) {
            const uint32_t ksOff = (uint32_t)(ks * 32);
#pragma unroll
            for (int nf = 0; nf < 8; nf += 2) {
                const uint32_t base0 = stKh + (uint32_t)(nf * 8 * SK * 2) + fragOff + ksOff;
                const uint32_t base1 = base0 + (uint32_t)(8 * SK * 2);
                const uint32_t lbase0 = base0 + (uint32_t)(ATT_TILE_BYTES);
                const uint32_t lbase1 = lbase0 + (uint32_t)(8 * SK * 2);
                uint32_t bh0[2], bh1[2], bl0[2], bl1[2];
                LDSM_X2(bh0, base0);  LDSM_X2(bh1, base1);
                LDSM_X2(bl0, lbase0); LDSM_X2(bl1, lbase1);
                MMA16816(s[nf],     aQh[ks], bh0);
                MMA16816(s[nf + 1], aQh[ks], bh1);
                MMA16816(s[nf],     aQh[ks], bl0);
                MMA16816(s[nf + 1], aQh[ks], bl1);
                MMA16816(s[nf],     aQl[ks], bh0);
                MMA16816(s[nf + 1], aQl[ks], bh1);
            }
        }

        // ---- online softmax (rows tq and tq+8) ----
#pragma unroll
        for (int r = 0; r < 2; r++) {
            float mx = -1e30f;
#pragma unroll
            for (int nf = 0; nf < 8; nf++)
                mx = fmaxf(mx, fmaxf(s[nf][2 * r], s[nf][2 * r + 1]));
            mx = fmaxf(mx, __shfl_xor_sync(0xffffffffu, mx, 1));
            mx = fmaxf(mx, __shfl_xor_sync(0xffffffffu, mx, 2));
            const float mn = fmaxf(m[r], mx);
            const float f  = __expf((m[r] - mn) * SCALE);
            float rs = 0.f;
#pragma unroll
            for (int nf = 0; nf < 8; nf++) {
                s[nf][2 * r]     = __expf((s[nf][2 * r]     - mn) * SCALE);
                s[nf][2 * r + 1] = __expf((s[nf][2 * r + 1] - mn) * SCALE);
                rs += s[nf][2 * r] + s[nf][2 * r + 1];
            }
            rs += __shfl_xor_sync(0xffffffffu, rs, 1);
            rs += __shfl_xor_sync(0xffffffffu, rs, 2);
            m[r] = mn;
            l[r] = l[r] * f + rs;
#pragma unroll
            for (int nf = 0; nf < 8; nf++) {
                oacc[nf][2 * r]     *= f;
                oacc[nf][2 * r + 1] *= f;
            }
        }

        // ---- O += P V (P single fp16; V fp16 hi/lo; 2-term) ----
#pragma unroll
        for (int ks = 0; ks < 4; ks++) {
            uint32_t aP[4];
            aP[0] = packh2(s[2 * ks][0],     s[2 * ks][1]);
            aP[1] = packh2(s[2 * ks][2],     s[2 * ks][3]);
            aP[2] = packh2(s[2 * ks + 1][0], s[2 * ks + 1][1]);
            aP[3] = packh2(s[2 * ks + 1][2], s[2 * ks + 1][3]);

            const uint32_t ksOff = (uint32_t)(ks * 32);
#pragma unroll
            for (int nf = 0; nf < 8; nf += 2) {
                const uint32_t base0 = stVh + (uint32_t)(nf * 8 * SK * 2) + fragOff + ksOff;
                const uint32_t base1 = base0 + (uint32_t)(8 * SK * 2);
                const uint32_t lbase0 = base0 + (uint32_t)(ATT_TILE_BYTES);
                const uint32_t lbase1 = lbase0 + (uint32_t)(8 * SK * 2);
                uint32_t bh0[2], bh1[2], bl0[2], bl1[2];
                LDSM_X2(bh0, base0);  LDSM_X2(bh1, base1);
                LDSM_X2(bl0, lbase0); LDSM_X2(bl1, lbase1);
                MMA16816F16(oacc[nf],     aP, bh0);
                MMA16816F16(oacc[nf + 1], aP, bh1);
                MMA16816F16(oacc[nf],     aP, bl0);
                MMA16816F16(oacc[nf + 1], aP, bl1);
            }
        }
        __syncthreads();
    }

    // ---- epilogue: O /= l, write single fp16 ----
    const float inv0 = 1.f / l[0], inv1 = 1.f / l[1];
    __half* oh0 = oa + grow0 * DIM + h * HDIM;
#pragma unroll
    for (int nf = 0; nf < 8; nf++) {
        const int col = nf * 8 + 2 * tr;
        *(uint32_t*)&oh0[col]           = packh2(oacc[nf][0] * inv0, oacc[nf][1] * inv0);
        *(uint32_t*)&oh0[8 * DIM + col] = packh2(oacc[nf][2] * inv1, oacc[nf][3] * inv1);
    }
}

// ----------------------------------------------------------------------------
// Launch
// ----------------------------------------------------------------------------
extern "C" void kernel_launch(void* const* d_in, const int* in_sizes, int n_in,
                              void* d_out, int out_size)
{
    const float* x     = (const float*)d_in[0];
    const float* y     = (const float*)d_in[1];
    const float* x_cos = (const float*)d_in[2];
    const float* x_sin = (const float*)d_in[3];
    const float* y_cos = (const float*)d_in[4];
    const float* y_sin = (const float*)d_in[5];
    const float* Wq    = (const float*)d_in[6];
    const float* bq    = (const float*)d_in[7];
    const float* Wk    = (const float*)d_in[8];
    const float* bk    = (const float*)d_in[9];
    const float* Wv    = (const float*)d_in[10];
    const float* bv    = (const float*)d_in[11];
    const float* Wo    = (const float*)d_in[12];
    const float* bo    = (const float*)d_in[13];
    const float* gq    = (const float*)d_in[14];
    const float* gk    = (const float*)d_in[15];
    float* out = (float*)d_out;

    float *qtmp, *ktmp;
    cudaGetSymbolAddress((void**)&qtmp, g_qtmp);
    cudaGetSymbolAddress((void**)&ktmp, g_ktmp);

    __nv_bfloat16 *qhi, *qlo, *khi, *klo, *xhi, *xlo, *yhi, *ylo;
    __nv_bfloat16 *wqh, *wql, *wkh, *wkl;
    __half *vthf, *vtlf, *yh16, *oa, *wvh, *wvl, *woh, *wol;
    cudaGetSymbolAddress((void**)&qhi, g_qhi);
    cudaGetSymbolAddress((void**)&qlo, g_qlo);
    cudaGetSymbolAddress((void**)&khi, g_khi);
    cudaGetSymbolAddress((void**)&klo, g_klo);
    cudaGetSymbolAddress((void**)&vthf, g_vthf);
    cudaGetSymbolAddress((void**)&vtlf, g_vtlf);
    cudaGetSymbolAddress((void**)&xhi, g_xhi);
    cudaGetSymbolAddress((void**)&xlo, g_xlo);
    cudaGetSymbolAddress((void**)&yhi, g_yhi);
    cudaGetSymbolAddress((void**)&ylo, g_ylo);
    cudaGetSymbolAddress((void**)&yh16, g_yh16);
    cudaGetSymbolAddress((void**)&oa, g_oa);
    cudaGetSymbolAddress((void**)&wqh, g_wqt_hi);
    cudaGetSymbolAddress((void**)&wql, g_wqt_lo);
    cudaGetSymbolAddress((void**)&wkh, g_wkt_hi);
    cudaGetSymbolAddress((void**)&wkl, g_wkt_lo);
    cudaGetSymbolAddress((void**)&wvh, g_wvt_hi);
    cudaGetSymbolAddress((void**)&wvl, g_wvt_lo);
    cudaGetSymbolAddress((void**)&woh, g_wot_hi);
    cudaGetSymbolAddress((void**)&wol, g_wot_lo);

    cudaFuncSetAttribute(gemm_qkv_kernel,
                         cudaFuncAttributeMaxDynamicSharedMemorySize, GEMM_SMEM_BYTES);
    cudaFuncSetAttribute(gemm_f16_kernel,
                         cudaFuncAttributeMaxDynamicSharedMemorySize, F16_SMEM_BYTES);
    cudaFuncSetAttribute(attn_mma_kernel,
                         cudaFuncAttributeMaxDynamicSharedMemorySize, ATT_SMEM_BYTES);

    const int Mq = BATCH * LQ;    // 8192
    const int Mk = BATCH * LKV;   // 2048
    const int n4x = Mq * DIM / 4;
    const int n4y = Mk * KV_DIM / 4;

    split_xy_kernel<<<(n4x + n4y + 255) / 256, 256>>>(
        x, xhi, xlo, n4x, y, yhi, ylo, yh16, n4y);
    split_transpose4_kernel<<<dim3(DIM / 32, DIM / 32, 4), 256>>>(
        Wq, wqh, wql, Wo, woh, wol, Wk, wkh, wkl, Wv, wvh, wvl);

    // Fused Q/K/V projections; V branch is fp16 2-term, writes transposed fp16 hi/lo
    gemm_qkv_kernel<<<dim3(DIM / 128, 96), 256, GEMM_SMEM_BYTES>>>(
        xhi, xlo, yhi, ylo, yh16,
        wqh, wql, wkh, wkl, wvh, wvl,
        bq, bk, bv, qtmp, ktmp, vthf, vtlf);

    normrope_bf16_kernel<<<Mq, 256>>>(qtmp, qhi, qlo, gq, x_cos, x_sin);
    normrope_bf16_kernel<<<Mk, 256>>>(ktmp, khi, klo, gk, y_cos, y_sin);

    // Attention: QK^T bf16x3, PV fp16 2-term; emits fp16 activations
    attn_mma_kernel<<<dim3(BATCH * NHEADS, LQ / 64), 128, ATT_SMEM_BYTES>>>(
        qhi, qlo, khi, klo, vthf, vtlf, oa);

    // O-projection: fp16 2-term
    gemm_f16_kernel<<<dim3(DIM / 128, Mq / 128), 256, F16_SMEM_BYTES>>>(
        oa, woh, wol, bo, out, Mq, DIM, DIM);
}